// round 4
// baseline (speedup 1.0000x reference)
#include <cuda_runtime.h>
#include <math_constants.h>

#define BB 4
#define TT 1024
#define EE 1024
#define HH 16
#define DD 64
#define BT (BB*TT)   // 4096

// ---------------- scratch (device globals; no runtime allocation) ----------------
__device__ float g_q[BT*EE];
__device__ float g_k[BT*EE];
__device__ float g_v[BT*EE];
__device__ float g_rv[BT*EE];
__device__ float g_echo[BT*EE];
__device__ float g_eb[BT*EE];
__device__ float g_comb[BT*EE];
__device__ float g_P[(long long)BB*HH*TT*TT];   // 256 MB attention probs (branch 1)
__device__ float g_s2[BB*HH*TT];
__device__ float g_sc[BB*TT];

// gate softmax weight for head h, branch c (gate is (H,3))
__device__ __forceinline__ float gate_w(const float* gate, int h, int c) {
    float a = gate[h*3+0], b = gate[h*3+1], d = gate[h*3+2];
    float m = fmaxf(a, fmaxf(b, d));
    float ea = __expf(a-m), ebv = __expf(b-m), ec = __expf(d-m);
    float s = ea + ebv + ec;
    float num = (c == 0) ? ea : (c == 1) ? ebv : ec;
    return num / s;
}

// ---------------- generic strided batched GEMM ----------------
// C[m,n] (+)= alpha * sum_k A[m*sAm + k*sAk] * B[k*sBk + n*sBn]
// batch bz: b1=bz/nh, h=bz%nh; per-operand offsets b1*s?1 + h*s?2.
// if gate != nullptr, alpha *= softmax(gate[h])[gateCol].
__global__ void gemm_generic(const float* __restrict__ Ag, const float* __restrict__ Bg,
                             float* __restrict__ Cg, int M, int N, int K,
                             long sAm, long sAk, long sBk, long sBn, long sCm,
                             int nh, long sA1, long sA2, long sB1, long sB2,
                             long sC1, long sC2,
                             float alpha, const float* gate, int gateCol, int accum)
{
    __shared__ float As[16][65];
    __shared__ float Bs[16][65];
    int bz = blockIdx.z;
    int b1 = bz / nh, hh = bz - b1*nh;
    const float* A = Ag + (long)b1*sA1 + (long)hh*sA2;
    const float* B = Bg + (long)b1*sB1 + (long)hh*sB2;
    float*       C = Cg + (long)b1*sC1 + (long)hh*sC2;
    if (gate) alpha *= gate_w(gate, hh, gateCol);

    int m0 = blockIdx.y*64, n0 = blockIdx.x*64;
    int tid = threadIdx.x;
    int tm = (tid >> 4) * 4, tn = (tid & 15) * 4;
    float acc[4][4] = {};

    for (int k0 = 0; k0 < K; k0 += 16) {
        // A tile: k fastest over consecutive threads (sAk==1 for all our uses)
        for (int i = tid; i < 64*16; i += 256) {
            int mm = i >> 4, kk = i & 15;
            int gm = m0+mm, gk = k0+kk;
            As[kk][mm] = (gm < M && gk < K) ? A[(long)gm*sAm + (long)gk*sAk] : 0.f;
        }
        if (sBk == 1) {  // k-contiguous B
            for (int i = tid; i < 64*16; i += 256) {
                int nn = i >> 4, kk = i & 15;
                int gn = n0+nn, gk = k0+kk;
                Bs[kk][nn] = (gn < N && gk < K) ? B[(long)gk + (long)gn*sBn] : 0.f;
            }
        } else {         // n-contiguous B
            for (int i = tid; i < 16*64; i += 256) {
                int kk = i >> 6, nn = i & 63;
                int gn = n0+nn, gk = k0+kk;
                Bs[kk][nn] = (gn < N && gk < K) ? B[(long)gk*sBk + (long)gn*sBn] : 0.f;
            }
        }
        __syncthreads();
        #pragma unroll
        for (int kk = 0; kk < 16; kk++) {
            float a0 = As[kk][tm+0], a1 = As[kk][tm+1], a2 = As[kk][tm+2], a3 = As[kk][tm+3];
            float b0 = Bs[kk][tn+0], b1v = Bs[kk][tn+1], b2 = Bs[kk][tn+2], b3 = Bs[kk][tn+3];
            acc[0][0] += a0*b0;  acc[0][1] += a0*b1v; acc[0][2] += a0*b2;  acc[0][3] += a0*b3;
            acc[1][0] += a1*b0;  acc[1][1] += a1*b1v; acc[1][2] += a1*b2;  acc[1][3] += a1*b3;
            acc[2][0] += a2*b0;  acc[2][1] += a2*b1v; acc[2][2] += a2*b2;  acc[2][3] += a2*b3;
            acc[3][0] += a3*b0;  acc[3][1] += a3*b1v; acc[3][2] += a3*b2;  acc[3][3] += a3*b3;
        }
        __syncthreads();
    }
    #pragma unroll
    for (int i = 0; i < 4; i++) {
        int gm = m0 + tm + i;
        if (gm >= M) continue;
        float* crow = C + (long)gm*sCm;
        #pragma unroll
        for (int j = 0; j < 4; j++) {
            int gn = n0 + tn + j;
            if (gn >= N) continue;
            float v = alpha * acc[i][j];
            if (accum) crow[gn] += v; else crow[gn] = v;
        }
    }
}

// ---------------- s2[b,h,t] = (1/8) * dot(x[b,t,:], wr[h,:,t]) ----------------
// grid (T/256, H, B), 256 threads
__global__ void s2_kernel(const float* __restrict__ x, const float* __restrict__ wr)
{
    __shared__ float xs[256][33];
    int t0 = blockIdx.x * 256;
    int h = blockIdx.y, b = blockIdx.z;
    int tid = threadIdx.x, w = tid >> 5, lane = tid & 31;
    int t = t0 + tid;
    float acc = 0.f;
    for (int e0 = 0; e0 < EE; e0 += 32) {
        // cooperative coalesced load: warp w loads 32 rows x 32 e
        #pragma unroll 4
        for (int rr = 0; rr < 32; rr++) {
            xs[w*32 + rr][lane] =
                x[(long)b*TT*EE + (long)(t0 + w*32 + rr)*EE + e0 + lane];
        }
        __syncthreads();
        const float* wrp = wr + (long)h*EE*TT + (long)e0*TT + t;
        #pragma unroll
        for (int e = 0; e < 32; e++)
            acc += xs[tid][e] * wrp[(long)e*TT];
        __syncthreads();
    }
    g_s2[(b*HH + h)*TT + t] = acc * 0.125f;
}

// ---------------- sc[b,t] = dot(x[b,t], echo_back[b,t]) / 32 ----------------
// grid B*T, 256 threads
__global__ void sc_kernel(const float* __restrict__ x)
{
    __shared__ float red[256];
    long base = (long)blockIdx.x * EE;
    int tid = threadIdx.x;
    float s = 0.f;
    for (int e = tid; e < EE; e += 256) s += x[base+e] * g_eb[base+e];
    red[tid] = s; __syncthreads();
    for (int st = 128; st; st >>= 1) {
        if (tid < st) red[tid] += red[tid+st];
        __syncthreads();
    }
    if (tid == 0) g_sc[blockIdx.x] = red[0] * (1.f/32.f);
}

// ---------------- causal row softmax of P (in place) ----------------
// grid (T, B*H), 256 threads; row i valid for j<=i, zeros beyond
__global__ void softmax1_kernel()
{
    __shared__ float red[256];
    int i = blockIdx.x;
    long base = (long)blockIdx.y*TT*TT + (long)i*TT;
    int tid = threadIdx.x;
    float m = -CUDART_INF_F;
    for (int j = tid; j <= i; j += 256) m = fmaxf(m, g_P[base+j]);
    red[tid] = m; __syncthreads();
    for (int st = 128; st; st >>= 1) {
        if (tid < st) red[tid] = fmaxf(red[tid], red[tid+st]);
        __syncthreads();
    }
    m = red[0]; __syncthreads();
    float sum = 0.f;
    for (int j = tid; j <= i; j += 256) {
        float w = __expf(g_P[base+j] - m);
        g_P[base+j] = w;
        sum += w;
    }
    red[tid] = sum; __syncthreads();
    for (int st = 128; st; st >>= 1) {
        if (tid < st) red[tid] += red[tid+st];
        __syncthreads();
    }
    float inv = 1.f / red[0];
    for (int j = tid; j <= i; j += 256) g_P[base+j] *= inv;
    for (int j = i+1+tid; j < TT; j += 256) g_P[base+j] = 0.f;
}

// ---------------- branch 2: online-softmax prefix scan ----------------
// grid B*H, 64 threads (one per d). comb += g1 * out2
__global__ void branch2_kernel(const float* __restrict__ gate)
{
    int bh = blockIdx.x, b = bh / HH, h = bh % HH, d = threadIdx.x;
    float g1 = gate_w(gate, h, 1);
    const float* s2p = g_s2 + bh*TT;
    const float* rvp = g_rv  + (long)b*TT*EE + h*DD + d;
    float*       cp  = g_comb + (long)b*TT*EE + h*DD + d;
    float m = -CUDART_INF_F, den = 0.f, acc = 0.f;
    for (int j = 0; j < TT; j++) {
        float s = s2p[j];
        float mn = fmaxf(m, s);
        float corr = __expf(m - mn);
        float w = __expf(s - mn);
        den = den*corr + w;
        acc = acc*corr + w * rvp[(long)j*EE];
        m = mn;
        cp[(long)j*EE] += g1 * acc / den;
    }
}

// ---------------- branch 3: rank-1 score softmax + weighted echo sum ----------------
// grid B*(T/8), 256 threads. comb += g2[h] * out3
__global__ void branch3_kernel(const float* __restrict__ gate)
{
    __shared__ float p[8][1024];   // normalized probs for 8 query rows
    int b  = blockIdx.x / (TT/8);
    int i0 = (blockIdx.x % (TT/8)) * 8;
    int tid = threadIdx.x, r = tid >> 5, lane = tid & 31;
    int jmax = i0 + 8;             // causal limit for this row tile (<= TT)

    // phase 1: warp r computes probs for row i0+r
    {
        int i = i0 + r;
        const float* scb = g_sc + b*TT;
        float sci = scb[i];
        float m = -CUDART_INF_F;
        for (int j = lane; j <= i; j += 32) m = fmaxf(m, sci * scb[j]);
        #pragma unroll
        for (int o = 16; o; o >>= 1) m = fmaxf(m, __shfl_xor_sync(0xffffffffu, m, o));
        float sum = 0.f;
        for (int j = lane; j <= i; j += 32) {
            float w = __expf(sci * scb[j] - m);
            p[r][j] = w;
            sum += w;
        }
        #pragma unroll
        for (int o = 16; o; o >>= 1) sum += __shfl_xor_sync(0xffffffffu, sum, o);
        float inv = 1.f / sum;
        for (int j = lane; j <= i; j += 32) p[r][j] *= inv;
        for (int j = i+1+lane; j < jmax; j += 32) p[r][j] = 0.f;
    }
    __syncthreads();

    // phase 2: every thread owns 4 consecutive e-columns for all 8 rows
    int e0 = tid * 4;
    int h = e0 / DD;
    float g2 = gate_w(gate, h, 2);
    float acc[8][4] = {};
    const float* ebase = g_echo + (long)b*TT*EE + e0;
    for (int j = 0; j < jmax; j++) {
        float4 ev = *(const float4*)(ebase + (long)j*EE);
        #pragma unroll
        for (int rr = 0; rr < 8; rr++) {
            float pr = p[rr][j];
            acc[rr][0] += pr * ev.x;
            acc[rr][1] += pr * ev.y;
            acc[rr][2] += pr * ev.z;
            acc[rr][3] += pr * ev.w;
        }
    }
    #pragma unroll
    for (int rr = 0; rr < 8; rr++) {
        float* cp = g_comb + (long)b*TT*EE + (long)(i0+rr)*EE + e0;
        cp[0] += g2 * acc[rr][0];
        cp[1] += g2 * acc[rr][1];
        cp[2] += g2 * acc[rr][2];
        cp[3] += g2 * acc[rr][3];
    }
}

// ---------------- host launch ----------------
extern "C" void kernel_launch(void* const* d_in, const int* in_sizes, int n_in,
                              void* d_out, int out_size)
{
    const float* x    = (const float*)d_in[0];
    const float* wq   = (const float*)d_in[1];
    const float* wk   = (const float*)d_in[2];
    const float* wv   = (const float*)d_in[3];
    const float* wvr  = (const float*)d_in[4];
    const float* wr   = (const float*)d_in[5];
    const float* wj   = (const float*)d_in[6];
    const float* gate = (const float*)d_in[7];
    const float* wo   = (const float*)d_in[8];
    float* out = (float*)d_out;

    float *q, *k, *v, *rv, *echo, *eb, *comb, *P;
    cudaGetSymbolAddress((void**)&q,    g_q);
    cudaGetSymbolAddress((void**)&k,    g_k);
    cudaGetSymbolAddress((void**)&v,    g_v);
    cudaGetSymbolAddress((void**)&rv,   g_rv);
    cudaGetSymbolAddress((void**)&echo, g_echo);
    cudaGetSymbolAddress((void**)&eb,   g_eb);
    cudaGetSymbolAddress((void**)&comb, g_comb);
    cudaGetSymbolAddress((void**)&P,    g_P);

    dim3 blk(256);
    dim3 gproj(EE/64, BT/64, 1);

    // 5 projections: y = x @ W^T   (sAk=1; W is (E,E) row-major -> sBk=1, sBn=E)
    gemm_generic<<<gproj, blk>>>(x, wq,  q,    BT, EE, EE, EE,1, 1,EE, EE, 1,0,0,0,0,0,0, 1.f, nullptr,0, 0);
    gemm_generic<<<gproj, blk>>>(x, wk,  k,    BT, EE, EE, EE,1, 1,EE, EE, 1,0,0,0,0,0,0, 1.f, nullptr,0, 0);
    gemm_generic<<<gproj, blk>>>(x, wv,  v,    BT, EE, EE, EE,1, 1,EE, EE, 1,0,0,0,0,0,0, 1.f, nullptr,0, 0);
    gemm_generic<<<gproj, blk>>>(x, wvr, rv,   BT, EE, EE, EE,1, 1,EE, EE, 1,0,0,0,0,0,0, 1.f, nullptr,0, 0);
    gemm_generic<<<gproj, blk>>>(x, wj,  echo, BT, EE, EE, EE,1, 1,EE, EE, 1,0,0,0,0,0,0, 1.f, nullptr,0, 0);
    // echo_back = echo @ wj   (no transpose: sBk=E, sBn=1)
    gemm_generic<<<gproj, blk>>>(echo, wj, eb, BT, EE, EE, EE,1, EE,1, EE, 1,0,0,0,0,0,0, 1.f, nullptr,0, 0);

    // s2 and sc
    s2_kernel<<<dim3(TT/256, HH, BB), 256>>>(x, wr);
    sc_kernel<<<BT, 256>>>(x);

    // branch 1: S = (1/8) Q K^T, batched over (b,h)
    dim3 gs(TT/64, TT/64, BB*HH);
    gemm_generic<<<gs, blk>>>(q, k, P, TT, TT, DD,
                              EE,1, 1,EE, TT,
                              HH, (long)TT*EE, (long)DD, (long)TT*EE, (long)DD,
                              (long)HH*TT*TT, (long)TT*TT,
                              0.125f, nullptr, 0, 0);
    softmax1_kernel<<<dim3(TT, BB*HH), 256>>>();

    // out1 = g0[h] * (P @ V)  -> comb (overwrite; branches 2,3 accumulate after)
    dim3 gpv(DD/64, TT/64, BB*HH);
    gemm_generic<<<gpv, blk>>>(P, v, comb, TT, DD, TT,
                               TT,1, EE,1, EE,
                               HH, (long)HH*TT*TT, (long)TT*TT,
                               (long)TT*EE, (long)DD,
                               (long)TT*EE, (long)DD,
                               1.f, gate, 0, 0);

    branch2_kernel<<<BB*HH, 64>>>(gate);
    branch3_kernel<<<BB*(TT/8), 256>>>(gate);

    // final: out = comb @ wo^T
    gemm_generic<<<gproj, blk>>>(comb, wo, out, BT, EE, EE, EE,1, 1,EE, EE,
                                 1,0,0,0,0,0,0, 1.f, nullptr,0, 0);
}

// round 6
// speedup vs baseline: 2.9169x; 2.9169x over previous
#include <cuda_runtime.h>
#include <cuda_bf16.h>
#include <math_constants.h>
#include <cstdint>

#define BB 4
#define TT 1024
#define EE 1024
#define HH 16
#define DD 64
#define BT (BB*TT)   // 4096
#define BH (BB*HH)   // 64

// ---------------- scratch (device globals) ----------------
__device__ __nv_bfloat16 g_xh[BT*EE],  g_xl[BT*EE];
__device__ __nv_bfloat16 g_wqh[EE*EE], g_wql[EE*EE];
__device__ __nv_bfloat16 g_wkh[EE*EE], g_wkl[EE*EE];
__device__ __nv_bfloat16 g_wvh[EE*EE], g_wvl[EE*EE];
__device__ __nv_bfloat16 g_wrh[EE*EE], g_wrl[EE*EE];   // wvr
__device__ __nv_bfloat16 g_wjh[EE*EE], g_wjl[EE*EE];
__device__ __nv_bfloat16 g_wjTh[EE*EE],g_wjTl[EE*EE];
__device__ __nv_bfloat16 g_woh[EE*EE], g_wol[EE*EE];
__device__ __nv_bfloat16 g_qsh[BH*TT*DD], g_qsl[BH*TT*DD];
__device__ __nv_bfloat16 g_ksh[BH*TT*DD], g_ksl[BH*TT*DD];
__device__ __nv_bfloat16 g_vth[BH*DD*TT], g_vtl[BH*DD*TT];
__device__ float g_rv[BT*EE];
__device__ float g_echo[BT*EE];
__device__ __nv_bfloat16 g_eh[BT*EE], g_el[BT*EE];
__device__ float g_eb[BT*EE];
__device__ float g_comb[BT*EE];
__device__ __nv_bfloat16 g_ch[BT*EE], g_cl[BT*EE];
__device__ float g_S[64*1024*1024];                 // branch-1 scores (fp32)
__device__ __nv_bfloat16 g_Ph[64*1024*1024], g_Pl[64*1024*1024];
__device__ float g_s2[BH*TT];
__device__ float g_sc[BB*TT];

// ---------------- helpers ----------------
__device__ __forceinline__ uint32_t smem_u32(const void* p) {
    uint32_t a;
    asm("{ .reg .u64 t; cvta.to.shared.u64 t, %1; cvt.u32.u64 %0, t; }" : "=r"(a) : "l"(p));
    return a;
}
__device__ __forceinline__ void cpasync16(uint32_t saddr, const void* g) {
    asm volatile("cp.async.cg.shared.global [%0], [%1], 16;" :: "r"(saddr), "l"(g));
}
#define CP_COMMIT() asm volatile("cp.async.commit_group;" ::: "memory")
#define CP_WAIT1()  asm volatile("cp.async.wait_group 1;"  ::: "memory")

__device__ __forceinline__ void ldsm4(uint32_t* r, uint32_t addr) {
    asm volatile("ldmatrix.sync.aligned.m8n8.x4.shared.b16 {%0,%1,%2,%3}, [%4];"
        : "=r"(r[0]), "=r"(r[1]), "=r"(r[2]), "=r"(r[3]) : "r"(addr));
}
__device__ __forceinline__ void mma16816(float* d, const uint32_t* a, const uint32_t* b) {
    asm volatile("mma.sync.aligned.m16n8k16.row.col.f32.bf16.bf16.f32 "
        "{%0,%1,%2,%3}, {%4,%5,%6,%7}, {%8,%9}, {%0,%1,%2,%3};"
        : "+f"(d[0]), "+f"(d[1]), "+f"(d[2]), "+f"(d[3])
        : "r"(a[0]), "r"(a[1]), "r"(a[2]), "r"(a[3]), "r"(b[0]), "r"(b[1]));
}

__device__ __forceinline__ float gate_w(const float* gate, int h, int c) {
    float a = gate[h*3+0], b = gate[h*3+1], d = gate[h*3+2];
    float m = fmaxf(a, fmaxf(b, d));
    float ea = __expf(a-m), eb = __expf(b-m), ec = __expf(d-m);
    float s = ea + eb + ec;
    float num = (c == 0) ? ea : (c == 1) ? eb : ec;
    return num / s;
}
__device__ __forceinline__ void bsplit(float v, __nv_bfloat16& h, __nv_bfloat16& l) {
    h = __float2bfloat16(v);
    l = __float2bfloat16(v - __bfloat162float(h));
}

__device__ __forceinline__ void storeC(
    int mode, float* Cf, __nv_bfloat16* Ch, __nv_bfloat16* Cl,
    long ldc, int zb, int zh, long sCb, long sCh, int gm, int gn, float v)
{
    if (mode == 0) {
        Cf[(long)zb*sCb + (long)zh*sCh + (long)gm*ldc + gn] = v;
    } else if (mode == 1 || mode == 4) {
        long idx = (long)gm*ldc + gn;
        if (mode == 4) Cf[idx] = v;
        bsplit(v, Ch[idx], Cl[idx]);
    } else if (mode == 2) {   // vT: [(b*16+h)][d][t]
        int b = gm >> 10, t = gm & 1023, h = gn >> 6, d = gn & 63;
        long idx = (((long)(b*16 + h)) * 64 + d) * 1024 + t;
        bsplit(v, Ch[idx], Cl[idx]);
    } else {                  // mode 3: [(b*16+h)][t][d]
        int b = gm >> 10, t = gm & 1023, h = gn >> 6, d = gn & 63;
        long idx = (((long)(b*16 + h)) * 1024 + t) * 64 + d;
        bsplit(v, Ch[idx], Cl[idx]);
    }
}

// ---------------- HMMA split-bf16 GEMM ----------------
// C[m,n] = alpha * sum_k (Ah+Al)[m,k]*(Bh+Bl)[n,k]  via Ah*Bh + Ah*Bl + Al*Bh.
// Block tile 128 x TN, K chunks of 32, 3-stage cp.async pipeline,
// mma.sync m16n8k16 bf16 (no sm_103a-only features).
template<int TN>
__global__ void __launch_bounds__(256) tgemm(
    const __nv_bfloat16* __restrict__ Ah, const __nv_bfloat16* __restrict__ Al,
    const __nv_bfloat16* __restrict__ Bh, const __nv_bfloat16* __restrict__ Bl,
    int K, long lda, long ldb, long sAz, long sBz, int causal,
    int mode, float* __restrict__ Cf,
    __nv_bfloat16* __restrict__ Ch, __nv_bfloat16* __restrict__ Cl,
    long ldc, int nh, long sCb, long sCh,
    float alpha, const float* __restrict__ gate, int gateCol)
{
    constexpr int TM = 128, TK = 32, STAGES = 3;
    constexpr int ROWB = 80;                 // 64B data + 16B pad: conflict-free LDSM
    constexpr int ASZ = TM*ROWB, BSZ = TN*ROWB, STG = ASZ + BSZ;
    constexpr int WARPS_N = TN/32, WARPS_M = 8/WARPS_N;
    constexpr int WM = TM/WARPS_M, MI = WM/16;

    extern __shared__ char smem[];
    const int tid = threadIdx.x, wid = tid >> 5, lane = tid & 31;
    const int m0 = blockIdx.y*TM, n0 = blockIdx.x*TN, z = blockIdx.z;
    if (causal && n0 > m0 + TM - 1) return;

    const int wm = wid / WARPS_N, wn = wid % WARPS_N;
    const uint32_t sbase = smem_u32(smem);

    const __nv_bfloat16* Ahz = Ah + (long)z * sAz;
    const __nv_bfloat16* Alz = Al + (long)z * sAz;
    const __nv_bfloat16* Bhz = Bh + (long)z * sBz;
    const __nv_bfloat16* Blz = Bl + (long)z * sBz;
    if (gate) alpha *= gate_w(gate, z % nh, gateCol);

    const int NC = K / TK;
    const int total = 3 * NC;

    auto prefetch = [&](int idx, int s) {
        int t = idx / NC, k0 = (idx % NC) * TK;
        const __nv_bfloat16* A_ = (t == 2) ? Alz : Ahz;
        const __nv_bfloat16* B_ = (t == 1) ? Blz : Bhz;
        uint32_t as = sbase + s*STG;
        uint32_t bs = as + ASZ;
        #pragma unroll 2
        for (int i = tid; i < TM*4; i += 256) {
            int r = i >> 2, c = i & 3;
            cpasync16(as + r*ROWB + c*16, A_ + (long)(m0 + r)*lda + k0 + c*8);
        }
        #pragma unroll 2
        for (int i = tid; i < TN*4; i += 256) {
            int r = i >> 2, c = i & 3;
            cpasync16(bs + r*ROWB + c*16, B_ + (long)(n0 + r)*ldb + k0 + c*8);
        }
    };

    float acc[MI][4][4] = {};

    prefetch(0, 0); CP_COMMIT();
    prefetch(1, 1); CP_COMMIT();

    for (int c = 0; c < total; c++) {
        CP_WAIT1();
        __syncthreads();
        int pc = c + 2;
        if (pc < total) prefetch(pc, pc % STAGES);
        CP_COMMIT();

        uint32_t abase = sbase + (c % STAGES)*STG;
        uint32_t bbase = abase + ASZ;
        #pragma unroll
        for (int ks = 0; ks < 2; ks++) {
            uint32_t afr[MI][4], bfr[2][4];
            #pragma unroll
            for (int mi = 0; mi < MI; mi++)
                ldsm4(afr[mi], abase + (wm*WM + mi*16 + (lane & 15))*ROWB
                               + ks*32 + (lane >> 4)*16);
            #pragma unroll
            for (int bi = 0; bi < 2; bi++)
                ldsm4(bfr[bi], bbase + (wn*32 + bi*16 + (lane & 15))*ROWB
                               + ks*32 + (lane >> 4)*16);
            #pragma unroll
            for (int mi = 0; mi < MI; mi++) {
                #pragma unroll
                for (int ni = 0; ni < 4; ni++) {
                    uint32_t bb[2];
                    bb[0] = (ni & 1) ? bfr[ni>>1][1] : bfr[ni>>1][0];
                    bb[1] = (ni & 1) ? bfr[ni>>1][3] : bfr[ni>>1][2];
                    mma16816(acc[mi][ni], afr[mi], bb);
                }
            }
        }
    }

    // epilogue
    int zb = z / nh, zh = z % nh;
    #pragma unroll
    for (int mi = 0; mi < MI; mi++) {
        #pragma unroll
        for (int ni = 0; ni < 4; ni++) {
            int rb = m0 + wm*WM + mi*16 + (lane >> 2);
            int cb = n0 + wn*32 + ni*8 + (lane & 3)*2;
            storeC(mode, Cf, Ch, Cl, ldc, zb, zh, sCb, sCh, rb,   cb,   alpha*acc[mi][ni][0]);
            storeC(mode, Cf, Ch, Cl, ldc, zb, zh, sCb, sCh, rb,   cb+1, alpha*acc[mi][ni][1]);
            storeC(mode, Cf, Ch, Cl, ldc, zb, zh, sCb, sCh, rb+8, cb,   alpha*acc[mi][ni][2]);
            storeC(mode, Cf, Ch, Cl, ldc, zb, zh, sCb, sCh, rb+8, cb+1, alpha*acc[mi][ni][3]);
        }
    }
}

// ---------------- conversion kernels ----------------
__global__ void conv_split(const float* __restrict__ in,
                           __nv_bfloat16* __restrict__ h, __nv_bfloat16* __restrict__ l, int n)
{
    int i = blockIdx.x * 256 + threadIdx.x;
    if (i < n) bsplit(in[i], h[i], l[i]);
}
__global__ void conv_split_T(const float* __restrict__ in,
                             __nv_bfloat16* __restrict__ h, __nv_bfloat16* __restrict__ l)
{   // out[e*E+f] = in[f*E+e]
    int i = blockIdx.x * 256 + threadIdx.x;
    int e = i >> 10, f = i & 1023;
    bsplit(in[(long)f * EE + e], h[i], l[i]);
}

// ---------------- s2[b,h,t] = (1/8) dot(x[b,t,:], wr[h,:,t]) ----------------
__global__ void s2_kernel(const float* __restrict__ x, const float* __restrict__ wr)
{
    __shared__ float xs[256][33];
    int t0 = blockIdx.x * 256;
    int h = blockIdx.y, b = blockIdx.z;
    int tid = threadIdx.x, w = tid >> 5, lane = tid & 31;
    int t = t0 + tid;
    float acc = 0.f;
    for (int e0 = 0; e0 < EE; e0 += 32) {
        #pragma unroll 4
        for (int rr = 0; rr < 32; rr++)
            xs[w*32 + rr][lane] = x[(long)b*TT*EE + (long)(t0 + w*32 + rr)*EE + e0 + lane];
        __syncthreads();
        const float* wrp = wr + (long)h*EE*TT + (long)e0*TT + t;
        #pragma unroll
        for (int e = 0; e < 32; e++) acc += xs[tid][e] * wrp[(long)e*TT];
        __syncthreads();
    }
    g_s2[(b*HH + h)*TT + t] = acc * 0.125f;
}

// ---------------- sc[b,t] = dot(x[b,t], eb[b,t]) / 32 ----------------
__global__ void sc_kernel(const float* __restrict__ x)
{
    __shared__ float red[256];
    long base = (long)blockIdx.x * EE;
    int tid = threadIdx.x;
    float s = 0.f;
    for (int e = tid; e < EE; e += 256) s += x[base+e] * g_eb[base+e];
    red[tid] = s; __syncthreads();
    for (int st = 128; st; st >>= 1) { if (tid < st) red[tid] += red[tid+st]; __syncthreads(); }
    if (tid == 0) g_sc[blockIdx.x] = red[0] * (1.f/32.f);
}

// ---------------- causal softmax of S -> bf16-split P ----------------
__global__ void softmax1_kernel()
{
    __shared__ float red[256];
    int i = blockIdx.x;
    long base = (long)blockIdx.y*TT*TT + (long)i*TT;
    int tid = threadIdx.x;
    float m = -CUDART_INF_F;
    for (int j = tid; j <= i; j += 256) m = fmaxf(m, g_S[base+j]);
    red[tid] = m; __syncthreads();
    for (int st = 128; st; st >>= 1) { if (tid < st) red[tid] = fmaxf(red[tid], red[tid+st]); __syncthreads(); }
    m = red[0]; __syncthreads();
    float sum = 0.f;
    for (int j = tid; j <= i; j += 256) {
        float w = __expf(g_S[base+j] - m);
        g_S[base+j] = w;
        sum += w;
    }
    red[tid] = sum; __syncthreads();
    for (int st = 128; st; st >>= 1) { if (tid < st) red[tid] += red[tid+st]; __syncthreads(); }
    float inv = 1.f / red[0];
    for (int j = tid; j <= i; j += 256) bsplit(g_S[base+j] * inv, g_Ph[base+j], g_Pl[base+j]);
    __nv_bfloat16 zz = __float2bfloat16(0.f);
    for (int j = i+1+tid; j < TT; j += 256) { g_Ph[base+j] = zz; g_Pl[base+j] = zz; }
}

// ---------------- branch 2: global-max softmax prefix (s2 std ~0.18, exact) ----------------
__global__ void branch2_kernel(const float* __restrict__ gate)
{
    __shared__ float w[TT];
    __shared__ float inv[TT];
    __shared__ float red[128];
    int bh = blockIdx.x, b = bh >> 4, h = bh & 15;
    int tid = threadIdx.x;  // 128
    const float* s2p = g_s2 + bh*TT;

    float m = -CUDART_INF_F;
    for (int j = tid; j < TT; j += 128) m = fmaxf(m, s2p[j]);
    red[tid] = m; __syncthreads();
    for (int st = 64; st; st >>= 1) { if (tid < st) red[tid] = fmaxf(red[tid], red[tid+st]); __syncthreads(); }
    m = red[0]; __syncthreads();

    for (int j = tid; j < TT; j += 128) w[j] = __expf(s2p[j] - m);
    __syncthreads();

    float local[8]; float s = 0.f;
    #pragma unroll
    for (int u = 0; u < 8; u++) { s += w[tid*8 + u]; local[u] = s; }
    red[tid] = s; __syncthreads();
    for (int off = 1; off < 128; off <<= 1) {
        float v = (tid >= off) ? red[tid - off] : 0.f;
        __syncthreads();
        red[tid] += v;
        __syncthreads();
    }
    float basep = (tid == 0) ? 0.f : red[tid - 1];
    #pragma unroll
    for (int u = 0; u < 8; u++) inv[tid*8 + u] = 1.f / (basep + local[u]);
    __syncthreads();

    if (tid < 64) {
        float g1 = gate_w(gate, h, 1);
        const float* rvp = g_rv   + (long)b*TT*EE + h*64 + tid;
        float*       cp  = g_comb + (long)b*TT*EE + h*64 + tid;
        float acc = 0.f;
        for (int j0 = 0; j0 < TT; j0 += 8) {
            float rb[8];
            #pragma unroll
            for (int u = 0; u < 8; u++) rb[u] = rvp[(long)(j0+u)*EE];
            #pragma unroll
            for (int u = 0; u < 8; u++) {
                acc += w[j0+u] * rb[u];
                cp[(long)(j0+u)*EE] += g1 * acc * inv[j0+u];
            }
        }
    }
}

// ---------------- branch 3: rank-1 softmax + weighted echo sum ----------------
__global__ void branch3_kernel(const float* __restrict__ gate)
{
    __shared__ float p[8][1024];
    int b  = blockIdx.x / (TT/8);
    int i0 = (blockIdx.x % (TT/8)) * 8;
    int tid = threadIdx.x, r = tid >> 5, lane = tid & 31;
    int jmax = i0 + 8;
    {
        int i = i0 + r;
        const float* scb = g_sc + b*TT;
        float sci = scb[i];
        float m = -CUDART_INF_F;
        for (int j = lane; j <= i; j += 32) m = fmaxf(m, sci * scb[j]);
        #pragma unroll
        for (int o = 16; o; o >>= 1) m = fmaxf(m, __shfl_xor_sync(0xffffffffu, m, o));
        float sum = 0.f;
        for (int j = lane; j <= i; j += 32) {
            float wv = __expf(sci * scb[j] - m);
            p[r][j] = wv; sum += wv;
        }
        #pragma unroll
        for (int o = 16; o; o >>= 1) sum += __shfl_xor_sync(0xffffffffu, sum, o);
        float iv = 1.f / sum;
        for (int j = lane; j <= i; j += 32) p[r][j] *= iv;
        for (int j = i+1+lane; j < jmax; j += 32) p[r][j] = 0.f;
    }
    __syncthreads();
    int e0 = tid * 4;
    int h = e0 / DD;
    float g2 = gate_w(gate, h, 2);
    float acc[8][4] = {};
    const float* ebase = g_echo + (long)b*TT*EE + e0;
    for (int j = 0; j < jmax; j++) {
        float4 ev = *(const float4*)(ebase + (long)j*EE);
        #pragma unroll
        for (int rr = 0; rr < 8; rr++) {
            float pr = p[rr][j];
            acc[rr][0] += pr * ev.x; acc[rr][1] += pr * ev.y;
            acc[rr][2] += pr * ev.z; acc[rr][3] += pr * ev.w;
        }
    }
    #pragma unroll
    for (int rr = 0; rr < 8; rr++) {
        float* cp = g_comb + (long)b*TT*EE + (long)(i0+rr)*EE + e0;
        cp[0] += g2*acc[rr][0]; cp[1] += g2*acc[rr][1];
        cp[2] += g2*acc[rr][2]; cp[3] += g2*acc[rr][3];
    }
}

// ---------------- host launch ----------------
extern "C" void kernel_launch(void* const* d_in, const int* in_sizes, int n_in,
                              void* d_out, int out_size)
{
    const float* x    = (const float*)d_in[0];
    const float* wq   = (const float*)d_in[1];
    const float* wk   = (const float*)d_in[2];
    const float* wv   = (const float*)d_in[3];
    const float* wvr  = (const float*)d_in[4];
    const float* wr   = (const float*)d_in[5];
    const float* wj   = (const float*)d_in[6];
    const float* gate = (const float*)d_in[7];
    const float* wo   = (const float*)d_in[8];
    float* out = (float*)d_out;

#define GA(sym, var, type) type* var; cudaGetSymbolAddress((void**)&var, sym)
    GA(g_xh, xh, __nv_bfloat16);   GA(g_xl, xl, __nv_bfloat16);
    GA(g_wqh, wqh, __nv_bfloat16); GA(g_wql, wql, __nv_bfloat16);
    GA(g_wkh, wkh, __nv_bfloat16); GA(g_wkl, wkl, __nv_bfloat16);
    GA(g_wvh, wvh, __nv_bfloat16); GA(g_wvl, wvl, __nv_bfloat16);
    GA(g_wrh, wrh, __nv_bfloat16); GA(g_wrl, wrl, __nv_bfloat16);
    GA(g_wjh, wjh, __nv_bfloat16); GA(g_wjl, wjl, __nv_bfloat16);
    GA(g_wjTh, wjTh, __nv_bfloat16); GA(g_wjTl, wjTl, __nv_bfloat16);
    GA(g_woh, woh, __nv_bfloat16); GA(g_wol, wol, __nv_bfloat16);
    GA(g_qsh, qsh, __nv_bfloat16); GA(g_qsl, qsl, __nv_bfloat16);
    GA(g_ksh, ksh, __nv_bfloat16); GA(g_ksl, ksl, __nv_bfloat16);
    GA(g_vth, vth, __nv_bfloat16); GA(g_vtl, vtl, __nv_bfloat16);
    GA(g_rv, rvf, float);
    GA(g_echo, echof, float);
    GA(g_eh, eh, __nv_bfloat16);   GA(g_el, el, __nv_bfloat16);
    GA(g_eb, ebf, float);
    GA(g_comb, combf, float);
    GA(g_ch, ch, __nv_bfloat16);   GA(g_cl, cl, __nv_bfloat16);
    GA(g_S, Sf, float);
    GA(g_Ph, Ph, __nv_bfloat16);   GA(g_Pl, Pl, __nv_bfloat16);
#undef GA

    const int SM128 = 3 * (128 + 128) * 80;   // 61440
    const int SM64  = 3 * (128 + 64) * 80;    // 46080
    cudaFuncSetAttribute(tgemm<128>, cudaFuncAttributeMaxDynamicSharedMemorySize, SM128);
    cudaFuncSetAttribute(tgemm<64>,  cudaFuncAttributeMaxDynamicSharedMemorySize, SM64);

    // --- bf16 hi/lo splits of inputs ---
    conv_split<<<(BT*EE)/256, 256>>>(x,   xh,  xl,  BT*EE);
    conv_split<<<(EE*EE)/256, 256>>>(wq,  wqh, wql, EE*EE);
    conv_split<<<(EE*EE)/256, 256>>>(wk,  wkh, wkl, EE*EE);
    conv_split<<<(EE*EE)/256, 256>>>(wv,  wvh, wvl, EE*EE);
    conv_split<<<(EE*EE)/256, 256>>>(wvr, wrh, wrl, EE*EE);
    conv_split<<<(EE*EE)/256, 256>>>(wj,  wjh, wjl, EE*EE);
    conv_split<<<(EE*EE)/256, 256>>>(wo,  woh, wol, EE*EE);
    conv_split_T<<<(EE*EE)/256, 256>>>(wj, wjTh, wjTl);

    dim3 big(8, 32, 1);
    // projections: y = x @ W^T
    tgemm<128><<<big, 256, SM128>>>(xh, xl, wqh, wql, 1024, 1024, 1024, 0, 0, 0,
                                    3, nullptr, qsh, qsl, 0, 1, 0, 0, 1.f, nullptr, 0);
    tgemm<128><<<big, 256, SM128>>>(xh, xl, wkh, wkl, 1024, 1024, 1024, 0, 0, 0,
                                    3, nullptr, ksh, ksl, 0, 1, 0, 0, 1.f, nullptr, 0);
    tgemm<128><<<big, 256, SM128>>>(xh, xl, wvh, wvl, 1024, 1024, 1024, 0, 0, 0,
                                    2, nullptr, vth, vtl, 0, 1, 0, 0, 1.f, nullptr, 0);
    tgemm<128><<<big, 256, SM128>>>(xh, xl, wrh, wrl, 1024, 1024, 1024, 0, 0, 0,
                                    0, rvf, nullptr, nullptr, 1024, 1, 0, 0, 1.f, nullptr, 0);
    tgemm<128><<<big, 256, SM128>>>(xh, xl, wjh, wjl, 1024, 1024, 1024, 0, 0, 0,
                                    4, echof, eh, el, 1024, 1, 0, 0, 1.f, nullptr, 0);
    // echo_back = echo @ wj (wjT is K-major)
    tgemm<128><<<big, 256, SM128>>>(eh, el, wjTh, wjTl, 1024, 1024, 1024, 0, 0, 0,
                                    0, ebf, nullptr, nullptr, 1024, 1, 0, 0, 1.f, nullptr, 0);

    s2_kernel<<<dim3(TT/256, HH, BB), 256>>>(x, wr);
    sc_kernel<<<BT, 256>>>(x);

    // branch 1: S = 0.125 * Q K^T, causal tile skip
    tgemm<128><<<dim3(8, 8, 64), 256, SM128>>>(
        qsh, qsl, ksh, ksl, 64, 64, 64, (long)TT*64, (long)TT*64, 1,
        0, Sf, nullptr, nullptr, 1024, 1, (long)TT*TT, 0, 0.125f, nullptr, 0);
    softmax1_kernel<<<dim3(TT, BH), 256>>>();

    // out1 = g0[h] * (P @ V) -> comb (overwrite)
    tgemm<64><<<dim3(1, 8, 64), 256, SM64>>>(
        Ph, Pl, vth, vtl, 1024, 1024, 1024, (long)TT*TT, (long)DD*TT, 0,
        0, combf, nullptr, nullptr, 1024, 16, (long)TT*EE, 64, 1.f, gate, 0);

    branch2_kernel<<<BH, 128>>>(gate);
    branch3_kernel<<<BB*(TT/8), 256>>>(gate);

    // final: out = comb @ wo^T
    conv_split<<<(BT*EE)/256, 256>>>(combf, ch, cl, BT*EE);
    tgemm<128><<<big, 256, SM128>>>(ch, cl, woh, wol, 1024, 1024, 1024, 0, 0, 0,
                                    0, out, nullptr, nullptr, 1024, 1, 0, 0, 1.f, nullptr, 0);
}

// round 8
// speedup vs baseline: 2.9750x; 1.0199x over previous
#include <cuda_runtime.h>
#include <cuda_bf16.h>
#include <math_constants.h>
#include <cstdint>

#define BB 4
#define TT 1024
#define EE 1024
#define HH 16
#define DD 64
#define BT (BB*TT)   // 4096
#define BH (BB*HH)   // 64

// ---------------- scratch (device globals) ----------------
__device__ __nv_bfloat16 g_xh[BT*EE],  g_xl[BT*EE];
__device__ __nv_bfloat16 g_wqh[EE*EE], g_wql[EE*EE];
__device__ __nv_bfloat16 g_wkh[EE*EE], g_wkl[EE*EE];
__device__ __nv_bfloat16 g_wvh[EE*EE], g_wvl[EE*EE];
__device__ __nv_bfloat16 g_wrh[EE*EE], g_wrl[EE*EE];   // wvr
__device__ __nv_bfloat16 g_wjh[EE*EE], g_wjl[EE*EE];
__device__ __nv_bfloat16 g_wjTh[EE*EE],g_wjTl[EE*EE];
__device__ __nv_bfloat16 g_woh[EE*EE], g_wol[EE*EE];
__device__ __nv_bfloat16 g_qsh[BH*TT*DD], g_qsl[BH*TT*DD];  // [bh][t][d]
__device__ __nv_bfloat16 g_ksh[BH*TT*DD], g_ksl[BH*TT*DD];  // [bh][t][d]
__device__ __nv_bfloat16 g_vth[BH*DD*TT], g_vtl[BH*DD*TT];  // [bh][d][t]
__device__ float g_rv[BT*EE];
__device__ float g_echo[BT*EE];
__device__ __nv_bfloat16 g_eh[BT*EE], g_el[BT*EE];
__device__ float g_eb[BT*EE];
__device__ float g_comb[BT*EE];
__device__ __nv_bfloat16 g_ch[BT*EE], g_cl[BT*EE];
__device__ float g_s2[BH*TT];
__device__ float g_sc[BB*TT];

// ---------------- helpers ----------------
__device__ __forceinline__ uint32_t smem_u32(const void* p) {
    uint32_t a;
    asm("{ .reg .u64 t; cvta.to.shared.u64 t, %1; cvt.u32.u64 %0, t; }" : "=r"(a) : "l"(p));
    return a;
}
__device__ __forceinline__ void cpasync16(uint32_t saddr, const void* g) {
    asm volatile("cp.async.cg.shared.global [%0], [%1], 16;" :: "r"(saddr), "l"(g));
}
#define CP_COMMIT() asm volatile("cp.async.commit_group;" ::: "memory")
#define CP_WAIT1()  asm volatile("cp.async.wait_group 1;"  ::: "memory")

__device__ __forceinline__ void ldsm4(uint32_t* r, uint32_t addr) {
    asm volatile("ldmatrix.sync.aligned.m8n8.x4.shared.b16 {%0,%1,%2,%3}, [%4];"
        : "=r"(r[0]), "=r"(r[1]), "=r"(r[2]), "=r"(r[3]) : "r"(addr));
}
__device__ __forceinline__ void mma16816(float* d, const uint32_t* a, const uint32_t* b) {
    asm volatile("mma.sync.aligned.m16n8k16.row.col.f32.bf16.bf16.f32 "
        "{%0,%1,%2,%3}, {%4,%5,%6,%7}, {%8,%9}, {%0,%1,%2,%3};"
        : "+f"(d[0]), "+f"(d[1]), "+f"(d[2]), "+f"(d[3])
        : "r"(a[0]), "r"(a[1]), "r"(a[2]), "r"(a[3]), "r"(b[0]), "r"(b[1]));
}

// fast exp on FMA pipe (MUFU rt=8/SMSP is a chip-level wall for softmax).
// valid for x <= 0; clamps below -80 (result ~0). rel err < 3e-6.
__device__ __forceinline__ float fexp(float x) {
    x = fmaxf(x, -80.f);
    float y = x * 1.4426950408889634f;
    int   e = __float2int_rn(y);
    float f = y - (float)e;
    float p = 1.3333558e-3f;
    p = fmaf(p, f, 9.6181292e-3f);
    p = fmaf(p, f, 5.5504109e-2f);
    p = fmaf(p, f, 2.4022651e-1f);
    p = fmaf(p, f, 6.9314718e-1f);
    p = fmaf(p, f, 1.0f);
    return __int_as_float((e + 127) << 23) * p;
}

__device__ __forceinline__ float gate_w(const float* gate, int h, int c) {
    float a = gate[h*3+0], b = gate[h*3+1], d = gate[h*3+2];
    float m = fmaxf(a, fmaxf(b, d));
    float ea = __expf(a-m), eb = __expf(b-m), ec = __expf(d-m);
    float s = ea + eb + ec;
    float num = (c == 0) ? ea : (c == 1) ? eb : ec;
    return num / s;
}
__device__ __forceinline__ void bsplit(float v, __nv_bfloat16& h, __nv_bfloat16& l) {
    h = __float2bfloat16(v);
    l = __float2bfloat16(v - __bfloat162float(h));
}
__device__ __forceinline__ uint32_t pk2(__nv_bfloat16 a, __nv_bfloat16 b) {
    __nv_bfloat162 t; t.x = a; t.y = b;
    return *reinterpret_cast<uint32_t*>(&t);
}

__device__ __forceinline__ void storeC(
    int mode, float* Cf, __nv_bfloat16* Ch, __nv_bfloat16* Cl,
    long ldc, int gm, int gn, float v)
{
    if (mode == 0) {
        Cf[(long)gm*ldc + gn] = v;
    } else if (mode == 4) {
        long idx = (long)gm*ldc + gn;
        Cf[idx] = v;
        bsplit(v, Ch[idx], Cl[idx]);
    } else if (mode == 2) {   // vT: [(b*16+h)][d][t]
        int b = gm >> 10, t = gm & 1023, h = gn >> 6, d = gn & 63;
        long idx = (((long)(b*16 + h)) * 64 + d) * 1024 + t;
        bsplit(v, Ch[idx], Cl[idx]);
    } else {                  // mode 3: [(b*16+h)][t][d]
        int b = gm >> 10, t = gm & 1023, h = gn >> 6, d = gn & 63;
        long idx = (((long)(b*16 + h)) * 1024 + t) * 64 + d;
        bsplit(v, Ch[idx], Cl[idx]);
    }
}

// ---------------- HMMA split-bf16 GEMM (unchanged core from round 6) ----------------
template<int TN>
__global__ void __launch_bounds__(256) tgemm(
    const __nv_bfloat16* __restrict__ Ah, const __nv_bfloat16* __restrict__ Al,
    const __nv_bfloat16* __restrict__ Bh, const __nv_bfloat16* __restrict__ Bl,
    int K, long lda, long ldb,
    int mode, float* __restrict__ Cf,
    __nv_bfloat16* __restrict__ Ch, __nv_bfloat16* __restrict__ Cl, long ldc)
{
    constexpr int TM = 128, STAGES = 3;
    constexpr int ROWB = 80;
    constexpr int ASZ = TM*ROWB, STG = ASZ + TN*ROWB;
    constexpr int WARPS_N = TN/32, WARPS_M = 8/WARPS_N;
    constexpr int WM = TM/WARPS_M, MI = WM/16;

    extern __shared__ char smem[];
    const int tid = threadIdx.x, wid = tid >> 5, lane = tid & 31;
    const int m0 = blockIdx.y*TM, n0 = blockIdx.x*TN;
    const int wm = wid / WARPS_N, wn = wid % WARPS_N;
    const uint32_t sbase = smem_u32(smem);

    const int NC = K / 32;
    const int total = 3 * NC;

    auto prefetch = [&](int idx, int s) {
        int t = idx / NC, k0 = (idx % NC) * 32;
        const __nv_bfloat16* A_ = (t == 2) ? Al : Ah;
        const __nv_bfloat16* B_ = (t == 1) ? Bl : Bh;
        uint32_t as = sbase + s*STG;
        uint32_t bs = as + ASZ;
        #pragma unroll 2
        for (int i = tid; i < TM*4; i += 256) {
            int r = i >> 2, c = i & 3;
            cpasync16(as + r*ROWB + c*16, A_ + (long)(m0 + r)*lda + k0 + c*8);
        }
        #pragma unroll 2
        for (int i = tid; i < TN*4; i += 256) {
            int r = i >> 2, c = i & 3;
            cpasync16(bs + r*ROWB + c*16, B_ + (long)(n0 + r)*ldb + k0 + c*8);
        }
    };

    float acc[MI][4][4] = {};
    prefetch(0, 0); CP_COMMIT();
    prefetch(1, 1); CP_COMMIT();

    for (int c = 0; c < total; c++) {
        CP_WAIT1();
        __syncthreads();
        int pc = c + 2;
        if (pc < total) prefetch(pc, pc % STAGES);
        CP_COMMIT();

        uint32_t abase = sbase + (c % STAGES)*STG;
        uint32_t bbase = abase + ASZ;
        #pragma unroll
        for (int ks = 0; ks < 2; ks++) {
            uint32_t afr[MI][4], bfr[2][4];
            #pragma unroll
            for (int mi = 0; mi < MI; mi++)
                ldsm4(afr[mi], abase + (wm*WM + mi*16 + (lane & 15))*ROWB
                               + ks*32 + (lane >> 4)*16);
            #pragma unroll
            for (int bi = 0; bi < 2; bi++)
                ldsm4(bfr[bi], bbase + (wn*32 + bi*16 + (lane & 15))*ROWB
                               + ks*32 + (lane >> 4)*16);
            #pragma unroll
            for (int mi = 0; mi < MI; mi++) {
                #pragma unroll
                for (int ni = 0; ni < 4; ni++) {
                    uint32_t bb[2];
                    bb[0] = (ni & 1) ? bfr[ni>>1][1] : bfr[ni>>1][0];
                    bb[1] = (ni & 1) ? bfr[ni>>1][3] : bfr[ni>>1][2];
                    mma16816(acc[mi][ni], afr[mi], bb);
                }
            }
        }
    }

    #pragma unroll
    for (int mi = 0; mi < MI; mi++) {
        #pragma unroll
        for (int ni = 0; ni < 4; ni++) {
            int rb = m0 + wm*WM + mi*16 + (lane >> 2);
            int cb = n0 + wn*32 + ni*8 + (lane & 3)*2;
            storeC(mode, Cf, Ch, Cl, ldc, rb,   cb,   acc[mi][ni][0]);
            storeC(mode, Cf, Ch, Cl, ldc, rb,   cb+1, acc[mi][ni][1]);
            storeC(mode, Cf, Ch, Cl, ldc, rb+8, cb,   acc[mi][ni][2]);
            storeC(mode, Cf, Ch, Cl, ldc, rb+8, cb+1, acc[mi][ni][3]);
        }
    }
}

// ---------------- fused flash branch 1 ----------------
// grid (8 qtiles, 64 bh), 256 threads. Writes comb = g0[h] * out1 (overwrite).
// smem: Qh/Ql 2*18432 | K stages 2*(2*18432) | V stages 2*(2*17408) = 180224 B
#define FL_SMEM 180224
__global__ void __launch_bounds__(256) flash1(const float* __restrict__ gate)
{
    extern __shared__ char smem[];
    const int tid = threadIdx.x, wid = tid >> 5, lane = tid & 31;
    const int m0 = blockIdx.x * 128;
    const int bh = blockIdx.y;
    const uint32_t sb = smem_u32(smem);
    const uint32_t sQh = sb, sQl = sb + 18432;

    const long qoff = (long)bh * TT * DD;
    const long voff = (long)bh * DD * TT;

    // Q tile (hi+lo) via cp.async — group 0
    for (int i = tid; i < 128*8; i += 256) {
        int r = i >> 3, c = i & 7;
        cpasync16(sQh + r*144 + c*16, g_qsh + qoff + (long)(m0+r)*64 + c*8);
        cpasync16(sQl + r*144 + c*16, g_qsl + qoff + (long)(m0+r)*64 + c*8);
    }
    CP_COMMIT();

    const int nchunks = m0/128 + 1;
    auto pf = [&](int cidx, int st) {
        uint32_t kh = sb + 36864 + st*36864, kl = kh + 18432;
        uint32_t vh = sb + 110592 + st*34816, vl = vh + 17408;
        int j0 = cidx * 128;
        for (int i = tid; i < 128*8; i += 256) {
            int r = i >> 3, c = i & 7;
            cpasync16(kh + r*144 + c*16, g_ksh + qoff + (long)(j0+r)*64 + c*8);
            cpasync16(kl + r*144 + c*16, g_ksl + qoff + (long)(j0+r)*64 + c*8);
        }
        for (int i = tid; i < 64*16; i += 256) {
            int r = i >> 4, c = i & 15;
            cpasync16(vh + r*272 + c*16, g_vth + voff + (long)r*TT + j0 + c*8);
            cpasync16(vl + r*272 + c*16, g_vtl + voff + (long)r*TT + j0 + c*8);
        }
    };
    pf(0, 0); CP_COMMIT();

    uint32_t qfh[4][4], qfl[4][4];
    float oa[8][4] = {};
    float ms0 = -1e30f, ms1 = -1e30f, l0 = 0.f, l1 = 0.f;

    for (int c = 0; c < nchunks; c++) {
        if (c + 1 < nchunks) pf(c + 1, (c + 1) & 1);
        CP_COMMIT();
        CP_WAIT1();
        __syncthreads();

        if (c == 0) {
            #pragma unroll
            for (int ks = 0; ks < 4; ks++) {
                ldsm4(qfh[ks], sQh + (wid*16 + (lane & 15))*144 + ks*32 + (lane >> 4)*16);
                ldsm4(qfl[ks], sQl + (wid*16 + (lane & 15))*144 + ks*32 + (lane >> 4)*16);
            }
        }

        const int st = c & 1, j0 = c * 128;
        const uint32_t khb = sb + 36864 + st*36864, klb = khb + 18432;
        const uint32_t vhb = sb + 110592 + st*34816, vlb = vhb + 17408;

        // ---- S = 0.125 * (Qh Kh^T + Qh Kl^T + Ql Kh^T) ----
        float sa[16][4];
        #pragma unroll
        for (int nt = 0; nt < 16; nt++)
            sa[nt][0] = sa[nt][1] = sa[nt][2] = sa[nt][3] = 0.f;

        #pragma unroll
        for (int term = 0; term < 3; term++) {
            const uint32_t (*aq)[4] = (term == 2) ? qfl : qfh;
            uint32_t kb = (term == 1) ? klb : khb;
            #pragma unroll
            for (int ks = 0; ks < 4; ks++) {
                uint32_t bf4[8][4];
                #pragma unroll
                for (int g = 0; g < 8; g++)
                    ldsm4(bf4[g], kb + (g*16 + (lane & 15))*144 + ks*32 + (lane >> 4)*16);
                #pragma unroll
                for (int nt = 0; nt < 16; nt++) {
                    uint32_t b2[2] = { bf4[nt>>1][nt & 1], bf4[nt>>1][(nt & 1) + 2] };
                    mma16816(sa[nt], aq[ks], b2);
                }
            }
        }

        const int qr0 = m0 + wid*16 + (lane >> 2);
        const int qr1 = qr0 + 8;
        // scale + causal mask (diag chunk only)
        if (j0 == m0) {
            #pragma unroll
            for (int nt = 0; nt < 16; nt++) {
                int col = j0 + nt*8 + (lane & 3)*2;
                sa[nt][0] = (col     > qr0) ? -1e30f : sa[nt][0]*0.125f;
                sa[nt][1] = (col + 1 > qr0) ? -1e30f : sa[nt][1]*0.125f;
                sa[nt][2] = (col     > qr1) ? -1e30f : sa[nt][2]*0.125f;
                sa[nt][3] = (col + 1 > qr1) ? -1e30f : sa[nt][3]*0.125f;
            }
        } else {
            #pragma unroll
            for (int nt = 0; nt < 16; nt++) {
                sa[nt][0] *= 0.125f; sa[nt][1] *= 0.125f;
                sa[nt][2] *= 0.125f; sa[nt][3] *= 0.125f;
            }
        }

        // row max (quad holds cols of same rows)
        float mx0 = -1e30f, mx1 = -1e30f;
        #pragma unroll
        for (int nt = 0; nt < 16; nt++) {
            mx0 = fmaxf(mx0, fmaxf(sa[nt][0], sa[nt][1]));
            mx1 = fmaxf(mx1, fmaxf(sa[nt][2], sa[nt][3]));
        }
        mx0 = fmaxf(mx0, __shfl_xor_sync(0xffffffffu, mx0, 1));
        mx0 = fmaxf(mx0, __shfl_xor_sync(0xffffffffu, mx0, 2));
        mx1 = fmaxf(mx1, __shfl_xor_sync(0xffffffffu, mx1, 1));
        mx1 = fmaxf(mx1, __shfl_xor_sync(0xffffffffu, mx1, 2));

        float mn0 = fmaxf(ms0, mx0), mn1 = fmaxf(ms1, mx1);
        float cor0 = fexp(ms0 - mn0), cor1 = fexp(ms1 - mn1);

        float rs0 = 0.f, rs1 = 0.f;
        #pragma unroll
        for (int nt = 0; nt < 16; nt++) {
            sa[nt][0] = fexp(sa[nt][0] - mn0);
            sa[nt][1] = fexp(sa[nt][1] - mn0);
            sa[nt][2] = fexp(sa[nt][2] - mn1);
            sa[nt][3] = fexp(sa[nt][3] - mn1);
            rs0 += sa[nt][0] + sa[nt][1];
            rs1 += sa[nt][2] + sa[nt][3];
        }
        rs0 += __shfl_xor_sync(0xffffffffu, rs0, 1);
        rs0 += __shfl_xor_sync(0xffffffffu, rs0, 2);
        rs1 += __shfl_xor_sync(0xffffffffu, rs1, 1);
        rs1 += __shfl_xor_sync(0xffffffffu, rs1, 2);
        l0 = l0*cor0 + rs0;
        l1 = l1*cor1 + rs1;
        ms0 = mn0; ms1 = mn1;
        #pragma unroll
        for (int dn = 0; dn < 8; dn++) {
            oa[dn][0] *= cor0; oa[dn][1] *= cor0;
            oa[dn][2] *= cor1; oa[dn][3] *= cor1;
        }

        // ---- O += Ph Vh + Pl Vh + Ph Vl ----
        #pragma unroll
        for (int ks = 0; ks < 8; ks++) {
            uint32_t aH[4], aL[4];
            {
                float p0 = sa[2*ks][0],   p1 = sa[2*ks][1];
                float p2 = sa[2*ks][2],   p3 = sa[2*ks][3];
                float r0 = sa[2*ks+1][0], r1 = sa[2*ks+1][1];
                float r2 = sa[2*ks+1][2], r3 = sa[2*ks+1][3];
                __nv_bfloat16 h0 = __float2bfloat16(p0), h1 = __float2bfloat16(p1);
                __nv_bfloat16 h2 = __float2bfloat16(p2), h3 = __float2bfloat16(p3);
                __nv_bfloat16 g0 = __float2bfloat16(r0), g1 = __float2bfloat16(r1);
                __nv_bfloat16 g2 = __float2bfloat16(r2), g3 = __float2bfloat16(r3);
                aH[0] = pk2(h0, h1); aH[1] = pk2(h2, h3);
                aH[2] = pk2(g0, g1); aH[3] = pk2(g2, g3);
                aL[0] = pk2(__float2bfloat16(p0 - __bfloat162float(h0)),
                            __float2bfloat16(p1 - __bfloat162float(h1)));
                aL[1] = pk2(__float2bfloat16(p2 - __bfloat162float(h2)),
                            __float2bfloat16(p3 - __bfloat162float(h3)));
                aL[2] = pk2(__float2bfloat16(r0 - __bfloat162float(g0)),
                            __float2bfloat16(r1 - __bfloat162float(g1)));
                aL[3] = pk2(__float2bfloat16(r2 - __bfloat162float(g2)),
                            __float2bfloat16(r3 - __bfloat162float(g3)));
            }
            uint32_t bvh[4][4], bvl[4][4];
            #pragma unroll
            for (int g = 0; g < 4; g++) {
                ldsm4(bvh[g], vhb + (g*16 + (lane & 15))*272 + ks*32 + (lane >> 4)*16);
                ldsm4(bvl[g], vlb + (g*16 + (lane & 15))*272 + ks*32 + (lane >> 4)*16);
            }
            #pragma unroll
            for (int dn = 0; dn < 8; dn++) {
                uint32_t b2h[2] = { bvh[dn>>1][dn & 1], bvh[dn>>1][(dn & 1) + 2] };
                uint32_t b2l[2] = { bvl[dn>>1][dn & 1], bvl[dn>>1][(dn & 1) + 2] };
                mma16816(oa[dn], aH, b2h);
                mma16816(oa[dn], aL, b2h);
                mma16816(oa[dn], aH, b2l);
            }
        }
        __syncthreads();  // protect stage reuse by next prefetch
    }

    // epilogue: comb[b][t][h*64+d] = g0 * O / l
    const float g0w = gate_w(gate, bh & 15, 0);
    const float s0 = g0w / l0, s1 = g0w / l1;
    const int b = bh >> 4, h = bh & 15;
    const int qr0 = m0 + wid*16 + (lane >> 2), qr1 = qr0 + 8;
    float* c0 = g_comb + ((long)b*TT + qr0)*EE + h*64;
    float* c1 = g_comb + ((long)b*TT + qr1)*EE + h*64;
    #pragma unroll
    for (int dn = 0; dn < 8; dn++) {
        int d = dn*8 + (lane & 3)*2;
        c0[d]   = oa[dn][0]*s0; c0[d+1] = oa[dn][1]*s0;
        c1[d]   = oa[dn][2]*s1; c1[d+1] = oa[dn][3]*s1;
    }
}

// ---------------- conversion kernels (vectorized x4) ----------------
__global__ void conv_split(const float* __restrict__ in,
                           __nv_bfloat16* __restrict__ h, __nv_bfloat16* __restrict__ l, int n)
{
    int i = (blockIdx.x * 256 + threadIdx.x) * 4;
    if (i >= n) return;
    float4 v = *(const float4*)(in + i);
    __nv_bfloat16 h0,h1,h2,h3,l0,l1,l2,l3;
    bsplit(v.x,h0,l0); bsplit(v.y,h1,l1); bsplit(v.z,h2,l2); bsplit(v.w,h3,l3);
    *(uint2*)(h + i) = make_uint2(pk2(h0,h1), pk2(h2,h3));
    *(uint2*)(l + i) = make_uint2(pk2(l0,l1), pk2(l2,l3));
}
__global__ void conv_split_T(const float* __restrict__ in,
                             __nv_bfloat16* __restrict__ h, __nv_bfloat16* __restrict__ l)
{   // out[e*E+f] = in[f*E+e]
    int i = blockIdx.x * 256 + threadIdx.x;
    int e = i >> 10, f = i & 1023;
    bsplit(in[(long)f * EE + e], h[i], l[i]);
}

// ---------------- s2[b,h,t] = (1/8) dot(x[b,t,:], wr[h,:,t]) ----------------
__global__ void s2_kernel(const float* __restrict__ x, const float* __restrict__ wr)
{
    __shared__ float xs[256][33];
    int t0 = blockIdx.x * 256;
    int h = blockIdx.y, b = blockIdx.z;
    int tid = threadIdx.x, w = tid >> 5, lane = tid & 31;
    int t = t0 + tid;
    float acc = 0.f;
    for (int e0 = 0; e0 < EE; e0 += 32) {
        #pragma unroll 4
        for (int rr = 0; rr < 32; rr++)
            xs[w*32 + rr][lane] = x[(long)b*TT*EE + (long)(t0 + w*32 + rr)*EE + e0 + lane];
        __syncthreads();
        const float* wrp = wr + (long)h*EE*TT + (long)e0*TT + t;
        #pragma unroll
        for (int e = 0; e < 32; e++) acc += xs[tid][e] * wrp[(long)e*TT];
        __syncthreads();
    }
    g_s2[(b*HH + h)*TT + t] = acc * 0.125f;
}

// ---------------- sc[b,t] = dot(x[b,t], eb[b,t]) / 32 ----------------
__global__ void sc_kernel(const float* __restrict__ x)
{
    __shared__ float red[256];
    long base = (long)blockIdx.x * EE;
    int tid = threadIdx.x;
    float s = 0.f;
    for (int e = tid; e < EE; e += 256) s += x[base+e] * g_eb[base+e];
    red[tid] = s; __syncthreads();
    for (int st = 128; st; st >>= 1) { if (tid < st) red[tid] += red[tid+st]; __syncthreads(); }
    if (tid == 0) g_sc[blockIdx.x] = red[0] * (1.f/32.f);
}

// ---------------- branch 2: segmented parallel prefix softmax-scan ----------------
// grid BH, 512 threads. comb += g1 * out2. Global-max softmax (exact here).
__global__ void __launch_bounds__(512) branch2_kernel(const float* __restrict__ gate)
{
    __shared__ float w[TT], inv[TT], seg[16][64], red[512];
    int bh = blockIdx.x, b = bh >> 4, h = bh & 15;
    int tid = threadIdx.x, wp = tid >> 5, ln = tid & 31;
    const float* s2p = g_s2 + bh*TT;

    float m = fmaxf(s2p[tid], s2p[tid + 512]);
    red[tid] = m; __syncthreads();
    for (int st = 256; st; st >>= 1) { if (tid < st) red[tid] = fmaxf(red[tid], red[tid+st]); __syncthreads(); }
    m = red[0]; __syncthreads();

    float w0 = fexp(s2p[2*tid] - m), w1 = fexp(s2p[2*tid+1] - m);
    w[2*tid] = w0; w[2*tid+1] = w1;
    red[tid] = w0 + w1; __syncthreads();
    for (int off = 1; off < 512; off <<= 1) {
        float v = (tid >= off) ? red[tid - off] : 0.f;
        __syncthreads();
        red[tid] += v;
        __syncthreads();
    }
    float basep = (tid == 0) ? 0.f : red[tid - 1];
    inv[2*tid]   = 1.f / (basep + w0);
    inv[2*tid+1] = 1.f / (basep + w0 + w1);
    __syncthreads();

    // segment partial sums: warp wp owns j in [wp*64, wp*64+64), lanes own d = ln, ln+32
    const float* rvp = g_rv + (long)b*TT*EE + h*64;
    float p0 = 0.f, p1 = 0.f;
    for (int j = wp*64; j < wp*64 + 64; j++) {
        float wj = w[j];
        p0 += wj * rvp[(long)j*EE + ln];
        p1 += wj * rvp[(long)j*EE + ln + 32];
    }
    seg[wp][ln] = p0; seg[wp][ln + 32] = p1;
    __syncthreads();
    if (tid < 64) {   // exclusive prefix across segments per d
        float a = 0.f;
        #pragma unroll
        for (int s = 0; s < 16; s++) { float t = seg[s][tid]; seg[s][tid] = a; a += t; }
    }
    __syncthreads();

    float g1 = gate_w(gate, h, 1);
    float a0 = seg[wp][ln], a1 = seg[wp][ln + 32];
    float* cp = g_comb + (long)b*TT*EE + h*64;
    for (int j = wp*64; j < wp*64 + 64; j++) {
        float wj = w[j], iv = inv[j];
        a0 += wj * rvp[(long)j*EE + ln];
        a1 += wj * rvp[(long)j*EE + ln + 32];
        cp[(long)j*EE + ln]      += g1 * a0 * iv;
        cp[(long)j*EE + ln + 32] += g1 * a1 * iv;
    }
}

// ---------------- branch 3: rank-1 softmax + weighted echo sum (16-row tiles) ----------------
__global__ void branch3_kernel(const float* __restrict__ gate)
{
    extern __shared__ float p[];   // [16][1024]
    int b  = blockIdx.x / (TT/16);
    int i0 = (blockIdx.x % (TT/16)) * 16;
    int tid = threadIdx.x, r = tid >> 5, lane = tid & 31;
    int jmax = i0 + 16;

    const float* scb = g_sc + b*TT;
    #pragma unroll
    for (int half = 0; half < 2; half++) {
        int rr = r + half*8;
        int i = i0 + rr;
        float* pr = p + rr*1024;
        float sci = scb[i];
        float m = -CUDART_INF_F;
        for (int j = lane; j <= i; j += 32) m = fmaxf(m, sci * scb[j]);
        #pragma unroll
        for (int o = 16; o; o >>= 1) m = fmaxf(m, __shfl_xor_sync(0xffffffffu, m, o));
        float sum = 0.f;
        for (int j = lane; j <= i; j += 32) {
            float wv = fexp(sci * scb[j] - m);
            pr[j] = wv; sum += wv;
        }
        #pragma unroll
        for (int o = 16; o; o >>= 1) sum += __shfl_xor_sync(0xffffffffu, sum, o);
        float iv = 1.f / sum;
        for (int j = lane; j <= i; j += 32) pr[j] *= iv;
        for (int j = i + 1 + lane; j < jmax; j += 32) pr[j] = 0.f;
    }
    __syncthreads();

    int e0 = tid * 4;
    int h = e0 / DD;
    float g2 = gate_w(gate, h, 2);
    float acc[16][4] = {};
    const float* ebase = g_echo + (long)b*TT*EE + e0;
    for (int j = 0; j < jmax; j++) {
        float4 ev = *(const float4*)(ebase + (long)j*EE);
        #pragma unroll
        for (int rr = 0; rr < 16; rr++) {
            float pr = p[rr*1024 + j];
            acc[rr][0] += pr * ev.x; acc[rr][1] += pr * ev.y;
            acc[rr][2] += pr * ev.z; acc[rr][3] += pr * ev.w;
        }
    }
    #pragma unroll
    for (int rr = 0; rr < 16; rr++) {
        float* cp = g_comb + (long)b*TT*EE + (long)(i0+rr)*EE + e0;
        cp[0] += g2*acc[rr][0]; cp[1] += g2*acc[rr][1];
        cp[2] += g2*acc[rr][2]; cp[3] += g2*acc[rr][3];
    }
}

// ---------------- host launch ----------------
extern "C" void kernel_launch(void* const* d_in, const int* in_sizes, int n_in,
                              void* d_out, int out_size)
{
    const float* x    = (const float*)d_in[0];
    const float* wq   = (const float*)d_in[1];
    const float* wk   = (const float*)d_in[2];
    const float* wv   = (const float*)d_in[3];
    const float* wvr  = (const float*)d_in[4];
    const float* wr   = (const float*)d_in[5];
    const float* wj   = (const float*)d_in[6];
    const float* gate = (const float*)d_in[7];
    const float* wo   = (const float*)d_in[8];
    float* out = (float*)d_out;

#define GA(sym, var, type) type* var; cudaGetSymbolAddress((void**)&var, sym)
    GA(g_xh, xh, __nv_bfloat16);   GA(g_xl, xl, __nv_bfloat16);
    GA(g_wqh, wqh, __nv_bfloat16); GA(g_wql, wql, __nv_bfloat16);
    GA(g_wkh, wkh, __nv_bfloat16); GA(g_wkl, wkl, __nv_bfloat16);
    GA(g_wvh, wvh, __nv_bfloat16); GA(g_wvl, wvl, __nv_bfloat16);
    GA(g_wrh, wrh, __nv_bfloat16); GA(g_wrl, wrl, __nv_bfloat16);
    GA(g_wjh, wjh, __nv_bfloat16); GA(g_wjl, wjl, __nv_bfloat16);
    GA(g_wjTh, wjTh, __nv_bfloat16); GA(g_wjTl, wjTl, __nv_bfloat16);
    GA(g_woh, woh, __nv_bfloat16); GA(g_wol, wol, __nv_bfloat16);
    GA(g_qsh, qsh, __nv_bfloat16); GA(g_qsl, qsl, __nv_bfloat16);
    GA(g_ksh, ksh, __nv_bfloat16); GA(g_ksl, ksl, __nv_bfloat16);
    GA(g_vth, vth, __nv_bfloat16); GA(g_vtl, vtl, __nv_bfloat16);
    GA(g_rv, rvf, float);
    GA(g_echo, echof, float);
    GA(g_eh, eh, __nv_bfloat16);   GA(g_el, el, __nv_bfloat16);
    GA(g_eb, ebf, float);
    GA(g_comb, combf, float);
    GA(g_ch, ch, __nv_bfloat16);   GA(g_cl, cl, __nv_bfloat16);
#undef GA

    const int SM128 = 3 * (128 + 128) * 80;   // 61440
    cudaFuncSetAttribute(tgemm<128>, cudaFuncAttributeMaxDynamicSharedMemorySize, SM128);
    cudaFuncSetAttribute(flash1, cudaFuncAttributeMaxDynamicSharedMemorySize, FL_SMEM);
    cudaFuncSetAttribute(branch3_kernel, cudaFuncAttributeMaxDynamicSharedMemorySize, 65536);

    // --- bf16 hi/lo splits of inputs ---
    conv_split<<<(BT*EE)/1024, 256>>>(x,   xh,  xl,  BT*EE);
    conv_split<<<(EE*EE)/1024, 256>>>(wq,  wqh, wql, EE*EE);
    conv_split<<<(EE*EE)/1024, 256>>>(wk,  wkh, wkl, EE*EE);
    conv_split<<<(EE*EE)/1024, 256>>>(wv,  wvh, wvl, EE*EE);
    conv_split<<<(EE*EE)/1024, 256>>>(wvr, wrh, wrl, EE*EE);
    conv_split<<<(EE*EE)/1024, 256>>>(wj,  wjh, wjl, EE*EE);
    conv_split<<<(EE*EE)/1024, 256>>>(wo,  woh, wol, EE*EE);
    conv_split_T<<<(EE*EE)/256, 256>>>(wj, wjTh, wjTl);

    dim3 big(8, 32, 1);
    // projections: y = x @ W^T
    tgemm<128><<<big, 256, SM128>>>(xh, xl, wqh, wql, 1024, 1024, 1024,
                                    3, nullptr, qsh, qsl, 0);
    tgemm<128><<<big, 256, SM128>>>(xh, xl, wkh, wkl, 1024, 1024, 1024,
                                    3, nullptr, ksh, ksl, 0);
    tgemm<128><<<big, 256, SM128>>>(xh, xl, wvh, wvl, 1024, 1024, 1024,
                                    2, nullptr, vth, vtl, 0);
    tgemm<128><<<big, 256, SM128>>>(xh, xl, wrh, wrl, 1024, 1024, 1024,
                                    0, rvf, nullptr, nullptr, 1024);
    tgemm<128><<<big, 256, SM128>>>(xh, xl, wjh, wjl, 1024, 1024, 1024,
                                    4, echof, eh, el, 1024);
    tgemm<128><<<big, 256, SM128>>>(eh, el, wjTh, wjTl, 1024, 1024, 1024,
                                    0, ebf, nullptr, nullptr, 1024);

    s2_kernel<<<dim3(TT/256, HH, BB), 256>>>(x, wr);
    sc_kernel<<<BT, 256>>>(x);

    // branch 1 fused: comb = g0[h] * flash_attention(q,k,v)
    flash1<<<dim3(8, 64), 256, FL_SMEM>>>(gate);

    branch2_kernel<<<BH, 512>>>(gate);
    branch3_kernel<<<BB*(TT/16), 256, 65536>>>(gate);

    // final: out = comb @ wo^T
    conv_split<<<(BT*EE)/1024, 256>>>(combf, ch, cl, BT*EE);
    tgemm<128><<<big, 256, SM128>>>(ch, cl, woh, wol, 1024, 1024, 1024,
                                    0, out, nullptr, nullptr, 1024);
}

// round 9
// speedup vs baseline: 4.6690x; 1.5694x over previous
#include <cuda_runtime.h>
#include <cuda_bf16.h>
#include <math_constants.h>
#include <cstdint>

#define BB 4
#define TT 1024
#define EE 1024
#define HH 16
#define DD 64
#define BT (BB*TT)   // 4096
#define BH (BB*HH)   // 64

// ---------------- scratch (device globals) ----------------
__device__ __nv_bfloat16 g_xh[BT*EE],  g_xl[BT*EE];
__device__ __nv_bfloat16 g_wqh[EE*EE], g_wql[EE*EE];
__device__ __nv_bfloat16 g_wkh[EE*EE], g_wkl[EE*EE];
__device__ __nv_bfloat16 g_wvh[EE*EE], g_wvl[EE*EE];
__device__ __nv_bfloat16 g_wrh[EE*EE], g_wrl[EE*EE];   // wvr
__device__ __nv_bfloat16 g_wjh[EE*EE], g_wjl[EE*EE];
__device__ __nv_bfloat16 g_wjTh[EE*EE],g_wjTl[EE*EE];
__device__ __nv_bfloat16 g_woh[EE*EE], g_wol[EE*EE];
__device__ __nv_bfloat16 g_qsh[BH*TT*DD], g_qsl[BH*TT*DD];  // [bh][t][d]
__device__ __nv_bfloat16 g_ksh[BH*TT*DD], g_ksl[BH*TT*DD];  // [bh][t][d]
__device__ __nv_bfloat16 g_vth[BH*DD*TT], g_vtl[BH*DD*TT];  // [bh][d][t]
__device__ float g_rv[BT*EE];
__device__ float g_echo[BT*EE];
__device__ __nv_bfloat16 g_eh[BT*EE], g_el[BT*EE];
__device__ __nv_bfloat16 g_eTh[BT*EE], g_eTl[BT*EE];        // echo^T per batch [b][e][t]
__device__ float g_eb[BT*EE];
__device__ float g_comb[BT*EE];
__device__ __nv_bfloat16 g_ch[BT*EE], g_cl[BT*EE];
__device__ __nv_bfloat16 g_p3h[(long)BB*TT*TT], g_p3l[(long)BB*TT*TT];  // branch-3 probs
__device__ float g_s2[BH*TT];
__device__ float g_sc[BB*TT];

// ---------------- helpers ----------------
__device__ __forceinline__ uint32_t smem_u32(const void* p) {
    uint32_t a;
    asm("{ .reg .u64 t; cvta.to.shared.u64 t, %1; cvt.u32.u64 %0, t; }" : "=r"(a) : "l"(p));
    return a;
}
__device__ __forceinline__ void cpasync16(uint32_t saddr, const void* g) {
    asm volatile("cp.async.cg.shared.global [%0], [%1], 16;" :: "r"(saddr), "l"(g));
}
#define CP_COMMIT() asm volatile("cp.async.commit_group;" ::: "memory")
#define CP_WAIT1()  asm volatile("cp.async.wait_group 1;"  ::: "memory")

__device__ __forceinline__ void ldsm4(uint32_t* r, uint32_t addr) {
    asm volatile("ldmatrix.sync.aligned.m8n8.x4.shared.b16 {%0,%1,%2,%3}, [%4];"
        : "=r"(r[0]), "=r"(r[1]), "=r"(r[2]), "=r"(r[3]) : "r"(addr));
}
__device__ __forceinline__ void mma16816(float* d, const uint32_t* a, const uint32_t* b) {
    asm volatile("mma.sync.aligned.m16n8k16.row.col.f32.bf16.bf16.f32 "
        "{%0,%1,%2,%3}, {%4,%5,%6,%7}, {%8,%9}, {%0,%1,%2,%3};"
        : "+f"(d[0]), "+f"(d[1]), "+f"(d[2]), "+f"(d[3])
        : "r"(a[0]), "r"(a[1]), "r"(a[2]), "r"(a[3]), "r"(b[0]), "r"(b[1]));
}

// fast exp on FMA pipe. valid x <= 0; clamps below -80. rel err < 3e-6.
__device__ __forceinline__ float fexp(float x) {
    x = fmaxf(x, -80.f);
    float y = x * 1.4426950408889634f;
    int   e = __float2int_rn(y);
    float f = y - (float)e;
    float p = 1.3333558e-3f;
    p = fmaf(p, f, 9.6181292e-3f);
    p = fmaf(p, f, 5.5504109e-2f);
    p = fmaf(p, f, 2.4022651e-1f);
    p = fmaf(p, f, 6.9314718e-1f);
    p = fmaf(p, f, 1.0f);
    return __int_as_float((e + 127) << 23) * p;
}

__device__ __forceinline__ float gate_w(const float* gate, int h, int c) {
    float a = gate[h*3+0], b = gate[h*3+1], d = gate[h*3+2];
    float m = fmaxf(a, fmaxf(b, d));
    float ea = __expf(a-m), eb = __expf(b-m), ec = __expf(d-m);
    float s = ea + eb + ec;
    float num = (c == 0) ? ea : (c == 1) ? eb : ec;
    return num / s;
}
__device__ __forceinline__ void bsplit(float v, __nv_bfloat16& h, __nv_bfloat16& l) {
    h = __float2bfloat16(v);
    l = __float2bfloat16(v - __bfloat162float(h));
}
__device__ __forceinline__ uint32_t pk2(__nv_bfloat16 a, __nv_bfloat16 b) {
    __nv_bfloat162 t; t.x = a; t.y = b;
    return *reinterpret_cast<uint32_t*>(&t);
}

// ---------------- single-pass 3-term HMMA split-bf16 GEMM ----------------
// C = sum_k (AhBh + AhBl + AlBh); all four operand tiles staged per K-chunk,
// 3 MMA terms per fragment set. 2-stage cp.async pipeline, 2 CTA/SM.
// modes: 0 fp32 store; 2 vT-split; 3 ts-split; 4 fp32+split; 5 fp32 += gate2[h(gn)]*v
template<int TN>
__global__ void __launch_bounds__(256, 2) tgemm(
    const __nv_bfloat16* __restrict__ Ah_, const __nv_bfloat16* __restrict__ Al_,
    const __nv_bfloat16* __restrict__ Bh_, const __nv_bfloat16* __restrict__ Bl_,
    int K, long lda, long ldb, long sAz, long sBz, int kcap,
    int mode, float* __restrict__ Cf,
    __nv_bfloat16* __restrict__ Ch, __nv_bfloat16* __restrict__ Cl,
    long ldc, long sCz, const float* __restrict__ gate)
{
    constexpr int TM = 128, ROWB = 80;
    constexpr int AOFF_L = TM*ROWB;
    constexpr int BOFF_H = 2*TM*ROWB;
    constexpr int BOFF_L = 2*TM*ROWB + TN*ROWB;
    constexpr int STG = 2*TM*ROWB + 2*TN*ROWB;
    constexpr int WARPS_N = TN/32, WARPS_M = 8/WARPS_N;
    constexpr int WM = TM/WARPS_M, MI = WM/16;

    extern __shared__ char smem[];
    __shared__ float sgate[16];
    const int tid = threadIdx.x, wid = tid >> 5, lane = tid & 31;
    const int m0 = blockIdx.y*TM, n0 = blockIdx.x*TN, z = blockIdx.z;
    const int wm = wid / WARPS_N, wn = wid % WARPS_N;
    const uint32_t sbase = smem_u32(smem);

    if (mode == 5 && tid < 16) sgate[tid] = gate_w(gate, tid, 2);

    const __nv_bfloat16* Ah = Ah_ + (long)z*sAz;
    const __nv_bfloat16* Al = Al_ + (long)z*sAz;
    const __nv_bfloat16* Bh = Bh_ + (long)z*sBz;
    const __nv_bfloat16* Bl = Bl_ + (long)z*sBz;

    const int Keff = kcap ? (m0 + TM) : K;
    const int NC = Keff / 32;

    auto prefetch = [&](int c, int s) {
        int k0 = c * 32;
        uint32_t st = sbase + s*STG;
        #pragma unroll 2
        for (int i = tid; i < TM*4; i += 256) {
            int r = i >> 2, cc = i & 3;
            long go = (long)(m0 + r)*lda + k0 + cc*8;
            cpasync16(st + r*ROWB + cc*16,            Ah + go);
            cpasync16(st + AOFF_L + r*ROWB + cc*16,   Al + go);
        }
        #pragma unroll 2
        for (int i = tid; i < TN*4; i += 256) {
            int r = i >> 2, cc = i & 3;
            long go = (long)(n0 + r)*ldb + k0 + cc*8;
            cpasync16(st + BOFF_H + r*ROWB + cc*16,   Bh + go);
            cpasync16(st + BOFF_L + r*ROWB + cc*16,   Bl + go);
        }
    };

    float acc[MI][4][4] = {};
    prefetch(0, 0); CP_COMMIT();

    for (int c = 0; c < NC; c++) {
        if (c + 1 < NC) prefetch(c + 1, (c + 1) & 1);
        CP_COMMIT();
        CP_WAIT1();
        __syncthreads();

        uint32_t st = sbase + (c & 1)*STG;
        #pragma unroll
        for (int ks = 0; ks < 2; ks++) {
            uint32_t aH[MI][4], bH[2][4], bL[2][4];
            #pragma unroll
            for (int mi = 0; mi < MI; mi++)
                ldsm4(aH[mi], st + (wm*WM + mi*16 + (lane & 15))*ROWB
                              + ks*32 + (lane >> 4)*16);
            #pragma unroll
            for (int bi = 0; bi < 2; bi++) {
                ldsm4(bH[bi], st + BOFF_H + (wn*32 + bi*16 + (lane & 15))*ROWB
                              + ks*32 + (lane >> 4)*16);
                ldsm4(bL[bi], st + BOFF_L + (wn*32 + bi*16 + (lane & 15))*ROWB
                              + ks*32 + (lane >> 4)*16);
            }
            #pragma unroll
            for (int mi = 0; mi < MI; mi++) {
                #pragma unroll
                for (int ni = 0; ni < 4; ni++) {
                    uint32_t h2[2] = { bH[ni>>1][ni & 1], bH[ni>>1][(ni & 1) + 2] };
                    uint32_t l2[2] = { bL[ni>>1][ni & 1], bL[ni>>1][(ni & 1) + 2] };
                    mma16816(acc[mi][ni], aH[mi], h2);
                    mma16816(acc[mi][ni], aH[mi], l2);
                }
            }
            uint32_t aL[MI][4];
            #pragma unroll
            for (int mi = 0; mi < MI; mi++)
                ldsm4(aL[mi], st + AOFF_L + (wm*WM + mi*16 + (lane & 15))*ROWB
                              + ks*32 + (lane >> 4)*16);
            #pragma unroll
            for (int mi = 0; mi < MI; mi++) {
                #pragma unroll
                for (int ni = 0; ni < 4; ni++) {
                    uint32_t h2[2] = { bH[ni>>1][ni & 1], bH[ni>>1][(ni & 1) + 2] };
                    mma16816(acc[mi][ni], aL[mi], h2);
                }
            }
        }
        __syncthreads();
    }

    // epilogue
    float* CfB = Cf ? (Cf + (long)z*sCz) : nullptr;
    #pragma unroll
    for (int mi = 0; mi < MI; mi++) {
        #pragma unroll
        for (int ni = 0; ni < 4; ni++) {
            int rb = m0 + wm*WM + mi*16 + (lane >> 2);
            int cb = n0 + wn*32 + ni*8 + (lane & 3)*2;
            #pragma unroll
            for (int q = 0; q < 4; q++) {
                int gm = rb + (q >> 1)*8, gn = cb + (q & 1);
                float v = acc[mi][ni][q];
                if (mode == 0) {
                    CfB[(long)gm*ldc + gn] = v;
                } else if (mode == 4) {
                    long idx = (long)gm*ldc + gn;
                    CfB[idx] = v;
                    bsplit(v, Ch[idx], Cl[idx]);
                } else if (mode == 2) {   // vT: [(b*16+h)][d][t]
                    int b = gm >> 10, t = gm & 1023, h = gn >> 6, d = gn & 63;
                    long idx = (((long)(b*16 + h)) * 64 + d) * 1024 + t;
                    bsplit(v, Ch[idx], Cl[idx]);
                } else if (mode == 3) {   // [(b*16+h)][t][d]
                    int b = gm >> 10, t = gm & 1023, h = gn >> 6, d = gn & 63;
                    long idx = (((long)(b*16 + h)) * 1024 + t) * 64 + d;
                    bsplit(v, Ch[idx], Cl[idx]);
                } else {                  // mode 5: gated accumulate
                    CfB[(long)gm*ldc + gn] += sgate[gn >> 6] * v;
                }
            }
        }
    }
}

// ---------------- fused flash branch 1 ----------------
#define FL_SMEM 180224
__global__ void __launch_bounds__(256) flash1(const float* __restrict__ gate)
{
    extern __shared__ char smem[];
    const int tid = threadIdx.x, wid = tid >> 5, lane = tid & 31;
    const int m0 = (gridDim.x - 1 - blockIdx.x) * 128;   // heavy tiles first
    const int bh = blockIdx.y;
    const uint32_t sb = smem_u32(smem);
    const uint32_t sQh = sb, sQl = sb + 18432;

    const long qoff = (long)bh * TT * DD;
    const long voff = (long)bh * DD * TT;

    for (int i = tid; i < 128*8; i += 256) {
        int r = i >> 3, c = i & 7;
        cpasync16(sQh + r*144 + c*16, g_qsh + qoff + (long)(m0+r)*64 + c*8);
        cpasync16(sQl + r*144 + c*16, g_qsl + qoff + (long)(m0+r)*64 + c*8);
    }
    CP_COMMIT();

    const int nchunks = m0/128 + 1;
    auto pf = [&](int cidx, int st) {
        uint32_t kh = sb + 36864 + st*36864, kl = kh + 18432;
        uint32_t vh = sb + 110592 + st*34816, vl = vh + 17408;
        int j0 = cidx * 128;
        for (int i = tid; i < 128*8; i += 256) {
            int r = i >> 3, c = i & 7;
            cpasync16(kh + r*144 + c*16, g_ksh + qoff + (long)(j0+r)*64 + c*8);
            cpasync16(kl + r*144 + c*16, g_ksl + qoff + (long)(j0+r)*64 + c*8);
        }
        for (int i = tid; i < 64*16; i += 256) {
            int r = i >> 4, c = i & 15;
            cpasync16(vh + r*272 + c*16, g_vth + voff + (long)r*TT + j0 + c*8);
            cpasync16(vl + r*272 + c*16, g_vtl + voff + (long)r*TT + j0 + c*8);
        }
    };
    pf(0, 0); CP_COMMIT();

    uint32_t qfh[4][4], qfl[4][4];
    float oa[8][4] = {};
    float ms0 = -1e30f, ms1 = -1e30f, l0 = 0.f, l1 = 0.f;

    for (int c = 0; c < nchunks; c++) {
        if (c + 1 < nchunks) pf(c + 1, (c + 1) & 1);
        CP_COMMIT();
        CP_WAIT1();
        __syncthreads();

        if (c == 0) {
            #pragma unroll
            for (int ks = 0; ks < 4; ks++) {
                ldsm4(qfh[ks], sQh + (wid*16 + (lane & 15))*144 + ks*32 + (lane >> 4)*16);
                ldsm4(qfl[ks], sQl + (wid*16 + (lane & 15))*144 + ks*32 + (lane >> 4)*16);
            }
        }

        const int st = c & 1, j0 = c * 128;
        const uint32_t khb = sb + 36864 + st*36864, klb = khb + 18432;
        const uint32_t vhb = sb + 110592 + st*34816, vlb = vhb + 17408;

        // ---- S: reuse Kh fragments for both Qh·Kh and Ql·Kh ----
        float sa[16][4];
        #pragma unroll
        for (int nt = 0; nt < 16; nt++)
            sa[nt][0] = sa[nt][1] = sa[nt][2] = sa[nt][3] = 0.f;

        #pragma unroll
        for (int ks = 0; ks < 4; ks++) {
            uint32_t bf4[8][4];
            #pragma unroll
            for (int g = 0; g < 8; g++)
                ldsm4(bf4[g], khb + (g*16 + (lane & 15))*144 + ks*32 + (lane >> 4)*16);
            #pragma unroll
            for (int nt = 0; nt < 16; nt++) {
                uint32_t b2[2] = { bf4[nt>>1][nt & 1], bf4[nt>>1][(nt & 1) + 2] };
                mma16816(sa[nt], qfh[ks], b2);
                mma16816(sa[nt], qfl[ks], b2);
            }
            #pragma unroll
            for (int g = 0; g < 8; g++)
                ldsm4(bf4[g], klb + (g*16 + (lane & 15))*144 + ks*32 + (lane >> 4)*16);
            #pragma unroll
            for (int nt = 0; nt < 16; nt++) {
                uint32_t b2[2] = { bf4[nt>>1][nt & 1], bf4[nt>>1][(nt & 1) + 2] };
                mma16816(sa[nt], qfh[ks], b2);
            }
        }

        const int qr0 = m0 + wid*16 + (lane >> 2);
        const int qr1 = qr0 + 8;
        if (j0 == m0) {
            #pragma unroll
            for (int nt = 0; nt < 16; nt++) {
                int col = j0 + nt*8 + (lane & 3)*2;
                sa[nt][0] = (col     > qr0) ? -1e30f : sa[nt][0]*0.125f;
                sa[nt][1] = (col + 1 > qr0) ? -1e30f : sa[nt][1]*0.125f;
                sa[nt][2] = (col     > qr1) ? -1e30f : sa[nt][2]*0.125f;
                sa[nt][3] = (col + 1 > qr1) ? -1e30f : sa[nt][3]*0.125f;
            }
        } else {
            #pragma unroll
            for (int nt = 0; nt < 16; nt++) {
                sa[nt][0] *= 0.125f; sa[nt][1] *= 0.125f;
                sa[nt][2] *= 0.125f; sa[nt][3] *= 0.125f;
            }
        }

        float mx0 = -1e30f, mx1 = -1e30f;
        #pragma unroll
        for (int nt = 0; nt < 16; nt++) {
            mx0 = fmaxf(mx0, fmaxf(sa[nt][0], sa[nt][1]));
            mx1 = fmaxf(mx1, fmaxf(sa[nt][2], sa[nt][3]));
        }
        mx0 = fmaxf(mx0, __shfl_xor_sync(0xffffffffu, mx0, 1));
        mx0 = fmaxf(mx0, __shfl_xor_sync(0xffffffffu, mx0, 2));
        mx1 = fmaxf(mx1, __shfl_xor_sync(0xffffffffu, mx1, 1));
        mx1 = fmaxf(mx1, __shfl_xor_sync(0xffffffffu, mx1, 2));

        float mn0 = fmaxf(ms0, mx0), mn1 = fmaxf(ms1, mx1);
        float cor0 = fexp(ms0 - mn0), cor1 = fexp(ms1 - mn1);

        float rs0 = 0.f, rs1 = 0.f;
        #pragma unroll
        for (int nt = 0; nt < 16; nt++) {
            sa[nt][0] = fexp(sa[nt][0] - mn0);
            sa[nt][1] = fexp(sa[nt][1] - mn0);
            sa[nt][2] = fexp(sa[nt][2] - mn1);
            sa[nt][3] = fexp(sa[nt][3] - mn1);
            rs0 += sa[nt][0] + sa[nt][1];
            rs1 += sa[nt][2] + sa[nt][3];
        }
        rs0 += __shfl_xor_sync(0xffffffffu, rs0, 1);
        rs0 += __shfl_xor_sync(0xffffffffu, rs0, 2);
        rs1 += __shfl_xor_sync(0xffffffffu, rs1, 1);
        rs1 += __shfl_xor_sync(0xffffffffu, rs1, 2);
        l0 = l0*cor0 + rs0;
        l1 = l1*cor1 + rs1;
        ms0 = mn0; ms1 = mn1;
        #pragma unroll
        for (int dn = 0; dn < 8; dn++) {
            oa[dn][0] *= cor0; oa[dn][1] *= cor0;
            oa[dn][2] *= cor1; oa[dn][3] *= cor1;
        }

        // ---- O += Ph Vh + Pl Vh + Ph Vl ----
        #pragma unroll
        for (int ks = 0; ks < 8; ks++) {
            uint32_t aH[4], aL[4];
            {
                float p0 = sa[2*ks][0],   p1 = sa[2*ks][1];
                float p2 = sa[2*ks][2],   p3 = sa[2*ks][3];
                float r0 = sa[2*ks+1][0], r1 = sa[2*ks+1][1];
                float r2 = sa[2*ks+1][2], r3 = sa[2*ks+1][3];
                __nv_bfloat16 h0 = __float2bfloat16(p0), h1 = __float2bfloat16(p1);
                __nv_bfloat16 h2 = __float2bfloat16(p2), h3 = __float2bfloat16(p3);
                __nv_bfloat16 g0 = __float2bfloat16(r0), g1 = __float2bfloat16(r1);
                __nv_bfloat16 g2 = __float2bfloat16(r2), g3 = __float2bfloat16(r3);
                aH[0] = pk2(h0, h1); aH[1] = pk2(h2, h3);
                aH[2] = pk2(g0, g1); aH[3] = pk2(g2, g3);
                aL[0] = pk2(__float2bfloat16(p0 - __bfloat162float(h0)),
                            __float2bfloat16(p1 - __bfloat162float(h1)));
                aL[1] = pk2(__float2bfloat16(p2 - __bfloat162float(h2)),
                            __float2bfloat16(p3 - __bfloat162float(h3)));
                aL[2] = pk2(__float2bfloat16(r0 - __bfloat162float(g0)),
                            __float2bfloat16(r1 - __bfloat162float(g1)));
                aL[3] = pk2(__float2bfloat16(r2 - __bfloat162float(g2)),
                            __float2bfloat16(r3 - __bfloat162float(g3)));
            }
            uint32_t bvh[4][4], bvl[4][4];
            #pragma unroll
            for (int g = 0; g < 4; g++) {
                ldsm4(bvh[g], vhb + (g*16 + (lane & 15))*272 + ks*32 + (lane >> 4)*16);
                ldsm4(bvl[g], vlb + (g*16 + (lane & 15))*272 + ks*32 + (lane >> 4)*16);
            }
            #pragma unroll
            for (int dn = 0; dn < 8; dn++) {
                uint32_t b2h[2] = { bvh[dn>>1][dn & 1], bvh[dn>>1][(dn & 1) + 2] };
                uint32_t b2l[2] = { bvl[dn>>1][dn & 1], bvl[dn>>1][(dn & 1) + 2] };
                mma16816(oa[dn], aH, b2h);
                mma16816(oa[dn], aL, b2h);
                mma16816(oa[dn], aH, b2l);
            }
        }
        __syncthreads();
    }

    const float g0w = gate_w(gate, bh & 15, 0);
    const float s0 = g0w / l0, s1 = g0w / l1;
    const int b = bh >> 4, h = bh & 15;
    const int qr0 = m0 + wid*16 + (lane >> 2), qr1 = qr0 + 8;
    float* c0 = g_comb + ((long)b*TT + qr0)*EE + h*64;
    float* c1 = g_comb + ((long)b*TT + qr1)*EE + h*64;
    #pragma unroll
    for (int dn = 0; dn < 8; dn++) {
        int d = dn*8 + (lane & 3)*2;
        c0[d]   = oa[dn][0]*s0; c0[d+1] = oa[dn][1]*s0;
        c1[d]   = oa[dn][2]*s1; c1[d+1] = oa[dn][3]*s1;
    }
}

// ---------------- conversion kernels ----------------
__global__ void conv_split(const float* __restrict__ in,
                           __nv_bfloat16* __restrict__ h, __nv_bfloat16* __restrict__ l, int n)
{
    int i = (blockIdx.x * 256 + threadIdx.x) * 4;
    if (i >= n) return;
    float4 v = *(const float4*)(in + i);
    __nv_bfloat16 h0,h1,h2,h3,l0,l1,l2,l3;
    bsplit(v.x,h0,l0); bsplit(v.y,h1,l1); bsplit(v.z,h2,l2); bsplit(v.w,h3,l3);
    *(uint2*)(h + i) = make_uint2(pk2(h0,h1), pk2(h2,h3));
    *(uint2*)(l + i) = make_uint2(pk2(l0,l1), pk2(l2,l3));
}
__global__ void conv_split_T(const float* __restrict__ in,
                             __nv_bfloat16* __restrict__ h, __nv_bfloat16* __restrict__ l)
{   // out[e*E+f] = in[f*E+e]
    int i = blockIdx.x * 256 + threadIdx.x;
    int e = i >> 10, f = i & 1023;
    bsplit(in[(long)f * EE + e], h[i], l[i]);
}
// per-batch transpose-split: echo [b][t][e] -> echoT [b][e][t] (bf16 hi/lo)
__global__ void transpose_split(const float* __restrict__ in,
                                __nv_bfloat16* __restrict__ oh, __nv_bfloat16* __restrict__ ol)
{
    __shared__ float tile[32][33];
    int b = blockIdx.z;
    int t0 = blockIdx.x * 32, e0 = blockIdx.y * 32;
    int tx = threadIdx.x, ty = threadIdx.y;   // (32, 8)
    const float* ib = in + ((long)b*TT + t0)*EE + e0;
    #pragma unroll
    for (int k = 0; k < 4; k++)
        tile[ty + k*8][tx] = ib[(long)(ty + k*8)*EE + tx];
    __syncthreads();
    #pragma unroll
    for (int k = 0; k < 4; k++) {
        int e = ty + k*8;
        long idx = ((long)b*EE + e0 + e)*TT + t0 + tx;
        bsplit(tile[tx][e], oh[idx], ol[idx]);
    }
}

// ---------------- s2[b,h,t] = (1/8) dot(x[b,t,:], wr[h,:,t]) ----------------
__global__ void s2_kernel(const float* __restrict__ x, const float* __restrict__ wr)
{
    __shared__ float xs[256][33];
    int t0 = blockIdx.x * 256;
    int h = blockIdx.y, b = blockIdx.z;
    int tid = threadIdx.x, w = tid >> 5, lane = tid & 31;
    int t = t0 + tid;
    float acc = 0.f;
    for (int e0 = 0; e0 < EE; e0 += 32) {
        #pragma unroll 4
        for (int rr = 0; rr < 32; rr++)
            xs[w*32 + rr][lane] = x[(long)b*TT*EE + (long)(t0 + w*32 + rr)*EE + e0 + lane];
        __syncthreads();
        const float* wrp = wr + (long)h*EE*TT + (long)e0*TT + t;
        #pragma unroll
        for (int e = 0; e < 32; e++) acc += xs[tid][e] * wrp[(long)e*TT];
        __syncthreads();
    }
    g_s2[(b*HH + h)*TT + t] = acc * 0.125f;
}

// ---------------- sc[b,t] = dot(x[b,t], eb[b,t]) / 32 ----------------
__global__ void sc_kernel(const float* __restrict__ x)
{
    __shared__ float red[256];
    long base = (long)blockIdx.x * EE;
    int tid = threadIdx.x;
    float s = 0.f;
    for (int e = tid; e < EE; e += 256) s += x[base+e] * g_eb[base+e];
    red[tid] = s; __syncthreads();
    for (int st = 128; st; st >>= 1) { if (tid < st) red[tid] += red[tid+st]; __syncthreads(); }
    if (tid == 0) g_sc[blockIdx.x] = red[0] * (1.f/32.f);
}

// ---------------- branch-3 probs: rank-1 causal softmax rows -> bf16 split ----------------
// grid (T, B), 256 threads
__global__ void p3_kernel()
{
    __shared__ float red[256];
    int i = blockIdx.x, b = blockIdx.y;
    int tid = threadIdx.x;
    const float* scb = g_sc + b*TT;
    float sci = scb[i];
    long base = ((long)b*TT + i)*TT;

    float m = -CUDART_INF_F;
    for (int j = tid; j <= i; j += 256) m = fmaxf(m, sci * scb[j]);
    red[tid] = m; __syncthreads();
    for (int st = 128; st; st >>= 1) { if (tid < st) red[tid] = fmaxf(red[tid], red[tid+st]); __syncthreads(); }
    m = red[0]; __syncthreads();

    float sum = 0.f;
    for (int j = tid; j <= i; j += 256) sum += fexp(sci * scb[j] - m);
    red[tid] = sum; __syncthreads();
    for (int st = 128; st; st >>= 1) { if (tid < st) red[tid] += red[tid+st]; __syncthreads(); }
    float inv = 1.f / red[0];

    for (int j = tid; j <= i; j += 256)
        bsplit(fexp(sci * scb[j] - m) * inv, g_p3h[base+j], g_p3l[base+j]);
    __nv_bfloat16 zz = __float2bfloat16(0.f);
    for (int j = i+1+tid; j < TT; j += 256) { g_p3h[base+j] = zz; g_p3l[base+j] = zz; }
}

// ---------------- branch 2: segmented parallel prefix softmax-scan ----------------
__global__ void __launch_bounds__(512) branch2_kernel(const float* __restrict__ gate)
{
    __shared__ float w[TT], inv[TT], seg[16][64], red[512];
    int bh = blockIdx.x, b = bh >> 4, h = bh & 15;
    int tid = threadIdx.x, wp = tid >> 5, ln = tid & 31;
    const float* s2p = g_s2 + bh*TT;

    float m = fmaxf(s2p[tid], s2p[tid + 512]);
    red[tid] = m; __syncthreads();
    for (int st = 256; st; st >>= 1) { if (tid < st) red[tid] = fmaxf(red[tid], red[tid+st]); __syncthreads(); }
    m = red[0]; __syncthreads();

    float w0 = fexp(s2p[2*tid] - m), w1 = fexp(s2p[2*tid+1] - m);
    w[2*tid] = w0; w[2*tid+1] = w1;
    red[tid] = w0 + w1; __syncthreads();
    for (int off = 1; off < 512; off <<= 1) {
        float v = (tid >= off) ? red[tid - off] : 0.f;
        __syncthreads();
        red[tid] += v;
        __syncthreads();
    }
    float basep = (tid == 0) ? 0.f : red[tid - 1];
    inv[2*tid]   = 1.f / (basep + w0);
    inv[2*tid+1] = 1.f / (basep + w0 + w1);
    __syncthreads();

    const float* rvp = g_rv + (long)b*TT*EE + h*64;
    float p0 = 0.f, p1 = 0.f;
    for (int j = wp*64; j < wp*64 + 64; j++) {
        float wj = w[j];
        p0 += wj * rvp[(long)j*EE + ln];
        p1 += wj * rvp[(long)j*EE + ln + 32];
    }
    seg[wp][ln] = p0; seg[wp][ln + 32] = p1;
    __syncthreads();
    if (tid < 64) {
        float a = 0.f;
        #pragma unroll
        for (int s = 0; s < 16; s++) { float t = seg[s][tid]; seg[s][tid] = a; a += t; }
    }
    __syncthreads();

    float g1 = gate_w(gate, h, 1);
    float a0 = seg[wp][ln], a1 = seg[wp][ln + 32];
    float* cp = g_comb + (long)b*TT*EE + h*64;
    for (int j = wp*64; j < wp*64 + 64; j++) {
        float wj = w[j], iv = inv[j];
        a0 += wj * rvp[(long)j*EE + ln];
        a1 += wj * rvp[(long)j*EE + ln + 32];
        cp[(long)j*EE + ln]      += g1 * a0 * iv;
        cp[(long)j*EE + ln + 32] += g1 * a1 * iv;
    }
}

// ---------------- host launch ----------------
extern "C" void kernel_launch(void* const* d_in, const int* in_sizes, int n_in,
                              void* d_out, int out_size)
{
    const float* x    = (const float*)d_in[0];
    const float* wq   = (const float*)d_in[1];
    const float* wk   = (const float*)d_in[2];
    const float* wv   = (const float*)d_in[3];
    const float* wvr  = (const float*)d_in[4];
    const float* wr   = (const float*)d_in[5];
    const float* wj   = (const float*)d_in[6];
    const float* gate = (const float*)d_in[7];
    const float* wo   = (const float*)d_in[8];
    float* out = (float*)d_out;

#define GA(sym, var, type) type* var; cudaGetSymbolAddress((void**)&var, sym)
    GA(g_xh, xh, __nv_bfloat16);   GA(g_xl, xl, __nv_bfloat16);
    GA(g_wqh, wqh, __nv_bfloat16); GA(g_wql, wql, __nv_bfloat16);
    GA(g_wkh, wkh, __nv_bfloat16); GA(g_wkl, wkl, __nv_bfloat16);
    GA(g_wvh, wvh, __nv_bfloat16); GA(g_wvl, wvl, __nv_bfloat16);
    GA(g_wrh, wrh, __nv_bfloat16); GA(g_wrl, wrl, __nv_bfloat16);
    GA(g_wjh, wjh, __nv_bfloat16); GA(g_wjl, wjl, __nv_bfloat16);
    GA(g_wjTh, wjTh, __nv_bfloat16); GA(g_wjTl, wjTl, __nv_bfloat16);
    GA(g_woh, woh, __nv_bfloat16); GA(g_wol, wol, __nv_bfloat16);
    GA(g_qsh, qsh, __nv_bfloat16); GA(g_qsl, qsl, __nv_bfloat16);
    GA(g_ksh, ksh, __nv_bfloat16); GA(g_ksl, ksl, __nv_bfloat16);
    GA(g_vth, vth, __nv_bfloat16); GA(g_vtl, vtl, __nv_bfloat16);
    GA(g_rv, rvf, float);
    GA(g_echo, echof, float);
    GA(g_eh, eh, __nv_bfloat16);   GA(g_el, el, __nv_bfloat16);
    GA(g_eTh, eTh, __nv_bfloat16); GA(g_eTl, eTl, __nv_bfloat16);
    GA(g_eb, ebf, float);
    GA(g_comb, combf, float);
    GA(g_ch, ch, __nv_bfloat16);   GA(g_cl, cl, __nv_bfloat16);
    GA(g_p3h, p3h, __nv_bfloat16); GA(g_p3l, p3l, __nv_bfloat16);
#undef GA

    const int SM1P = 2 * 2 * (128 + 128) * 80;   // 81920
    cudaFuncSetAttribute(tgemm<128>, cudaFuncAttributeMaxDynamicSharedMemorySize, SM1P);
    cudaFuncSetAttribute(flash1, cudaFuncAttributeMaxDynamicSharedMemorySize, FL_SMEM);

    // --- bf16 hi/lo splits of inputs ---
    conv_split<<<(BT*EE)/1024, 256>>>(x,   xh,  xl,  BT*EE);
    conv_split<<<(EE*EE)/1024, 256>>>(wq,  wqh, wql, EE*EE);
    conv_split<<<(EE*EE)/1024, 256>>>(wk,  wkh, wkl, EE*EE);
    conv_split<<<(EE*EE)/1024, 256>>>(wv,  wvh, wvl, EE*EE);
    conv_split<<<(EE*EE)/1024, 256>>>(wvr, wrh, wrl, EE*EE);
    conv_split<<<(EE*EE)/1024, 256>>>(wj,  wjh, wjl, EE*EE);
    conv_split<<<(EE*EE)/1024, 256>>>(wo,  woh, wol, EE*EE);
    conv_split_T<<<(EE*EE)/256, 256>>>(wj, wjTh, wjTl);

    dim3 big(8, 32, 1);
    // projections: y = x @ W^T
    tgemm<128><<<big, 256, SM1P>>>(xh, xl, wqh, wql, 1024, 1024, 1024, 0, 0, 0,
                                   3, nullptr, qsh, qsl, 0, 0, nullptr);
    tgemm<128><<<big, 256, SM1P>>>(xh, xl, wkh, wkl, 1024, 1024, 1024, 0, 0, 0,
                                   3, nullptr, ksh, ksl, 0, 0, nullptr);
    tgemm<128><<<big, 256, SM1P>>>(xh, xl, wvh, wvl, 1024, 1024, 1024, 0, 0, 0,
                                   2, nullptr, vth, vtl, 0, 0, nullptr);
    tgemm<128><<<big, 256, SM1P>>>(xh, xl, wrh, wrl, 1024, 1024, 1024, 0, 0, 0,
                                   0, rvf, nullptr, nullptr, 1024, 0, nullptr);
    tgemm<128><<<big, 256, SM1P>>>(xh, xl, wjh, wjl, 1024, 1024, 1024, 0, 0, 0,
                                   4, echof, eh, el, 1024, 0, nullptr);
    tgemm<128><<<big, 256, SM1P>>>(eh, el, wjTh, wjTl, 1024, 1024, 1024, 0, 0, 0,
                                   0, ebf, nullptr, nullptr, 1024, 0, nullptr);

    s2_kernel<<<dim3(TT/256, HH, BB), 256>>>(x, wr);
    sc_kernel<<<BT, 256>>>(x);

    // branch 1 fused: comb = g0[h] * flash_attention(q,k,v)
    flash1<<<dim3(8, 64), 256, FL_SMEM>>>(gate);

    // branch 2: comb += g1 * out2
    branch2_kernel<<<BH, 512>>>(gate);

    // branch 3 as GEMM: comb += g2[h] * (P3 @ echo), causal K-capped
    p3_kernel<<<dim3(TT, BB), 256>>>();
    transpose_split<<<dim3(32, 32, BB), dim3(32, 8)>>>(echof, eTh, eTl);
    tgemm<128><<<dim3(8, 8, BB), 256, SM1P>>>(
        p3h, p3l, eTh, eTl, 1024, 1024, 1024,
        (long)TT*TT, (long)TT*EE, 1,
        5, combf, nullptr, nullptr, 1024, (long)TT*EE, gate);

    // final: out = comb @ wo^T
    conv_split<<<(BT*EE)/1024, 256>>>(combf, ch, cl, BT*EE);
    tgemm<128><<<big, 256, SM1P>>>(ch, cl, woh, wol, 1024, 1024, 1024, 0, 0, 0,
                                   0, out, nullptr, nullptr, 1024, 0, nullptr);
}

// round 10
// speedup vs baseline: 4.9924x; 1.0693x over previous
#include <cuda_runtime.h>
#include <cuda_bf16.h>
#include <math_constants.h>
#include <cstdint>

#define BB 4
#define TT 1024
#define EE 1024
#define HH 16
#define DD 64
#define BT (BB*TT)   // 4096
#define BH (BB*HH)   // 64

// ---------------- scratch (device globals) ----------------
__device__ __nv_bfloat16 g_xh[BT*EE],  g_xl[BT*EE];
__device__ __nv_bfloat16 g_wqh[EE*EE], g_wql[EE*EE];
__device__ __nv_bfloat16 g_wkh[EE*EE], g_wkl[EE*EE];
__device__ __nv_bfloat16 g_wvh[EE*EE], g_wvl[EE*EE];
__device__ __nv_bfloat16 g_wrh[EE*EE], g_wrl[EE*EE];   // wvr
__device__ __nv_bfloat16 g_wjh[EE*EE], g_wjl[EE*EE];
__device__ __nv_bfloat16 g_wjTh[EE*EE],g_wjTl[EE*EE];
__device__ __nv_bfloat16 g_woh[EE*EE], g_wol[EE*EE];
__device__ __nv_bfloat16 g_qsh[BH*TT*DD], g_qsl[BH*TT*DD];  // [bh][t][d]
__device__ __nv_bfloat16 g_ksh[BH*TT*DD], g_ksl[BH*TT*DD];  // [bh][t][d]
__device__ __nv_bfloat16 g_vth[BH*DD*TT], g_vtl[BH*DD*TT];  // [bh][d][t]
__device__ float g_rv[BT*EE];
__device__ float g_echo[BT*EE];
__device__ __nv_bfloat16 g_eh[BT*EE], g_el[BT*EE];
__device__ __nv_bfloat16 g_eTh[BT*EE], g_eTl[BT*EE];        // echo^T per batch [b][e][t]
__device__ float g_eb[BT*EE];
__device__ float g_comb[BT*EE];
__device__ __nv_bfloat16 g_ch[BT*EE], g_cl[BT*EE];
__device__ __nv_bfloat16 g_p3h[(long)BB*TT*TT], g_p3l[(long)BB*TT*TT];  // branch-3 probs
__device__ float g_s2[BH*TT];
__device__ float g_sc[BB*TT];
__device__ float g_b2w[BH*TT], g_b2inv[BH*TT];

// ---------------- helpers ----------------
__device__ __forceinline__ uint32_t smem_u32(const void* p) {
    uint32_t a;
    asm("{ .reg .u64 t; cvta.to.shared.u64 t, %1; cvt.u32.u64 %0, t; }" : "=r"(a) : "l"(p));
    return a;
}
__device__ __forceinline__ void cpasync16(uint32_t saddr, const void* g) {
    asm volatile("cp.async.cg.shared.global [%0], [%1], 16;" :: "r"(saddr), "l"(g));
}
#define CP_COMMIT() asm volatile("cp.async.commit_group;" ::: "memory")
#define CP_WAIT1()  asm volatile("cp.async.wait_group 1;"  ::: "memory")

__device__ __forceinline__ void ldsm4(uint32_t* r, uint32_t addr) {
    asm volatile("ldmatrix.sync.aligned.m8n8.x4.shared.b16 {%0,%1,%2,%3}, [%4];"
        : "=r"(r[0]), "=r"(r[1]), "=r"(r[2]), "=r"(r[3]) : "r"(addr));
}
__device__ __forceinline__ void mma16816(float* d, const uint32_t* a, const uint32_t* b) {
    asm volatile("mma.sync.aligned.m16n8k16.row.col.f32.bf16.bf16.f32 "
        "{%0,%1,%2,%3}, {%4,%5,%6,%7}, {%8,%9}, {%0,%1,%2,%3};"
        : "+f"(d[0]), "+f"(d[1]), "+f"(d[2]), "+f"(d[3])
        : "r"(a[0]), "r"(a[1]), "r"(a[2]), "r"(a[3]), "r"(b[0]), "r"(b[1]));
}

// fast exp on FMA pipe. valid x <= 0; clamps below -80. rel err < 3e-6.
__device__ __forceinline__ float fexp(float x) {
    x = fmaxf(x, -80.f);
    float y = x * 1.4426950408889634f;
    int   e = __float2int_rn(y);
    float f = y - (float)e;
    float p = 1.3333558e-3f;
    p = fmaf(p, f, 9.6181292e-3f);
    p = fmaf(p, f, 5.5504109e-2f);
    p = fmaf(p, f, 2.4022651e-1f);
    p = fmaf(p, f, 6.9314718e-1f);
    p = fmaf(p, f, 1.0f);
    return __int_as_float((e + 127) << 23) * p;
}

__device__ __forceinline__ float gate_w(const float* gate, int h, int c) {
    float a = gate[h*3+0], b = gate[h*3+1], d = gate[h*3+2];
    float m = fmaxf(a, fmaxf(b, d));
    float ea = __expf(a-m), eb = __expf(b-m), ec = __expf(d-m);
    float s = ea + eb + ec;
    float num = (c == 0) ? ea : (c == 1) ? eb : ec;
    return num / s;
}
__device__ __forceinline__ void bsplit(float v, __nv_bfloat16& h, __nv_bfloat16& l) {
    h = __float2bfloat16(v);
    l = __float2bfloat16(v - __bfloat162float(h));
}
__device__ __forceinline__ uint32_t pk2(__nv_bfloat16 a, __nv_bfloat16 b) {
    __nv_bfloat162 t; t.x = a; t.y = b;
    return *reinterpret_cast<uint32_t*>(&t);
}

// ---------------- single-pass 3-term HMMA split-bf16 GEMM body ----------------
// C = sum_k (AhBh + AhBl + AlBh). modes: 0 fp32; 2 vT-split; 3 ts-split;
// 4 fp32+split; 5 fp32 += gate2[h(gn)]*v
template<int TN>
__device__ __forceinline__ void gemm_body(
    char* smem, const __nv_bfloat16* __restrict__ Ah, const __nv_bfloat16* __restrict__ Al,
    const __nv_bfloat16* __restrict__ Bh, const __nv_bfloat16* __restrict__ Bl,
    int NC, long lda, long ldb,
    int mode, float* __restrict__ CfB,
    __nv_bfloat16* __restrict__ Ch, __nv_bfloat16* __restrict__ Cl,
    long ldc, const float* __restrict__ gate)
{
    constexpr int TM = 128, ROWB = 80;
    constexpr int AOFF_L = TM*ROWB;
    constexpr int BOFF_H = 2*TM*ROWB;
    constexpr int BOFF_L = 2*TM*ROWB + TN*ROWB;
    constexpr int STG = 2*TM*ROWB + 2*TN*ROWB;
    constexpr int WARPS_N = TN/32, WARPS_M = 8/WARPS_N;
    constexpr int WM = TM/WARPS_M, MI = WM/16;

    __shared__ float sgate[16];
    const int tid = threadIdx.x, wid = tid >> 5, lane = tid & 31;
    const int m0 = blockIdx.y*TM, n0 = blockIdx.x*TN;
    const int wm = wid / WARPS_N, wn = wid % WARPS_N;
    const uint32_t sbase = smem_u32(smem);

    if (mode == 5 && tid < 16) sgate[tid] = gate_w(gate, tid, 2);

    auto prefetch = [&](int c, int s) {
        int k0 = c * 32;
        uint32_t st = sbase + s*STG;
        #pragma unroll 2
        for (int i = tid; i < TM*4; i += 256) {
            int r = i >> 2, cc = i & 3;
            long go = (long)(m0 + r)*lda + k0 + cc*8;
            cpasync16(st + r*ROWB + cc*16,            Ah + go);
            cpasync16(st + AOFF_L + r*ROWB + cc*16,   Al + go);
        }
        #pragma unroll 2
        for (int i = tid; i < TN*4; i += 256) {
            int r = i >> 2, cc = i & 3;
            long go = (long)(n0 + r)*ldb + k0 + cc*8;
            cpasync16(st + BOFF_H + r*ROWB + cc*16,   Bh + go);
            cpasync16(st + BOFF_L + r*ROWB + cc*16,   Bl + go);
        }
    };

    float acc[MI][4][4] = {};
    prefetch(0, 0); CP_COMMIT();

    for (int c = 0; c < NC; c++) {
        if (c + 1 < NC) prefetch(c + 1, (c + 1) & 1);
        CP_COMMIT();
        CP_WAIT1();
        __syncthreads();

        uint32_t st = sbase + (c & 1)*STG;
        #pragma unroll
        for (int ks = 0; ks < 2; ks++) {
            uint32_t aH[MI][4], bH[2][4], bL[2][4];
            #pragma unroll
            for (int mi = 0; mi < MI; mi++)
                ldsm4(aH[mi], st + (wm*WM + mi*16 + (lane & 15))*ROWB
                              + ks*32 + (lane >> 4)*16);
            #pragma unroll
            for (int bi = 0; bi < 2; bi++) {
                ldsm4(bH[bi], st + BOFF_H + (wn*32 + bi*16 + (lane & 15))*ROWB
                              + ks*32 + (lane >> 4)*16);
                ldsm4(bL[bi], st + BOFF_L + (wn*32 + bi*16 + (lane & 15))*ROWB
                              + ks*32 + (lane >> 4)*16);
            }
            // independent-accumulator sweeps
            #pragma unroll
            for (int mi = 0; mi < MI; mi++)
                #pragma unroll
                for (int ni = 0; ni < 4; ni++) {
                    uint32_t h2[2] = { bH[ni>>1][ni & 1], bH[ni>>1][(ni & 1) + 2] };
                    mma16816(acc[mi][ni], aH[mi], h2);
                }
            #pragma unroll
            for (int mi = 0; mi < MI; mi++)
                #pragma unroll
                for (int ni = 0; ni < 4; ni++) {
                    uint32_t l2[2] = { bL[ni>>1][ni & 1], bL[ni>>1][(ni & 1) + 2] };
                    mma16816(acc[mi][ni], aH[mi], l2);
                }
            uint32_t aL[MI][4];
            #pragma unroll
            for (int mi = 0; mi < MI; mi++)
                ldsm4(aL[mi], st + AOFF_L + (wm*WM + mi*16 + (lane & 15))*ROWB
                              + ks*32 + (lane >> 4)*16);
            #pragma unroll
            for (int mi = 0; mi < MI; mi++)
                #pragma unroll
                for (int ni = 0; ni < 4; ni++) {
                    uint32_t h2[2] = { bH[ni>>1][ni & 1], bH[ni>>1][(ni & 1) + 2] };
                    mma16816(acc[mi][ni], aL[mi], h2);
                }
        }
        __syncthreads();
    }

    // epilogue
    #pragma unroll
    for (int mi = 0; mi < MI; mi++) {
        #pragma unroll
        for (int ni = 0; ni < 4; ni++) {
            int rb = m0 + wm*WM + mi*16 + (lane >> 2);
            int cb = n0 + wn*32 + ni*8 + (lane & 3)*2;
            #pragma unroll
            for (int q = 0; q < 4; q++) {
                int gm = rb + (q >> 1)*8, gn = cb + (q & 1);
                float v = acc[mi][ni][q];
                if (mode == 0) {
                    CfB[(long)gm*ldc + gn] = v;
                } else if (mode == 4) {
                    long idx = (long)gm*ldc + gn;
                    CfB[idx] = v;
                    bsplit(v, Ch[idx], Cl[idx]);
                } else if (mode == 2) {   // vT: [(b*16+h)][d][t]
                    int b = gm >> 10, t = gm & 1023, h = gn >> 6, d = gn & 63;
                    long idx = (((long)(b*16 + h)) * 64 + d) * 1024 + t;
                    bsplit(v, Ch[idx], Cl[idx]);
                } else if (mode == 3) {   // [(b*16+h)][t][d]
                    int b = gm >> 10, t = gm & 1023, h = gn >> 6, d = gn & 63;
                    long idx = (((long)(b*16 + h)) * 1024 + t) * 64 + d;
                    bsplit(v, Ch[idx], Cl[idx]);
                } else {                  // mode 5: gated accumulate
                    CfB[(long)gm*ldc + gn] += sgate[gn >> 6] * v;
                }
            }
        }
    }
}

// generic wrapper (eb / branch-3 / final)
template<int TN>
__global__ void __launch_bounds__(256, 2) tgemm(
    const __nv_bfloat16* __restrict__ Ah_, const __nv_bfloat16* __restrict__ Al_,
    const __nv_bfloat16* __restrict__ Bh_, const __nv_bfloat16* __restrict__ Bl_,
    int K, long lda, long ldb, long sAz, long sBz, int kcap,
    int mode, float* __restrict__ Cf,
    __nv_bfloat16* __restrict__ Ch, __nv_bfloat16* __restrict__ Cl,
    long ldc, long sCz, const float* __restrict__ gate)
{
    extern __shared__ char smem[];
    const int z = blockIdx.z;
    const int Keff = kcap ? (blockIdx.y*128 + 128) : K;
    gemm_body<TN>(smem,
                  Ah_ + (long)z*sAz, Al_ + (long)z*sAz,
                  Bh_ + (long)z*sBz, Bl_ + (long)z*sBz,
                  Keff/32, lda, ldb, mode,
                  Cf ? (Cf + (long)z*sCz) : nullptr, Ch, Cl, ldc, gate);
}

// merged 5-projection kernel (z picks weight + output mode)
struct P5 {
    const __nv_bfloat16* bh[5]; const __nv_bfloat16* bl[5];
    float* cf[5]; __nv_bfloat16* ch[5]; __nv_bfloat16* cl[5];
    long ldc[5]; int mode[5];
};
__global__ void __launch_bounds__(256, 2) proj5(
    const __nv_bfloat16* __restrict__ xh, const __nv_bfloat16* __restrict__ xl, P5 p)
{
    extern __shared__ char smem[];
    const int z = blockIdx.z;
    gemm_body<128>(smem, xh, xl, p.bh[z], p.bl[z], 32, 1024, 1024,
                   p.mode[z], p.cf[z], p.ch[z], p.cl[z], p.ldc[z], nullptr);
}

// ---------------- fused flash branch 1 ----------------
#define FL_SMEM 180224
__global__ void __launch_bounds__(256) flash1(const float* __restrict__ gate)
{
    extern __shared__ char smem[];
    const int tid = threadIdx.x, wid = tid >> 5, lane = tid & 31;
    const int m0 = (gridDim.x - 1 - blockIdx.x) * 128;   // heavy tiles first
    const int bh = blockIdx.y;
    const uint32_t sb = smem_u32(smem);
    const uint32_t sQh = sb, sQl = sb + 18432;

    const long qoff = (long)bh * TT * DD;
    const long voff = (long)bh * DD * TT;

    for (int i = tid; i < 128*8; i += 256) {
        int r = i >> 3, c = i & 7;
        cpasync16(sQh + r*144 + c*16, g_qsh + qoff + (long)(m0+r)*64 + c*8);
        cpasync16(sQl + r*144 + c*16, g_qsl + qoff + (long)(m0+r)*64 + c*8);
    }
    CP_COMMIT();

    const int nchunks = m0/128 + 1;
    auto pf = [&](int cidx, int st) {
        uint32_t kh = sb + 36864 + st*36864, kl = kh + 18432;
        uint32_t vh = sb + 110592 + st*34816, vl = vh + 17408;
        int j0 = cidx * 128;
        for (int i = tid; i < 128*8; i += 256) {
            int r = i >> 3, c = i & 7;
            cpasync16(kh + r*144 + c*16, g_ksh + qoff + (long)(j0+r)*64 + c*8);
            cpasync16(kl + r*144 + c*16, g_ksl + qoff + (long)(j0+r)*64 + c*8);
        }
        for (int i = tid; i < 64*16; i += 256) {
            int r = i >> 4, c = i & 15;
            cpasync16(vh + r*272 + c*16, g_vth + voff + (long)r*TT + j0 + c*8);
            cpasync16(vl + r*272 + c*16, g_vtl + voff + (long)r*TT + j0 + c*8);
        }
    };
    pf(0, 0); CP_COMMIT();

    uint32_t qfh[4][4], qfl[4][4];
    float oa[8][4] = {};
    float ms0 = -1e30f, ms1 = -1e30f, l0 = 0.f, l1 = 0.f;

    for (int c = 0; c < nchunks; c++) {
        if (c + 1 < nchunks) pf(c + 1, (c + 1) & 1);
        CP_COMMIT();
        CP_WAIT1();
        __syncthreads();

        if (c == 0) {
            #pragma unroll
            for (int ks = 0; ks < 4; ks++) {
                ldsm4(qfh[ks], sQh + (wid*16 + (lane & 15))*144 + ks*32 + (lane >> 4)*16);
                ldsm4(qfl[ks], sQl + (wid*16 + (lane & 15))*144 + ks*32 + (lane >> 4)*16);
            }
        }

        const int st = c & 1, j0 = c * 128;
        const uint32_t khb = sb + 36864 + st*36864, klb = khb + 18432;
        const uint32_t vhb = sb + 110592 + st*34816, vlb = vhb + 17408;

        float sa[16][4];
        #pragma unroll
        for (int nt = 0; nt < 16; nt++)
            sa[nt][0] = sa[nt][1] = sa[nt][2] = sa[nt][3] = 0.f;

        #pragma unroll
        for (int ks = 0; ks < 4; ks++) {
            uint32_t bf4[8][4];
            #pragma unroll
            for (int g = 0; g < 8; g++)
                ldsm4(bf4[g], khb + (g*16 + (lane & 15))*144 + ks*32 + (lane >> 4)*16);
            #pragma unroll
            for (int nt = 0; nt < 16; nt++) {
                uint32_t b2[2] = { bf4[nt>>1][nt & 1], bf4[nt>>1][(nt & 1) + 2] };
                mma16816(sa[nt], qfh[ks], b2);
            }
            #pragma unroll
            for (int nt = 0; nt < 16; nt++) {
                uint32_t b2[2] = { bf4[nt>>1][nt & 1], bf4[nt>>1][(nt & 1) + 2] };
                mma16816(sa[nt], qfl[ks], b2);
            }
            #pragma unroll
            for (int g = 0; g < 8; g++)
                ldsm4(bf4[g], klb + (g*16 + (lane & 15))*144 + ks*32 + (lane >> 4)*16);
            #pragma unroll
            for (int nt = 0; nt < 16; nt++) {
                uint32_t b2[2] = { bf4[nt>>1][nt & 1], bf4[nt>>1][(nt & 1) + 2] };
                mma16816(sa[nt], qfh[ks], b2);
            }
        }

        const int qr0 = m0 + wid*16 + (lane >> 2);
        const int qr1 = qr0 + 8;
        if (j0 == m0) {
            #pragma unroll
            for (int nt = 0; nt < 16; nt++) {
                int col = j0 + nt*8 + (lane & 3)*2;
                sa[nt][0] = (col     > qr0) ? -1e30f : sa[nt][0]*0.125f;
                sa[nt][1] = (col + 1 > qr0) ? -1e30f : sa[nt][1]*0.125f;
                sa[nt][2] = (col     > qr1) ? -1e30f : sa[nt][2]*0.125f;
                sa[nt][3] = (col + 1 > qr1) ? -1e30f : sa[nt][3]*0.125f;
            }
        } else {
            #pragma unroll
            for (int nt = 0; nt < 16; nt++) {
                sa[nt][0] *= 0.125f; sa[nt][1] *= 0.125f;
                sa[nt][2] *= 0.125f; sa[nt][3] *= 0.125f;
            }
        }

        float mx0 = -1e30f, mx1 = -1e30f;
        #pragma unroll
        for (int nt = 0; nt < 16; nt++) {
            mx0 = fmaxf(mx0, fmaxf(sa[nt][0], sa[nt][1]));
            mx1 = fmaxf(mx1, fmaxf(sa[nt][2], sa[nt][3]));
        }
        mx0 = fmaxf(mx0, __shfl_xor_sync(0xffffffffu, mx0, 1));
        mx0 = fmaxf(mx0, __shfl_xor_sync(0xffffffffu, mx0, 2));
        mx1 = fmaxf(mx1, __shfl_xor_sync(0xffffffffu, mx1, 1));
        mx1 = fmaxf(mx1, __shfl_xor_sync(0xffffffffu, mx1, 2));

        float mn0 = fmaxf(ms0, mx0), mn1 = fmaxf(ms1, mx1);
        float cor0 = fexp(ms0 - mn0), cor1 = fexp(ms1 - mn1);

        float rs0 = 0.f, rs1 = 0.f;
        #pragma unroll
        for (int nt = 0; nt < 16; nt++) {
            sa[nt][0] = fexp(sa[nt][0] - mn0);
            sa[nt][1] = fexp(sa[nt][1] - mn0);
            sa[nt][2] = fexp(sa[nt][2] - mn1);
            sa[nt][3] = fexp(sa[nt][3] - mn1);
            rs0 += sa[nt][0] + sa[nt][1];
            rs1 += sa[nt][2] + sa[nt][3];
        }
        rs0 += __shfl_xor_sync(0xffffffffu, rs0, 1);
        rs0 += __shfl_xor_sync(0xffffffffu, rs0, 2);
        rs1 += __shfl_xor_sync(0xffffffffu, rs1, 1);
        rs1 += __shfl_xor_sync(0xffffffffu, rs1, 2);
        l0 = l0*cor0 + rs0;
        l1 = l1*cor1 + rs1;
        ms0 = mn0; ms1 = mn1;
        #pragma unroll
        for (int dn = 0; dn < 8; dn++) {
            oa[dn][0] *= cor0; oa[dn][1] *= cor0;
            oa[dn][2] *= cor1; oa[dn][3] *= cor1;
        }

        // ---- O += Ph Vh + Pl Vh + Ph Vl (independent-acc sweeps) ----
        #pragma unroll
        for (int ks = 0; ks < 8; ks++) {
            uint32_t aH[4], aL[4];
            {
                float p0 = sa[2*ks][0],   p1 = sa[2*ks][1];
                float p2 = sa[2*ks][2],   p3 = sa[2*ks][3];
                float r0 = sa[2*ks+1][0], r1 = sa[2*ks+1][1];
                float r2 = sa[2*ks+1][2], r3 = sa[2*ks+1][3];
                __nv_bfloat16 h0 = __float2bfloat16(p0), h1 = __float2bfloat16(p1);
                __nv_bfloat16 h2 = __float2bfloat16(p2), h3 = __float2bfloat16(p3);
                __nv_bfloat16 g0 = __float2bfloat16(r0), g1 = __float2bfloat16(r1);
                __nv_bfloat16 g2 = __float2bfloat16(r2), g3 = __float2bfloat16(r3);
                aH[0] = pk2(h0, h1); aH[1] = pk2(h2, h3);
                aH[2] = pk2(g0, g1); aH[3] = pk2(g2, g3);
                aL[0] = pk2(__float2bfloat16(p0 - __bfloat162float(h0)),
                            __float2bfloat16(p1 - __bfloat162float(h1)));
                aL[1] = pk2(__float2bfloat16(p2 - __bfloat162float(h2)),
                            __float2bfloat16(p3 - __bfloat162float(h3)));
                aL[2] = pk2(__float2bfloat16(r0 - __bfloat162float(g0)),
                            __float2bfloat16(r1 - __bfloat162float(g1)));
                aL[3] = pk2(__float2bfloat16(r2 - __bfloat162float(g2)),
                            __float2bfloat16(r3 - __bfloat162float(g3)));
            }
            uint32_t bvh[4][4], bvl[4][4];
            #pragma unroll
            for (int g = 0; g < 4; g++) {
                ldsm4(bvh[g], vhb + (g*16 + (lane & 15))*272 + ks*32 + (lane >> 4)*16);
                ldsm4(bvl[g], vlb + (g*16 + (lane & 15))*272 + ks*32 + (lane >> 4)*16);
            }
            #pragma unroll
            for (int dn = 0; dn < 8; dn++) {
                uint32_t b2h[2] = { bvh[dn>>1][dn & 1], bvh[dn>>1][(dn & 1) + 2] };
                mma16816(oa[dn], aH, b2h);
            }
            #pragma unroll
            for (int dn = 0; dn < 8; dn++) {
                uint32_t b2h[2] = { bvh[dn>>1][dn & 1], bvh[dn>>1][(dn & 1) + 2] };
                mma16816(oa[dn], aL, b2h);
            }
            #pragma unroll
            for (int dn = 0; dn < 8; dn++) {
                uint32_t b2l[2] = { bvl[dn>>1][dn & 1], bvl[dn>>1][(dn & 1) + 2] };
                mma16816(oa[dn], aH, b2l);
            }
        }
        __syncthreads();
    }

    const float g0w = gate_w(gate, bh & 15, 0);
    const float s0 = g0w / l0, s1 = g0w / l1;
    const int b = bh >> 4, h = bh & 15;
    const int qr0 = m0 + wid*16 + (lane >> 2), qr1 = qr0 + 8;
    float* c0 = g_comb + ((long)b*TT + qr0)*EE + h*64;
    float* c1 = g_comb + ((long)b*TT + qr1)*EE + h*64;
    #pragma unroll
    for (int dn = 0; dn < 8; dn++) {
        int d = dn*8 + (lane & 3)*2;
        c0[d]   = oa[dn][0]*s0; c0[d+1] = oa[dn][1]*s0;
        c1[d]   = oa[dn][2]*s1; c1[d+1] = oa[dn][3]*s1;
    }
}

// ---------------- conversion kernels ----------------
__global__ void conv_split(const float* __restrict__ in,
                           __nv_bfloat16* __restrict__ h, __nv_bfloat16* __restrict__ l, int n)
{
    int i = (blockIdx.x * 256 + threadIdx.x) * 4;
    if (i >= n) return;
    float4 v = *(const float4*)(in + i);
    __nv_bfloat16 h0,h1,h2,h3,l0,l1,l2,l3;
    bsplit(v.x,h0,l0); bsplit(v.y,h1,l1); bsplit(v.z,h2,l2); bsplit(v.w,h3,l3);
    *(uint2*)(h + i) = make_uint2(pk2(h0,h1), pk2(h2,h3));
    *(uint2*)(l + i) = make_uint2(pk2(l0,l1), pk2(l2,l3));
}
struct CW { const float* in[6]; __nv_bfloat16* oh[6]; __nv_bfloat16* ol[6]; };
__global__ void conv_split_w(CW cw)
{
    int t = blockIdx.y;
    int i = (blockIdx.x * 256 + threadIdx.x) * 4;
    float4 v = *(const float4*)(cw.in[t] + i);
    __nv_bfloat16 h0,h1,h2,h3,l0,l1,l2,l3;
    bsplit(v.x,h0,l0); bsplit(v.y,h1,l1); bsplit(v.z,h2,l2); bsplit(v.w,h3,l3);
    *(uint2*)(cw.oh[t] + i) = make_uint2(pk2(h0,h1), pk2(h2,h3));
    *(uint2*)(cw.ol[t] + i) = make_uint2(pk2(l0,l1), pk2(l2,l3));
}
__global__ void conv_split_T(const float* __restrict__ in,
                             __nv_bfloat16* __restrict__ h, __nv_bfloat16* __restrict__ l)
{   // out[e*E+f] = in[f*E+e]
    int i = blockIdx.x * 256 + threadIdx.x;
    int e = i >> 10, f = i & 1023;
    bsplit(in[(long)f * EE + e], h[i], l[i]);
}
// per-batch transpose-split: echo [b][t][e] -> echoT [b][e][t]
__global__ void transpose_split(const float* __restrict__ in,
                                __nv_bfloat16* __restrict__ oh, __nv_bfloat16* __restrict__ ol)
{
    __shared__ float tile[32][33];
    int b = blockIdx.z;
    int t0 = blockIdx.x * 32, e0 = blockIdx.y * 32;
    int tx = threadIdx.x, ty = threadIdx.y;   // (32, 8)
    const float* ib = in + ((long)b*TT + t0)*EE + e0;
    #pragma unroll
    for (int k = 0; k < 4; k++)
        tile[ty + k*8][tx] = ib[(long)(ty + k*8)*EE + tx];
    __syncthreads();
    #pragma unroll
    for (int k = 0; k < 4; k++) {
        int e = ty + k*8;
        long idx = ((long)b*EE + e0 + e)*TT + t0 + tx;
        bsplit(tile[tx][e], oh[idx], ol[idx]);
    }
}

// ---------------- s2[b,h,t] = (1/8) dot(x[b,t,:], wr[h,:,t]) ----------------
__global__ void s2_kernel(const float* __restrict__ x, const float* __restrict__ wr)
{
    __shared__ float xs[256][33];
    int t0 = blockIdx.x * 256;
    int h = blockIdx.y, b = blockIdx.z;
    int tid = threadIdx.x, w = tid >> 5, lane = tid & 31;
    int t = t0 + tid;
    float acc = 0.f;
    for (int e0 = 0; e0 < EE; e0 += 32) {
        #pragma unroll 4
        for (int rr = 0; rr < 32; rr++)
            xs[w*32 + rr][lane] = x[(long)b*TT*EE + (long)(t0 + w*32 + rr)*EE + e0 + lane];
        __syncthreads();
        const float* wrp = wr + (long)h*EE*TT + (long)e0*TT + t;
        #pragma unroll
        for (int e = 0; e < 32; e++) acc += xs[tid][e] * wrp[(long)e*TT];
        __syncthreads();
    }
    g_s2[(b*HH + h)*TT + t] = acc * 0.125f;
}

// ---------------- sc[b,t] = dot(x[b,t], eb[b,t]) / 32 ----------------
__global__ void sc_kernel(const float* __restrict__ x)
{
    __shared__ float red[256];
    long base = (long)blockIdx.x * EE;
    int tid = threadIdx.x;
    float s = 0.f;
    for (int e = tid; e < EE; e += 256) s += x[base+e] * g_eb[base+e];
    red[tid] = s; __syncthreads();
    for (int st = 128; st; st >>= 1) { if (tid < st) red[tid] += red[tid+st]; __syncthreads(); }
    if (tid == 0) g_sc[blockIdx.x] = red[0] * (1.f/32.f);
}

// ---------------- branch-3 probs (single exp pass, smem-staged) ----------------
// grid (T, B), 512 threads
__global__ void __launch_bounds__(512) p3_kernel()
{
    __shared__ float scs[1024];
    __shared__ float w[1024];
    __shared__ float red[512];
    int i = blockIdx.x, b = blockIdx.y;
    int tid = threadIdx.x;
    scs[tid] = g_sc[b*TT + tid];
    scs[tid + 512] = g_sc[b*TT + tid + 512];
    __syncthreads();
    float sci = scs[i];
    long base = ((long)b*TT + i)*TT;

    float m = -CUDART_INF_F;
    for (int j = tid; j <= i; j += 512) m = fmaxf(m, sci * scs[j]);
    red[tid] = m; __syncthreads();
    for (int st = 256; st; st >>= 1) { if (tid < st) red[tid] = fmaxf(red[tid], red[tid+st]); __syncthreads(); }
    m = red[0]; __syncthreads();

    float sum = 0.f;
    for (int j = tid; j <= i; j += 512) {
        float v = fexp(sci * scs[j] - m);
        w[j] = v; sum += v;
    }
    red[tid] = sum; __syncthreads();
    for (int st = 256; st; st >>= 1) { if (tid < st) red[tid] += red[tid+st]; __syncthreads(); }
    float inv = 1.f / red[0];

    for (int j = tid; j <= i; j += 512)
        bsplit(w[j] * inv, g_p3h[base+j], g_p3l[base+j]);
    __nv_bfloat16 zz = __float2bfloat16(0.f);
    for (int j = i+1+tid; j < TT; j += 512) { g_p3h[base+j] = zz; g_p3l[base+j] = zz; }
}

// ---------------- branch 2 ----------------
// b2a: softmax weights + prefix inverse -> global. grid BH, 512 threads.
__global__ void __launch_bounds__(512) b2a_kernel()
{
    __shared__ float red[512];
    int bh = blockIdx.x;
    int tid = threadIdx.x;
    const float* s2p = g_s2 + bh*TT;

    float m = fmaxf(s2p[tid], s2p[tid + 512]);
    red[tid] = m; __syncthreads();
    for (int st = 256; st; st >>= 1) { if (tid < st) red[tid] = fmaxf(red[tid], red[tid+st]); __syncthreads(); }
    m = red[0]; __syncthreads();

    float w0 = fexp(s2p[2*tid] - m), w1 = fexp(s2p[2*tid+1] - m);
    g_b2w[bh*TT + 2*tid] = w0; g_b2w[bh*TT + 2*tid+1] = w1;
    red[tid] = w0 + w1; __syncthreads();
    for (int off = 1; off < 512; off <<= 1) {
        float v = (tid >= off) ? red[tid - off] : 0.f;
        __syncthreads();
        red[tid] += v;
        __syncthreads();
    }
    float basep = (tid == 0) ? 0.f : red[tid - 1];
    g_b2inv[bh*TT + 2*tid]   = 1.f / (basep + w0);
    g_b2inv[bh*TT + 2*tid+1] = 1.f / (basep + w0 + w1);
}

// b2b: gated prefix accumulate. grid (2, BH), 512 threads; lane = d column.
__global__ void __launch_bounds__(512) b2b_kernel(const float* __restrict__ gate)
{
    __shared__ float w[1024], inv[1024], seg[16][32];
    int bh = blockIdx.y, b = bh >> 4, h = bh & 15;
    int dh = blockIdx.x;
    int tid = threadIdx.x, wp = tid >> 5, ln = tid & 31;
    w[tid] = g_b2w[bh*TT + tid];     w[tid+512] = g_b2w[bh*TT + tid+512];
    inv[tid] = g_b2inv[bh*TT + tid]; inv[tid+512] = g_b2inv[bh*TT + tid+512];
    __syncthreads();

    const int d = dh*32 + ln;
    const float* rvp = g_rv + (long)b*TT*EE + h*64 + d;
    float p = 0.f;
    #pragma unroll 4
    for (int j = wp*64; j < wp*64 + 64; j++) p += w[j] * rvp[(long)j*EE];
    seg[wp][ln] = p;
    __syncthreads();
    if (tid < 32) {
        float a = 0.f;
        #pragma unroll
        for (int s = 0; s < 16; s++) { float t = seg[s][tid]; seg[s][tid] = a; a += t; }
    }
    __syncthreads();

    float g1 = gate_w(gate, h, 1);
    float a = seg[wp][ln];
    float* cp = g_comb + (long)b*TT*EE + h*64 + d;
    #pragma unroll 4
    for (int j = wp*64; j < wp*64 + 64; j++) {
        a += w[j] * rvp[(long)j*EE];
        cp[(long)j*EE] += g1 * a * inv[j];
    }
}

// ---------------- host launch ----------------
extern "C" void kernel_launch(void* const* d_in, const int* in_sizes, int n_in,
                              void* d_out, int out_size)
{
    const float* x    = (const float*)d_in[0];
    const float* wq   = (const float*)d_in[1];
    const float* wk   = (const float*)d_in[2];
    const float* wv   = (const float*)d_in[3];
    const float* wvr  = (const float*)d_in[4];
    const float* wr   = (const float*)d_in[5];
    const float* wj   = (const float*)d_in[6];
    const float* gate = (const float*)d_in[7];
    const float* wo   = (const float*)d_in[8];
    float* out = (float*)d_out;

#define GA(sym, var, type) type* var; cudaGetSymbolAddress((void**)&var, sym)
    GA(g_xh, xh, __nv_bfloat16);   GA(g_xl, xl, __nv_bfloat16);
    GA(g_wqh, wqh, __nv_bfloat16); GA(g_wql, wql, __nv_bfloat16);
    GA(g_wkh, wkh, __nv_bfloat16); GA(g_wkl, wkl, __nv_bfloat16);
    GA(g_wvh, wvh, __nv_bfloat16); GA(g_wvl, wvl, __nv_bfloat16);
    GA(g_wrh, wrh, __nv_bfloat16); GA(g_wrl, wrl, __nv_bfloat16);
    GA(g_wjh, wjh, __nv_bfloat16); GA(g_wjl, wjl, __nv_bfloat16);
    GA(g_wjTh, wjTh, __nv_bfloat16); GA(g_wjTl, wjTl, __nv_bfloat16);
    GA(g_woh, woh, __nv_bfloat16); GA(g_wol, wol, __nv_bfloat16);
    GA(g_qsh, qsh, __nv_bfloat16); GA(g_qsl, qsl, __nv_bfloat16);
    GA(g_ksh, ksh, __nv_bfloat16); GA(g_ksl, ksl, __nv_bfloat16);
    GA(g_vth, vth, __nv_bfloat16); GA(g_vtl, vtl, __nv_bfloat16);
    GA(g_rv, rvf, float);
    GA(g_echo, echof, float);
    GA(g_eh, eh, __nv_bfloat16);   GA(g_el, el, __nv_bfloat16);
    GA(g_eTh, eTh, __nv_bfloat16); GA(g_eTl, eTl, __nv_bfloat16);
    GA(g_eb, ebf, float);
    GA(g_comb, combf, float);
    GA(g_ch, ch, __nv_bfloat16);   GA(g_cl, cl, __nv_bfloat16);
    GA(g_p3h, p3h, __nv_bfloat16); GA(g_p3l, p3l, __nv_bfloat16);
#undef GA

    const int SM1P = 2 * 2 * (128 + 128) * 80;   // 81920
    cudaFuncSetAttribute(tgemm<128>, cudaFuncAttributeMaxDynamicSharedMemorySize, SM1P);
    cudaFuncSetAttribute(proj5, cudaFuncAttributeMaxDynamicSharedMemorySize, SM1P);
    cudaFuncSetAttribute(flash1, cudaFuncAttributeMaxDynamicSharedMemorySize, FL_SMEM);

    // 1. split x
    conv_split<<<(BT*EE)/1024, 256>>>(x, xh, xl, BT*EE);
    // 2. split all 6 weights in one launch
    CW cw;
    cw.in[0]=wq;  cw.oh[0]=wqh; cw.ol[0]=wql;
    cw.in[1]=wk;  cw.oh[1]=wkh; cw.ol[1]=wkl;
    cw.in[2]=wv;  cw.oh[2]=wvh; cw.ol[2]=wvl;
    cw.in[3]=wvr; cw.oh[3]=wrh; cw.ol[3]=wrl;
    cw.in[4]=wj;  cw.oh[4]=wjh; cw.ol[4]=wjl;
    cw.in[5]=wo;  cw.oh[5]=woh; cw.ol[5]=wol;
    conv_split_w<<<dim3((EE*EE)/1024, 6), 256>>>(cw);
    // 3. wj transpose split
    conv_split_T<<<(EE*EE)/256, 256>>>(wj, wjTh, wjTl);

    // 4. merged 5 projections
    P5 p;
    p.bh[0]=wqh; p.bl[0]=wql; p.cf[0]=nullptr; p.ch[0]=qsh; p.cl[0]=qsl; p.ldc[0]=0;    p.mode[0]=3;
    p.bh[1]=wkh; p.bl[1]=wkl; p.cf[1]=nullptr; p.ch[1]=ksh; p.cl[1]=ksl; p.ldc[1]=0;    p.mode[1]=3;
    p.bh[2]=wvh; p.bl[2]=wvl; p.cf[2]=nullptr; p.ch[2]=vth; p.cl[2]=vtl; p.ldc[2]=0;    p.mode[2]=2;
    p.bh[3]=wrh; p.bl[3]=wrl; p.cf[3]=rvf;     p.ch[3]=nullptr; p.cl[3]=nullptr; p.ldc[3]=1024; p.mode[3]=0;
    p.bh[4]=wjh; p.bl[4]=wjl; p.cf[4]=echof;   p.ch[4]=eh;  p.cl[4]=el;  p.ldc[4]=1024; p.mode[4]=4;
    proj5<<<dim3(8, 32, 5), 256, SM1P>>>(xh, xl, p);

    // 5. echo_back = echo @ wj
    tgemm<128><<<dim3(8, 32, 1), 256, SM1P>>>(eh, el, wjTh, wjTl, 1024, 1024, 1024, 0, 0, 0,
                                              0, ebf, nullptr, nullptr, 1024, 0, nullptr);

    // 6. branch 1 fused (ncu capture target: 6th launch)
    flash1<<<dim3(8, 64), 256, FL_SMEM>>>(gate);

    // 7-8. s2 / sc
    s2_kernel<<<dim3(TT/256, HH, BB), 256>>>(x, wr);
    sc_kernel<<<BT, 256>>>(x);

    // 9-10. branch-3 probs + echo transpose
    p3_kernel<<<dim3(TT, BB), 512>>>();
    transpose_split<<<dim3(32, 32, BB), dim3(32, 8)>>>(echof, eTh, eTl);

    // 11-12. branch 2
    b2a_kernel<<<BH, 512>>>();
    b2b_kernel<<<dim3(2, BH), 512>>>(gate);

    // 13. branch 3 GEMM: comb += g2[h] * (P3 @ echo), causal K-capped
    tgemm<128><<<dim3(8, 8, BB), 256, SM1P>>>(
        p3h, p3l, eTh, eTl, 1024, 1024, 1024,
        (long)TT*TT, (long)TT*EE, 1,
        5, combf, nullptr, nullptr, 1024, (long)TT*EE, gate);

    // 14-15. final: out = comb @ wo^T
    conv_split<<<(BT*EE)/1024, 256>>>(combf, ch, cl, BT*EE);
    tgemm<128><<<dim3(8, 32, 1), 256, SM1P>>>(ch, cl, woh, wol, 1024, 1024, 1024, 0, 0, 0,
                                              0, out, nullptr, nullptr, 1024, 0, nullptr);
}

// round 11
// speedup vs baseline: 5.3260x; 1.0668x over previous
#include <cuda_runtime.h>
#include <cuda_bf16.h>
#include <math_constants.h>
#include <cstdint>

#define BB 4
#define TT 1024
#define EE 1024
#define HH 16
#define DD 64
#define BT (BB*TT)   // 4096
#define BH (BB*HH)   // 64

// ---------------- scratch (device globals) ----------------
__device__ __nv_bfloat16 g_xh[BT*EE],  g_xl[BT*EE];
__device__ __nv_bfloat16 g_wqh[EE*EE], g_wql[EE*EE];
__device__ __nv_bfloat16 g_wkh[EE*EE], g_wkl[EE*EE];
__device__ __nv_bfloat16 g_wvh[EE*EE], g_wvl[EE*EE];
__device__ __nv_bfloat16 g_wrh[EE*EE], g_wrl[EE*EE];   // wvr
__device__ __nv_bfloat16 g_wjh[EE*EE], g_wjl[EE*EE];
__device__ __nv_bfloat16 g_wjTh[EE*EE],g_wjTl[EE*EE];
__device__ __nv_bfloat16 g_woh[EE*EE], g_wol[EE*EE];
__device__ __nv_bfloat16 g_qsh[BH*TT*DD], g_qsl[BH*TT*DD];  // [bh][t][d]
__device__ __nv_bfloat16 g_ksh[BH*TT*DD], g_ksl[BH*TT*DD];  // [bh][t][d]
__device__ __nv_bfloat16 g_vth[BH*DD*TT], g_vtl[BH*DD*TT];  // [bh][d][t]
__device__ float g_rv[BT*EE];
__device__ float g_echo[BT*EE];
__device__ __nv_bfloat16 g_eh[BT*EE], g_el[BT*EE];
__device__ __nv_bfloat16 g_eTh[BT*EE], g_eTl[BT*EE];        // echo^T per batch [b][e][t]
__device__ float g_eb[BT*EE];
__device__ float g_comb[BT*EE];
__device__ __nv_bfloat16 g_ch[BT*EE], g_cl[BT*EE];
__device__ __nv_bfloat16 g_p3h[(long)BB*TT*TT], g_p3l[(long)BB*TT*TT];  // branch-3 probs
__device__ float g_s2[BH*TT];
__device__ float g_sc[BB*TT];
__device__ float g_b2w[BH*TT], g_b2inv[BH*TT];

// ---------------- helpers ----------------
__device__ __forceinline__ uint32_t smem_u32(const void* p) {
    uint32_t a;
    asm("{ .reg .u64 t; cvta.to.shared.u64 t, %1; cvt.u32.u64 %0, t; }" : "=r"(a) : "l"(p));
    return a;
}
__device__ __forceinline__ void cpasync16(uint32_t saddr, const void* g) {
    asm volatile("cp.async.cg.shared.global [%0], [%1], 16;" :: "r"(saddr), "l"(g));
}
#define CP_COMMIT() asm volatile("cp.async.commit_group;" ::: "memory")
#define CP_WAIT1()  asm volatile("cp.async.wait_group 1;"  ::: "memory")
#define CP_WAIT2()  asm volatile("cp.async.wait_group 2;"  ::: "memory")

__device__ __forceinline__ void ldsm4(uint32_t* r, uint32_t addr) {
    asm volatile("ldmatrix.sync.aligned.m8n8.x4.shared.b16 {%0,%1,%2,%3}, [%4];"
        : "=r"(r[0]), "=r"(r[1]), "=r"(r[2]), "=r"(r[3]) : "r"(addr));
}
__device__ __forceinline__ void mma16816(float* d, const uint32_t* a, const uint32_t* b) {
    asm volatile("mma.sync.aligned.m16n8k16.row.col.f32.bf16.bf16.f32 "
        "{%0,%1,%2,%3}, {%4,%5,%6,%7}, {%8,%9}, {%0,%1,%2,%3};"
        : "+f"(d[0]), "+f"(d[1]), "+f"(d[2]), "+f"(d[3])
        : "r"(a[0]), "r"(a[1]), "r"(a[2]), "r"(a[3]), "r"(b[0]), "r"(b[1]));
}

// fast exp on FMA pipe. valid x <= 0; clamps below -80. rel err < 3e-6.
__device__ __forceinline__ float fexp(float x) {
    x = fmaxf(x, -80.f);
    float y = x * 1.4426950408889634f;
    int   e = __float2int_rn(y);
    float f = y - (float)e;
    float p = 1.3333558e-3f;
    p = fmaf(p, f, 9.6181292e-3f);
    p = fmaf(p, f, 5.5504109e-2f);
    p = fmaf(p, f, 2.4022651e-1f);
    p = fmaf(p, f, 6.9314718e-1f);
    p = fmaf(p, f, 1.0f);
    return __int_as_float((e + 127) << 23) * p;
}

__device__ __forceinline__ float gate_w(const float* gate, int h, int c) {
    float a = gate[h*3+0], b = gate[h*3+1], d = gate[h*3+2];
    float m = fmaxf(a, fmaxf(b, d));
    float ea = __expf(a-m), eb = __expf(b-m), ec = __expf(d-m);
    float s = ea + eb + ec;
    float num = (c == 0) ? ea : (c == 1) ? eb : ec;
    return num / s;
}
__device__ __forceinline__ void bsplit(float v, __nv_bfloat16& h, __nv_bfloat16& l) {
    h = __float2bfloat16(v);
    l = __float2bfloat16(v - __bfloat162float(h));
}
__device__ __forceinline__ uint32_t pk2(__nv_bfloat16 a, __nv_bfloat16 b) {
    __nv_bfloat162 t; t.x = a; t.y = b;
    return *reinterpret_cast<uint32_t*>(&t);
}

// swizzled offset within a 64B-row tile: row r, 16B column c (0..3)
__device__ __forceinline__ uint32_t swz(int r, int c) {
    return (uint32_t)(r*64 + ((c ^ ((r >> 1) & 3)) << 4));
}

// ---------------- single-pass 3-term HMMA split-bf16 GEMM body ----------------
// C = sum_k (AhBh + AhBl + AlBh). 3-stage cp.async pipeline, swizzled smem.
// modes: 0 fp32; 2 vT-split; 3 ts-split; 4 fp32+split; 5 fp32 += gate2[h(gn)]*v
template<int TN>
__device__ __forceinline__ void gemm_body(
    char* smem, const __nv_bfloat16* __restrict__ Ah, const __nv_bfloat16* __restrict__ Al,
    const __nv_bfloat16* __restrict__ Bh, const __nv_bfloat16* __restrict__ Bl,
    int NC, long lda, long ldb,
    int mode, float* __restrict__ CfB,
    __nv_bfloat16* __restrict__ Ch, __nv_bfloat16* __restrict__ Cl,
    long ldc, const float* __restrict__ gate)
{
    constexpr int TM = 128;
    constexpr int AOFF_L = TM*64;
    constexpr int BOFF_H = 2*TM*64;
    constexpr int BOFF_L = 2*TM*64 + TN*64;
    constexpr int STG = 2*TM*64 + 2*TN*64;   // 32768 for TN=128
    constexpr int WARPS_N = TN/32, WARPS_M = 8/WARPS_N;
    constexpr int WM = TM/WARPS_M, MI = WM/16;

    __shared__ float sgate[16];
    const int tid = threadIdx.x, wid = tid >> 5, lane = tid & 31;
    const int m0 = blockIdx.y*TM, n0 = blockIdx.x*TN;
    const int wm = wid / WARPS_N, wn = wid % WARPS_N;
    const uint32_t sbase = smem_u32(smem);

    if (mode == 5 && tid < 16) sgate[tid] = gate_w(gate, tid, 2);

    auto prefetch = [&](int c, int s) {
        int k0 = c * 32;
        uint32_t st = sbase + s*STG;
        #pragma unroll 2
        for (int i = tid; i < TM*4; i += 256) {
            int r = i >> 2, cc = i & 3;
            long go = (long)(m0 + r)*lda + k0 + cc*8;
            uint32_t so = swz(r, cc);
            cpasync16(st + so,            Ah + go);
            cpasync16(st + AOFF_L + so,   Al + go);
        }
        #pragma unroll 2
        for (int i = tid; i < TN*4; i += 256) {
            int r = i >> 2, cc = i & 3;
            long go = (long)(n0 + r)*ldb + k0 + cc*8;
            uint32_t so = swz(r, cc);
            cpasync16(st + BOFF_H + so,   Bh + go);
            cpasync16(st + BOFF_L + so,   Bl + go);
        }
    };

    float acc[MI][4][4] = {};
    prefetch(0, 0); CP_COMMIT();
    if (NC > 1) prefetch(1, 1);
    CP_COMMIT();

    for (int c = 0; c < NC; c++) {
        if (c + 2 < NC) prefetch(c + 2, (c + 2) % 3);
        CP_COMMIT();
        CP_WAIT2();
        __syncthreads();

        uint32_t st = sbase + (c % 3)*STG;
        #pragma unroll
        for (int ks = 0; ks < 2; ks++) {
            const int kc = ks*2 + (lane >> 4);   // logical 16B column
            uint32_t aH[MI][4], bH[2][4], bL[2][4];
            #pragma unroll
            for (int mi = 0; mi < MI; mi++)
                ldsm4(aH[mi], st + swz(wm*WM + mi*16 + (lane & 15), kc));
            #pragma unroll
            for (int bi = 0; bi < 2; bi++) {
                ldsm4(bH[bi], st + BOFF_H + swz(wn*32 + bi*16 + (lane & 15), kc));
                ldsm4(bL[bi], st + BOFF_L + swz(wn*32 + bi*16 + (lane & 15), kc));
            }
            // independent-accumulator sweeps
            #pragma unroll
            for (int mi = 0; mi < MI; mi++)
                #pragma unroll
                for (int ni = 0; ni < 4; ni++) {
                    uint32_t h2[2] = { bH[ni>>1][ni & 1], bH[ni>>1][(ni & 1) + 2] };
                    mma16816(acc[mi][ni], aH[mi], h2);
                }
            #pragma unroll
            for (int mi = 0; mi < MI; mi++)
                #pragma unroll
                for (int ni = 0; ni < 4; ni++) {
                    uint32_t l2[2] = { bL[ni>>1][ni & 1], bL[ni>>1][(ni & 1) + 2] };
                    mma16816(acc[mi][ni], aH[mi], l2);
                }
            uint32_t aL[MI][4];
            #pragma unroll
            for (int mi = 0; mi < MI; mi++)
                ldsm4(aL[mi], st + AOFF_L + swz(wm*WM + mi*16 + (lane & 15), kc));
            #pragma unroll
            for (int mi = 0; mi < MI; mi++)
                #pragma unroll
                for (int ni = 0; ni < 4; ni++) {
                    uint32_t h2[2] = { bH[ni>>1][ni & 1], bH[ni>>1][(ni & 1) + 2] };
                    mma16816(acc[mi][ni], aL[mi], h2);
                }
        }
        __syncthreads();
    }

    // epilogue
    #pragma unroll
    for (int mi = 0; mi < MI; mi++) {
        #pragma unroll
        for (int ni = 0; ni < 4; ni++) {
            int rb = m0 + wm*WM + mi*16 + (lane >> 2);
            int cb = n0 + wn*32 + ni*8 + (lane & 3)*2;
            #pragma unroll
            for (int q = 0; q < 4; q++) {
                int gm = rb + (q >> 1)*8, gn = cb + (q & 1);
                float v = acc[mi][ni][q];
                if (mode == 0) {
                    CfB[(long)gm*ldc + gn] = v;
                } else if (mode == 4) {
                    long idx = (long)gm*ldc + gn;
                    CfB[idx] = v;
                    bsplit(v, Ch[idx], Cl[idx]);
                } else if (mode == 2) {   // vT: [(b*16+h)][d][t]
                    int b = gm >> 10, t = gm & 1023, h = gn >> 6, d = gn & 63;
                    long idx = (((long)(b*16 + h)) * 64 + d) * 1024 + t;
                    bsplit(v, Ch[idx], Cl[idx]);
                } else if (mode == 3) {   // [(b*16+h)][t][d]
                    int b = gm >> 10, t = gm & 1023, h = gn >> 6, d = gn & 63;
                    long idx = (((long)(b*16 + h)) * 1024 + t) * 64 + d;
                    bsplit(v, Ch[idx], Cl[idx]);
                } else {                  // mode 5: gated accumulate
                    CfB[(long)gm*ldc + gn] += sgate[gn >> 6] * v;
                }
            }
        }
    }
}

// generic wrapper (eb / branch-3 / final)
template<int TN>
__global__ void __launch_bounds__(256, 2) tgemm(
    const __nv_bfloat16* __restrict__ Ah_, const __nv_bfloat16* __restrict__ Al_,
    const __nv_bfloat16* __restrict__ Bh_, const __nv_bfloat16* __restrict__ Bl_,
    int K, long lda, long ldb, long sAz, long sBz, int kcap,
    int mode, float* __restrict__ Cf,
    __nv_bfloat16* __restrict__ Ch, __nv_bfloat16* __restrict__ Cl,
    long ldc, long sCz, const float* __restrict__ gate)
{
    extern __shared__ char smem[];
    const int z = blockIdx.z;
    const int Keff = kcap ? (blockIdx.y*128 + 128) : K;
    gemm_body<TN>(smem,
                  Ah_ + (long)z*sAz, Al_ + (long)z*sAz,
                  Bh_ + (long)z*sBz, Bl_ + (long)z*sBz,
                  Keff/32, lda, ldb, mode,
                  Cf ? (Cf + (long)z*sCz) : nullptr, Ch, Cl, ldc, gate);
}

// merged 5-projection kernel (z picks weight + output mode)
struct P5 {
    const __nv_bfloat16* bh[5]; const __nv_bfloat16* bl[5];
    float* cf[5]; __nv_bfloat16* ch[5]; __nv_bfloat16* cl[5];
    long ldc[5]; int mode[5];
};
__global__ void __launch_bounds__(256, 2) proj5(
    const __nv_bfloat16* __restrict__ xh, const __nv_bfloat16* __restrict__ xl, P5 p)
{
    extern __shared__ char smem[];
    const int z = blockIdx.z;
    gemm_body<128>(smem, xh, xl, p.bh[z], p.bl[z], 32, 1024, 1024,
                   p.mode[z], p.cf[z], p.ch[z], p.cl[z], p.ldc[z], nullptr);
}

// ---------------- fused flash branch 1 ----------------
#define FL_SMEM 180224
__global__ void __launch_bounds__(256) flash1(const float* __restrict__ gate)
{
    extern __shared__ char smem[];
    const int tid = threadIdx.x, wid = tid >> 5, lane = tid & 31;
    const int m0 = (gridDim.x - 1 - blockIdx.x) * 128;   // heavy tiles first
    const int bh = blockIdx.y;
    const uint32_t sb = smem_u32(smem);
    const uint32_t sQh = sb, sQl = sb + 18432;

    const long qoff = (long)bh * TT * DD;
    const long voff = (long)bh * DD * TT;

    for (int i = tid; i < 128*8; i += 256) {
        int r = i >> 3, c = i & 7;
        cpasync16(sQh + r*144 + c*16, g_qsh + qoff + (long)(m0+r)*64 + c*8);
        cpasync16(sQl + r*144 + c*16, g_qsl + qoff + (long)(m0+r)*64 + c*8);
    }
    CP_COMMIT();

    const int nchunks = m0/128 + 1;
    auto pf = [&](int cidx, int st) {
        uint32_t kh = sb + 36864 + st*36864, kl = kh + 18432;
        uint32_t vh = sb + 110592 + st*34816, vl = vh + 17408;
        int j0 = cidx * 128;
        for (int i = tid; i < 128*8; i += 256) {
            int r = i >> 3, c = i & 7;
            cpasync16(kh + r*144 + c*16, g_ksh + qoff + (long)(j0+r)*64 + c*8);
            cpasync16(kl + r*144 + c*16, g_ksl + qoff + (long)(j0+r)*64 + c*8);
        }
        for (int i = tid; i < 64*16; i += 256) {
            int r = i >> 4, c = i & 15;
            cpasync16(vh + r*272 + c*16, g_vth + voff + (long)r*TT + j0 + c*8);
            cpasync16(vl + r*272 + c*16, g_vtl + voff + (long)r*TT + j0 + c*8);
        }
    };
    pf(0, 0); CP_COMMIT();

    uint32_t qfh[4][4], qfl[4][4];
    float oa[8][4] = {};
    float ms0 = -1e30f, ms1 = -1e30f, l0 = 0.f, l1 = 0.f;

    for (int c = 0; c < nchunks; c++) {
        if (c + 1 < nchunks) pf(c + 1, (c + 1) & 1);
        CP_COMMIT();
        CP_WAIT1();
        __syncthreads();

        if (c == 0) {
            #pragma unroll
            for (int ks = 0; ks < 4; ks++) {
                ldsm4(qfh[ks], sQh + (wid*16 + (lane & 15))*144 + ks*32 + (lane >> 4)*16);
                ldsm4(qfl[ks], sQl + (wid*16 + (lane & 15))*144 + ks*32 + (lane >> 4)*16);
            }
        }

        const int st = c & 1, j0 = c * 128;
        const uint32_t khb = sb + 36864 + st*36864, klb = khb + 18432;
        const uint32_t vhb = sb + 110592 + st*34816, vlb = vhb + 17408;

        float sa[16][4];
        #pragma unroll
        for (int nt = 0; nt < 16; nt++)
            sa[nt][0] = sa[nt][1] = sa[nt][2] = sa[nt][3] = 0.f;

        #pragma unroll
        for (int ks = 0; ks < 4; ks++) {
            uint32_t bf4[8][4];
            #pragma unroll
            for (int g = 0; g < 8; g++)
                ldsm4(bf4[g], khb + (g*16 + (lane & 15))*144 + ks*32 + (lane >> 4)*16);
            #pragma unroll
            for (int nt = 0; nt < 16; nt++) {
                uint32_t b2[2] = { bf4[nt>>1][nt & 1], bf4[nt>>1][(nt & 1) + 2] };
                mma16816(sa[nt], qfh[ks], b2);
            }
            #pragma unroll
            for (int nt = 0; nt < 16; nt++) {
                uint32_t b2[2] = { bf4[nt>>1][nt & 1], bf4[nt>>1][(nt & 1) + 2] };
                mma16816(sa[nt], qfl[ks], b2);
            }
            #pragma unroll
            for (int g = 0; g < 8; g++)
                ldsm4(bf4[g], klb + (g*16 + (lane & 15))*144 + ks*32 + (lane >> 4)*16);
            #pragma unroll
            for (int nt = 0; nt < 16; nt++) {
                uint32_t b2[2] = { bf4[nt>>1][nt & 1], bf4[nt>>1][(nt & 1) + 2] };
                mma16816(sa[nt], qfh[ks], b2);
            }
        }

        const int qr0 = m0 + wid*16 + (lane >> 2);
        const int qr1 = qr0 + 8;
        if (j0 == m0) {
            #pragma unroll
            for (int nt = 0; nt < 16; nt++) {
                int col = j0 + nt*8 + (lane & 3)*2;
                sa[nt][0] = (col     > qr0) ? -1e30f : sa[nt][0]*0.125f;
                sa[nt][1] = (col + 1 > qr0) ? -1e30f : sa[nt][1]*0.125f;
                sa[nt][2] = (col     > qr1) ? -1e30f : sa[nt][2]*0.125f;
                sa[nt][3] = (col + 1 > qr1) ? -1e30f : sa[nt][3]*0.125f;
            }
        } else {
            #pragma unroll
            for (int nt = 0; nt < 16; nt++) {
                sa[nt][0] *= 0.125f; sa[nt][1] *= 0.125f;
                sa[nt][2] *= 0.125f; sa[nt][3] *= 0.125f;
            }
        }

        float mx0 = -1e30f, mx1 = -1e30f;
        #pragma unroll
        for (int nt = 0; nt < 16; nt++) {
            mx0 = fmaxf(mx0, fmaxf(sa[nt][0], sa[nt][1]));
            mx1 = fmaxf(mx1, fmaxf(sa[nt][2], sa[nt][3]));
        }
        mx0 = fmaxf(mx0, __shfl_xor_sync(0xffffffffu, mx0, 1));
        mx0 = fmaxf(mx0, __shfl_xor_sync(0xffffffffu, mx0, 2));
        mx1 = fmaxf(mx1, __shfl_xor_sync(0xffffffffu, mx1, 1));
        mx1 = fmaxf(mx1, __shfl_xor_sync(0xffffffffu, mx1, 2));

        float mn0 = fmaxf(ms0, mx0), mn1 = fmaxf(ms1, mx1);
        float cor0 = fexp(ms0 - mn0), cor1 = fexp(ms1 - mn1);

        float rs0 = 0.f, rs1 = 0.f;
        #pragma unroll
        for (int nt = 0; nt < 16; nt++) {
            sa[nt][0] = fexp(sa[nt][0] - mn0);
            sa[nt][1] = fexp(sa[nt][1] - mn0);
            sa[nt][2] = fexp(sa[nt][2] - mn1);
            sa[nt][3] = fexp(sa[nt][3] - mn1);
            rs0 += sa[nt][0] + sa[nt][1];
            rs1 += sa[nt][2] + sa[nt][3];
        }
        rs0 += __shfl_xor_sync(0xffffffffu, rs0, 1);
        rs0 += __shfl_xor_sync(0xffffffffu, rs0, 2);
        rs1 += __shfl_xor_sync(0xffffffffu, rs1, 1);
        rs1 += __shfl_xor_sync(0xffffffffu, rs1, 2);
        l0 = l0*cor0 + rs0;
        l1 = l1*cor1 + rs1;
        ms0 = mn0; ms1 = mn1;
        #pragma unroll
        for (int dn = 0; dn < 8; dn++) {
            oa[dn][0] *= cor0; oa[dn][1] *= cor0;
            oa[dn][2] *= cor1; oa[dn][3] *= cor1;
        }

        // ---- O += Ph Vh + Pl Vh + Ph Vl (independent-acc sweeps) ----
        #pragma unroll
        for (int ks = 0; ks < 8; ks++) {
            uint32_t aH[4], aL[4];
            {
                float p0 = sa[2*ks][0],   p1 = sa[2*ks][1];
                float p2 = sa[2*ks][2],   p3 = sa[2*ks][3];
                float r0 = sa[2*ks+1][0], r1 = sa[2*ks+1][1];
                float r2 = sa[2*ks+1][2], r3 = sa[2*ks+1][3];
                __nv_bfloat16 h0 = __float2bfloat16(p0), h1 = __float2bfloat16(p1);
                __nv_bfloat16 h2 = __float2bfloat16(p2), h3 = __float2bfloat16(p3);
                __nv_bfloat16 g0 = __float2bfloat16(r0), g1 = __float2bfloat16(r1);
                __nv_bfloat16 g2 = __float2bfloat16(r2), g3 = __float2bfloat16(r3);
                aH[0] = pk2(h0, h1); aH[1] = pk2(h2, h3);
                aH[2] = pk2(g0, g1); aH[3] = pk2(g2, g3);
                aL[0] = pk2(__float2bfloat16(p0 - __bfloat162float(h0)),
                            __float2bfloat16(p1 - __bfloat162float(h1)));
                aL[1] = pk2(__float2bfloat16(p2 - __bfloat162float(h2)),
                            __float2bfloat16(p3 - __bfloat162float(h3)));
                aL[2] = pk2(__float2bfloat16(r0 - __bfloat162float(g0)),
                            __float2bfloat16(r1 - __bfloat162float(g1)));
                aL[3] = pk2(__float2bfloat16(r2 - __bfloat162float(g2)),
                            __float2bfloat16(r3 - __bfloat162float(g3)));
            }
            uint32_t bvh[4][4], bvl[4][4];
            #pragma unroll
            for (int g = 0; g < 4; g++) {
                ldsm4(bvh[g], vhb + (g*16 + (lane & 15))*272 + ks*32 + (lane >> 4)*16);
                ldsm4(bvl[g], vlb + (g*16 + (lane & 15))*272 + ks*32 + (lane >> 4)*16);
            }
            #pragma unroll
            for (int dn = 0; dn < 8; dn++) {
                uint32_t b2h[2] = { bvh[dn>>1][dn & 1], bvh[dn>>1][(dn & 1) + 2] };
                mma16816(oa[dn], aH, b2h);
            }
            #pragma unroll
            for (int dn = 0; dn < 8; dn++) {
                uint32_t b2h[2] = { bvh[dn>>1][dn & 1], bvh[dn>>1][(dn & 1) + 2] };
                mma16816(oa[dn], aL, b2h);
            }
            #pragma unroll
            for (int dn = 0; dn < 8; dn++) {
                uint32_t b2l[2] = { bvl[dn>>1][dn & 1], bvl[dn>>1][(dn & 1) + 2] };
                mma16816(oa[dn], aH, b2l);
            }
        }
        __syncthreads();
    }

    const float g0w = gate_w(gate, bh & 15, 0);
    const float s0 = g0w / l0, s1 = g0w / l1;
    const int b = bh >> 4, h = bh & 15;
    const int qr0 = m0 + wid*16 + (lane >> 2), qr1 = qr0 + 8;
    float* c0 = g_comb + ((long)b*TT + qr0)*EE + h*64;
    float* c1 = g_comb + ((long)b*TT + qr1)*EE + h*64;
    #pragma unroll
    for (int dn = 0; dn < 8; dn++) {
        int d = dn*8 + (lane & 3)*2;
        c0[d]   = oa[dn][0]*s0; c0[d+1] = oa[dn][1]*s0;
        c1[d]   = oa[dn][2]*s1; c1[d+1] = oa[dn][3]*s1;
    }
}

// ---------------- conversion kernels ----------------
__global__ void conv_split(const float* __restrict__ in,
                           __nv_bfloat16* __restrict__ h, __nv_bfloat16* __restrict__ l, int n)
{
    int i = (blockIdx.x * 256 + threadIdx.x) * 4;
    if (i >= n) return;
    float4 v = *(const float4*)(in + i);
    __nv_bfloat16 h0,h1,h2,h3,l0,l1,l2,l3;
    bsplit(v.x,h0,l0); bsplit(v.y,h1,l1); bsplit(v.z,h2,l2); bsplit(v.w,h3,l3);
    *(uint2*)(h + i) = make_uint2(pk2(h0,h1), pk2(h2,h3));
    *(uint2*)(l + i) = make_uint2(pk2(l0,l1), pk2(l2,l3));
}
struct CW { const float* in[6]; __nv_bfloat16* oh[6]; __nv_bfloat16* ol[6]; };
__global__ void conv_split_w(CW cw)
{
    int t = blockIdx.y;
    int i = (blockIdx.x * 256 + threadIdx.x) * 4;
    float4 v = *(const float4*)(cw.in[t] + i);
    __nv_bfloat16 h0,h1,h2,h3,l0,l1,l2,l3;
    bsplit(v.x,h0,l0); bsplit(v.y,h1,l1); bsplit(v.z,h2,l2); bsplit(v.w,h3,l3);
    *(uint2*)(cw.oh[t] + i) = make_uint2(pk2(h0,h1), pk2(h2,h3));
    *(uint2*)(cw.ol[t] + i) = make_uint2(pk2(l0,l1), pk2(l2,l3));
}
__global__ void conv_split_T(const float* __restrict__ in,
                             __nv_bfloat16* __restrict__ h, __nv_bfloat16* __restrict__ l)
{   // out[e*E+f] = in[f*E+e]
    int i = blockIdx.x * 256 + threadIdx.x;
    int e = i >> 10, f = i & 1023;
    bsplit(in[(long)f * EE + e], h[i], l[i]);
}
// per-batch transpose-split: echo [b][t][e] -> echoT [b][e][t]
__global__ void transpose_split(const float* __restrict__ in,
                                __nv_bfloat16* __restrict__ oh, __nv_bfloat16* __restrict__ ol)
{
    __shared__ float tile[32][33];
    int b = blockIdx.z;
    int t0 = blockIdx.x * 32, e0 = blockIdx.y * 32;
    int tx = threadIdx.x, ty = threadIdx.y;   // (32, 8)
    const float* ib = in + ((long)b*TT + t0)*EE + e0;
    #pragma unroll
    for (int k = 0; k < 4; k++)
        tile[ty + k*8][tx] = ib[(long)(ty + k*8)*EE + tx];
    __syncthreads();
    #pragma unroll
    for (int k = 0; k < 4; k++) {
        int e = ty + k*8;
        long idx = ((long)b*EE + e0 + e)*TT + t0 + tx;
        bsplit(tile[tx][e], oh[idx], ol[idx]);
    }
}

// ---------------- s2[b,h,t] = (1/8) dot(x[b,t,:], wr[h,:,t]) ----------------
__global__ void s2_kernel(const float* __restrict__ x, const float* __restrict__ wr)
{
    __shared__ float xs[256][33];
    int t0 = blockIdx.x * 256;
    int h = blockIdx.y, b = blockIdx.z;
    int tid = threadIdx.x, w = tid >> 5, lane = tid & 31;
    int t = t0 + tid;
    float acc = 0.f;
    for (int e0 = 0; e0 < EE; e0 += 32) {
        #pragma unroll 4
        for (int rr = 0; rr < 32; rr++)
            xs[w*32 + rr][lane] = x[(long)b*TT*EE + (long)(t0 + w*32 + rr)*EE + e0 + lane];
        __syncthreads();
        const float* wrp = wr + (long)h*EE*TT + (long)e0*TT + t;
        #pragma unroll
        for (int e = 0; e < 32; e++) acc += xs[tid][e] * wrp[(long)e*TT];
        __syncthreads();
    }
    g_s2[(b*HH + h)*TT + t] = acc * 0.125f;
}

// ---------------- sc[b,t] = dot(x[b,t], eb[b,t]) / 32 ----------------
__global__ void sc_kernel(const float* __restrict__ x)
{
    __shared__ float red[256];
    long base = (long)blockIdx.x * EE;
    int tid = threadIdx.x;
    float s = 0.f;
    for (int e = tid; e < EE; e += 256) s += x[base+e] * g_eb[base+e];
    red[tid] = s; __syncthreads();
    for (int st = 128; st; st >>= 1) { if (tid < st) red[tid] += red[tid+st]; __syncthreads(); }
    if (tid == 0) g_sc[blockIdx.x] = red[0] * (1.f/32.f);
}

// ---------------- branch-3 probs (single exp pass, smem-staged) ----------------
// grid (T, B), 512 threads
__global__ void __launch_bounds__(512) p3_kernel()
{
    __shared__ float scs[1024];
    __shared__ float w[1024];
    __shared__ float red[512];
    int i = blockIdx.x, b = blockIdx.y;
    int tid = threadIdx.x;
    scs[tid] = g_sc[b*TT + tid];
    scs[tid + 512] = g_sc[b*TT + tid + 512];
    __syncthreads();
    float sci = scs[i];
    long base = ((long)b*TT + i)*TT;

    float m = -CUDART_INF_F;
    for (int j = tid; j <= i; j += 512) m = fmaxf(m, sci * scs[j]);
    red[tid] = m; __syncthreads();
    for (int st = 256; st; st >>= 1) { if (tid < st) red[tid] = fmaxf(red[tid], red[tid+st]); __syncthreads(); }
    m = red[0]; __syncthreads();

    float sum = 0.f;
    for (int j = tid; j <= i; j += 512) {
        float v = fexp(sci * scs[j] - m);
        w[j] = v; sum += v;
    }
    red[tid] = sum; __syncthreads();
    for (int st = 256; st; st >>= 1) { if (tid < st) red[tid] += red[tid+st]; __syncthreads(); }
    float inv = 1.f / red[0];

    for (int j = tid; j <= i; j += 512)
        bsplit(w[j] * inv, g_p3h[base+j], g_p3l[base+j]);
    __nv_bfloat16 zz = __float2bfloat16(0.f);
    for (int j = i+1+tid; j < TT; j += 512) { g_p3h[base+j] = zz; g_p3l[base+j] = zz; }
}

// ---------------- branch 2 ----------------
// b2a: softmax weights + prefix inverse -> global. grid BH, 512 threads.
__global__ void __launch_bounds__(512) b2a_kernel()
{
    __shared__ float red[512];
    int bh = blockIdx.x;
    int tid = threadIdx.x;
    const float* s2p = g_s2 + bh*TT;

    float m = fmaxf(s2p[tid], s2p[tid + 512]);
    red[tid] = m; __syncthreads();
    for (int st = 256; st; st >>= 1) { if (tid < st) red[tid] = fmaxf(red[tid], red[tid+st]); __syncthreads(); }
    m = red[0]; __syncthreads();

    float w0 = fexp(s2p[2*tid] - m), w1 = fexp(s2p[2*tid+1] - m);
    g_b2w[bh*TT + 2*tid] = w0; g_b2w[bh*TT + 2*tid+1] = w1;
    red[tid] = w0 + w1; __syncthreads();
    for (int off = 1; off < 512; off <<= 1) {
        float v = (tid >= off) ? red[tid - off] : 0.f;
        __syncthreads();
        red[tid] += v;
        __syncthreads();
    }
    float basep = (tid == 0) ? 0.f : red[tid - 1];
    g_b2inv[bh*TT + 2*tid]   = 1.f / (basep + w0);
    g_b2inv[bh*TT + 2*tid+1] = 1.f / (basep + w0 + w1);
}

// b2b: gated prefix accumulate. grid (2, BH), 512 threads; lane = d column.
__global__ void __launch_bounds__(512) b2b_kernel(const float* __restrict__ gate)
{
    __shared__ float w[1024], inv[1024], seg[16][32];
    int bh = blockIdx.y, b = bh >> 4, h = bh & 15;
    int dh = blockIdx.x;
    int tid = threadIdx.x, wp = tid >> 5, ln = tid & 31;
    w[tid] = g_b2w[bh*TT + tid];     w[tid+512] = g_b2w[bh*TT + tid+512];
    inv[tid] = g_b2inv[bh*TT + tid]; inv[tid+512] = g_b2inv[bh*TT + tid+512];
    __syncthreads();

    const int d = dh*32 + ln;
    const float* rvp = g_rv + (long)b*TT*EE + h*64 + d;
    float p = 0.f;
    #pragma unroll 4
    for (int j = wp*64; j < wp*64 + 64; j++) p += w[j] * rvp[(long)j*EE];
    seg[wp][ln] = p;
    __syncthreads();
    if (tid < 32) {
        float a = 0.f;
        #pragma unroll
        for (int s = 0; s < 16; s++) { float t = seg[s][tid]; seg[s][tid] = a; a += t; }
    }
    __syncthreads();

    float g1 = gate_w(gate, h, 1);
    float a = seg[wp][ln];
    float* cp = g_comb + (long)b*TT*EE + h*64 + d;
    #pragma unroll 4
    for (int j = wp*64; j < wp*64 + 64; j++) {
        a += w[j] * rvp[(long)j*EE];
        cp[(long)j*EE] += g1 * a * inv[j];
    }
}

// ---------------- host launch ----------------
extern "C" void kernel_launch(void* const* d_in, const int* in_sizes, int n_in,
                              void* d_out, int out_size)
{
    const float* x    = (const float*)d_in[0];
    const float* wq   = (const float*)d_in[1];
    const float* wk   = (const float*)d_in[2];
    const float* wv   = (const float*)d_in[3];
    const float* wvr  = (const float*)d_in[4];
    const float* wr   = (const float*)d_in[5];
    const float* wj   = (const float*)d_in[6];
    const float* gate = (const float*)d_in[7];
    const float* wo   = (const float*)d_in[8];
    float* out = (float*)d_out;

#define GA(sym, var, type) type* var; cudaGetSymbolAddress((void**)&var, sym)
    GA(g_xh, xh, __nv_bfloat16);   GA(g_xl, xl, __nv_bfloat16);
    GA(g_wqh, wqh, __nv_bfloat16); GA(g_wql, wql, __nv_bfloat16);
    GA(g_wkh, wkh, __nv_bfloat16); GA(g_wkl, wkl, __nv_bfloat16);
    GA(g_wvh, wvh, __nv_bfloat16); GA(g_wvl, wvl, __nv_bfloat16);
    GA(g_wrh, wrh, __nv_bfloat16); GA(g_wrl, wrl, __nv_bfloat16);
    GA(g_wjh, wjh, __nv_bfloat16); GA(g_wjl, wjl, __nv_bfloat16);
    GA(g_wjTh, wjTh, __nv_bfloat16); GA(g_wjTl, wjTl, __nv_bfloat16);
    GA(g_woh, woh, __nv_bfloat16); GA(g_wol, wol, __nv_bfloat16);
    GA(g_qsh, qsh, __nv_bfloat16); GA(g_qsl, qsl, __nv_bfloat16);
    GA(g_ksh, ksh, __nv_bfloat16); GA(g_ksl, ksl, __nv_bfloat16);
    GA(g_vth, vth, __nv_bfloat16); GA(g_vtl, vtl, __nv_bfloat16);
    GA(g_rv, rvf, float);
    GA(g_echo, echof, float);
    GA(g_eh, eh, __nv_bfloat16);   GA(g_el, el, __nv_bfloat16);
    GA(g_eTh, eTh, __nv_bfloat16); GA(g_eTl, eTl, __nv_bfloat16);
    GA(g_eb, ebf, float);
    GA(g_comb, combf, float);
    GA(g_ch, ch, __nv_bfloat16);   GA(g_cl, cl, __nv_bfloat16);
    GA(g_p3h, p3h, __nv_bfloat16); GA(g_p3l, p3l, __nv_bfloat16);
#undef GA

    const int SM1P = 3 * (2*128 + 2*128) * 64;   // 98304 (3-stage swizzled)
    cudaFuncSetAttribute(tgemm<128>, cudaFuncAttributeMaxDynamicSharedMemorySize, SM1P);
    cudaFuncSetAttribute(proj5, cudaFuncAttributeMaxDynamicSharedMemorySize, SM1P);
    cudaFuncSetAttribute(flash1, cudaFuncAttributeMaxDynamicSharedMemorySize, FL_SMEM);

    // 1. split x
    conv_split<<<(BT*EE)/1024, 256>>>(x, xh, xl, BT*EE);
    // 2. split all 6 weights in one launch
    CW cw;
    cw.in[0]=wq;  cw.oh[0]=wqh; cw.ol[0]=wql;
    cw.in[1]=wk;  cw.oh[1]=wkh; cw.ol[1]=wkl;
    cw.in[2]=wv;  cw.oh[2]=wvh; cw.ol[2]=wvl;
    cw.in[3]=wvr; cw.oh[3]=wrh; cw.ol[3]=wrl;
    cw.in[4]=wj;  cw.oh[4]=wjh; cw.ol[4]=wjl;
    cw.in[5]=wo;  cw.oh[5]=woh; cw.ol[5]=wol;
    conv_split_w<<<dim3((EE*EE)/1024, 6), 256>>>(cw);
    // 3. wj transpose split
    conv_split_T<<<(EE*EE)/256, 256>>>(wj, wjTh, wjTl);

    // 4. merged 5 projections
    P5 p;
    p.bh[0]=wqh; p.bl[0]=wql; p.cf[0]=nullptr; p.ch[0]=qsh; p.cl[0]=qsl; p.ldc[0]=0;    p.mode[0]=3;
    p.bh[1]=wkh; p.bl[1]=wkl; p.cf[1]=nullptr; p.ch[1]=ksh; p.cl[1]=ksl; p.ldc[1]=0;    p.mode[1]=3;
    p.bh[2]=wvh; p.bl[2]=wvl; p.cf[2]=nullptr; p.ch[2]=vth; p.cl[2]=vtl; p.ldc[2]=0;    p.mode[2]=2;
    p.bh[3]=wrh; p.bl[3]=wrl; p.cf[3]=rvf;     p.ch[3]=nullptr; p.cl[3]=nullptr; p.ldc[3]=1024; p.mode[3]=0;
    p.bh[4]=wjh; p.bl[4]=wjl; p.cf[4]=echof;   p.ch[4]=eh;  p.cl[4]=el;  p.ldc[4]=1024; p.mode[4]=4;
    proj5<<<dim3(8, 32, 5), 256, SM1P>>>(xh, xl, p);

    // 5. echo_back = echo @ wj
    tgemm<128><<<dim3(8, 32, 1), 256, SM1P>>>(eh, el, wjTh, wjTl, 1024, 1024, 1024, 0, 0, 0,
                                              0, ebf, nullptr, nullptr, 1024, 0, nullptr);

    // 6. branch 1 fused
    flash1<<<dim3(8, 64), 256, FL_SMEM>>>(gate);

    // 7-8. s2 / sc
    s2_kernel<<<dim3(TT/256, HH, BB), 256>>>(x, wr);
    sc_kernel<<<BT, 256>>>(x);

    // 9-10. branch-3 probs + echo transpose
    p3_kernel<<<dim3(TT, BB), 512>>>();
    transpose_split<<<dim3(32, 32, BB), dim3(32, 8)>>>(echof, eTh, eTl);

    // 11-12. branch 2
    b2a_kernel<<<BH, 512>>>();
    b2b_kernel<<<dim3(2, BH), 512>>>(gate);

    // 13. branch 3 GEMM: comb += g2[h] * (P3 @ echo), causal K-capped
    tgemm<128><<<dim3(8, 8, BB), 256, SM1P>>>(
        p3h, p3l, eTh, eTl, 1024, 1024, 1024,
        (long)TT*TT, (long)TT*EE, 1,
        5, combf, nullptr, nullptr, 1024, (long)TT*EE, gate);

    // 14-15. final: out = comb @ wo^T
    conv_split<<<(BT*EE)/1024, 256>>>(combf, ch, cl, BT*EE);
    tgemm<128><<<dim3(8, 32, 1), 256, SM1P>>>(ch, cl, woh, wol, 1024, 1024, 1024, 0, 0, 0,
                                              0, out, nullptr, nullptr, 1024, 0, nullptr);
}

// round 16
// speedup vs baseline: 5.7088x; 1.0719x over previous
#include <cuda_runtime.h>
#include <cuda_bf16.h>
#include <math_constants.h>
#include <cstdint>

#define BB 4
#define TT 1024
#define EE 1024
#define HH 16
#define DD 64
#define BT (BB*TT)   // 4096
#define BH (BB*HH)   // 64

// ---------------- scratch (device globals) ----------------
__device__ __nv_bfloat16 g_xh[BT*EE],  g_xl[BT*EE];
__device__ __nv_bfloat16 g_wqh[EE*EE], g_wql[EE*EE];
__device__ __nv_bfloat16 g_wkh[EE*EE], g_wkl[EE*EE];
__device__ __nv_bfloat16 g_wvh[EE*EE], g_wvl[EE*EE];
__device__ __nv_bfloat16 g_wrh[EE*EE], g_wrl[EE*EE];   // wvr
__device__ __nv_bfloat16 g_wjh[EE*EE], g_wjl[EE*EE];
__device__ __nv_bfloat16 g_wjTh[EE*EE],g_wjTl[EE*EE];
__device__ __nv_bfloat16 g_woh[EE*EE], g_wol[EE*EE];
__device__ __nv_bfloat16 g_qsh[BH*TT*DD], g_qsl[BH*TT*DD];  // [bh][t][d]
__device__ __nv_bfloat16 g_ksh[BH*TT*DD], g_ksl[BH*TT*DD];  // [bh][t][d]
__device__ __nv_bfloat16 g_vth[BH*DD*TT], g_vtl[BH*DD*TT];  // [bh][d][t]
__device__ float g_rv[BT*EE];
__device__ float g_echo[BT*EE];
__device__ __nv_bfloat16 g_eh[BT*EE], g_el[BT*EE];
__device__ __nv_bfloat16 g_eTh[BT*EE], g_eTl[BT*EE];        // echo^T per batch [b][e][t]
__device__ float g_eb[BT*EE];
__device__ float g_comb[BT*EE];
__device__ __nv_bfloat16 g_ch[BT*EE], g_cl[BT*EE];
__device__ __nv_bfloat16 g_p3h[(long)BB*TT*TT], g_p3l[(long)BB*TT*TT];  // branch-3 probs
__device__ float g_s2[BH*TT];
__device__ float g_sc[BB*TT];
__device__ float g_b2w[BH*TT], g_b2inv[BH*TT];

// ---------------- helpers ----------------
__device__ __forceinline__ uint32_t smem_u32(const void* p) {
    uint32_t a;
    asm("{ .reg .u64 t; cvta.to.shared.u64 t, %1; cvt.u32.u64 %0, t; }" : "=r"(a) : "l"(p));
    return a;
}
__device__ __forceinline__ void cpasync16(uint32_t saddr, const void* g) {
    asm volatile("cp.async.cg.shared.global [%0], [%1], 16;" :: "r"(saddr), "l"(g));
}
#define CP_COMMIT() asm volatile("cp.async.commit_group;" ::: "memory")
#define CP_WAIT0()  asm volatile("cp.async.wait_group 0;"  ::: "memory")
#define CP_WAIT1()  asm volatile("cp.async.wait_group 1;"  ::: "memory")

__device__ __forceinline__ void ldsm4(uint32_t* r, uint32_t addr) {
    asm volatile("ldmatrix.sync.aligned.m8n8.x4.shared.b16 {%0,%1,%2,%3}, [%4];"
        : "=r"(r[0]), "=r"(r[1]), "=r"(r[2]), "=r"(r[3]) : "r"(addr));
}
__device__ __forceinline__ void mma16816(float* d, const uint32_t* a, const uint32_t* b) {
    asm volatile("mma.sync.aligned.m16n8k16.row.col.f32.bf16.bf16.f32 "
        "{%0,%1,%2,%3}, {%4,%5,%6,%7}, {%8,%9}, {%0,%1,%2,%3};"
        : "+f"(d[0]), "+f"(d[1]), "+f"(d[2]), "+f"(d[3])
        : "r"(a[0]), "r"(a[1]), "r"(a[2]), "r"(a[3]), "r"(b[0]), "r"(b[1]));
}

// fast exp on FMA pipe. valid x <= 0; clamps below -80. rel err < 3e-6.
__device__ __forceinline__ float fexp(float x) {
    x = fmaxf(x, -80.f);
    float y = x * 1.4426950408889634f;
    int   e = __float2int_rn(y);
    float f = y - (float)e;
    float p = 1.3333558e-3f;
    p = fmaf(p, f, 9.6181292e-3f);
    p = fmaf(p, f, 5.5504109e-2f);
    p = fmaf(p, f, 2.4022651e-1f);
    p = fmaf(p, f, 6.9314718e-1f);
    p = fmaf(p, f, 1.0f);
    return __int_as_float((e + 127) << 23) * p;
}

__device__ __forceinline__ float gate_w(const float* gate, int h, int c) {
    float a = gate[h*3+0], b = gate[h*3+1], d = gate[h*3+2];
    float m = fmaxf(a, fmaxf(b, d));
    float ea = __expf(a-m), eb = __expf(b-m), ec = __expf(d-m);
    float s = ea + eb + ec;
    float num = (c == 0) ? ea : (c == 1) ? eb : ec;
    return num / s;
}
__device__ __forceinline__ void bsplit(float v, __nv_bfloat16& h, __nv_bfloat16& l) {
    h = __float2bfloat16(v);
    l = __float2bfloat16(v - __bfloat162float(h));
}
__device__ __forceinline__ uint32_t pk2(__nv_bfloat16 a, __nv_bfloat16 b) {
    __nv_bfloat162 t; t.x = a; t.y = b;
    return *reinterpret_cast<uint32_t*>(&t);
}

// swizzled offset within a 64B-row tile: row r, 16B column c (0..3)
__device__ __forceinline__ uint32_t swz(int r, int c) {
    return (uint32_t)(r*64 + ((c ^ ((r >> 1) & 3)) << 4));
}

// ---------------- single-pass 3-term HMMA split-bf16 GEMM body ----------------
// C = sum_k (AhBh + AhBl + AlBh). 3-stage cp.async pipeline, ONE barrier/chunk.
// modes: 0 fp32; 2 vT-split; 3 ts-split; 4 fp32+split; 5 fp32 += gate2[h(gn)]*v
template<int TN>
__device__ __forceinline__ void gemm_body(
    char* smem, const __nv_bfloat16* __restrict__ Ah, const __nv_bfloat16* __restrict__ Al,
    const __nv_bfloat16* __restrict__ Bh, const __nv_bfloat16* __restrict__ Bl,
    int NC, long lda, long ldb,
    int mode, float* __restrict__ CfB,
    __nv_bfloat16* __restrict__ Ch, __nv_bfloat16* __restrict__ Cl,
    long ldc, const float* __restrict__ gate)
{
    constexpr int TM = 128;
    constexpr int AOFF_L = TM*64;
    constexpr int BOFF_H = 2*TM*64;
    constexpr int BOFF_L = 2*TM*64 + TN*64;
    constexpr int STG = 2*TM*64 + 2*TN*64;   // 32768 for TN=128
    constexpr int WARPS_N = TN/32, WARPS_M = 8/WARPS_N;
    constexpr int WM = TM/WARPS_M, MI = WM/16;

    __shared__ float sgate[16];
    const int tid = threadIdx.x, wid = tid >> 5, lane = tid & 31;
    const int m0 = blockIdx.y*TM, n0 = blockIdx.x*TN;
    const int wm = wid / WARPS_N, wn = wid % WARPS_N;
    const uint32_t sbase = smem_u32(smem);

    if (mode == 5 && tid < 16) sgate[tid] = gate_w(gate, tid, 2);

    auto prefetch = [&](int c, int s) {
        int k0 = c * 32;
        uint32_t st = sbase + s*STG;
        #pragma unroll 2
        for (int i = tid; i < TM*4; i += 256) {
            int r = i >> 2, cc = i & 3;
            long go = (long)(m0 + r)*lda + k0 + cc*8;
            uint32_t so = swz(r, cc);
            cpasync16(st + so,            Ah + go);
            cpasync16(st + AOFF_L + so,   Al + go);
        }
        #pragma unroll 2
        for (int i = tid; i < TN*4; i += 256) {
            int r = i >> 2, cc = i & 3;
            long go = (long)(n0 + r)*ldb + k0 + cc*8;
            uint32_t so = swz(r, cc);
            cpasync16(st + BOFF_H + so,   Bh + go);
            cpasync16(st + BOFF_L + so,   Bl + go);
        }
    };

    float acc[MI][4][4] = {};
    prefetch(0, 0); CP_COMMIT();
    if (NC > 1) prefetch(1, 1);
    CP_COMMIT();   // always commit (possibly empty) so wait_group 1 => stage c done

    for (int c = 0; c < NC; c++) {
        CP_WAIT1();
        __syncthreads();   // stage c arrived AND all warps done with stage (c-1)
        if (c + 2 < NC) { prefetch(c + 2, (c + 2) % 3); CP_COMMIT(); }

        uint32_t st = sbase + (c % 3)*STG;
        #pragma unroll
        for (int ks = 0; ks < 2; ks++) {
            const int kc = ks*2 + (lane >> 4);   // logical 16B column
            uint32_t aH[MI][4], bH[2][4], bL[2][4];
            #pragma unroll
            for (int mi = 0; mi < MI; mi++)
                ldsm4(aH[mi], st + swz(wm*WM + mi*16 + (lane & 15), kc));
            #pragma unroll
            for (int bi = 0; bi < 2; bi++) {
                ldsm4(bH[bi], st + BOFF_H + swz(wn*32 + bi*16 + (lane & 15), kc));
                ldsm4(bL[bi], st + BOFF_L + swz(wn*32 + bi*16 + (lane & 15), kc));
            }
            // independent-accumulator sweeps
            #pragma unroll
            for (int mi = 0; mi < MI; mi++)
                #pragma unroll
                for (int ni = 0; ni < 4; ni++) {
                    uint32_t h2[2] = { bH[ni>>1][ni & 1], bH[ni>>1][(ni & 1) + 2] };
                    mma16816(acc[mi][ni], aH[mi], h2);
                }
            #pragma unroll
            for (int mi = 0; mi < MI; mi++)
                #pragma unroll
                for (int ni = 0; ni < 4; ni++) {
                    uint32_t l2[2] = { bL[ni>>1][ni & 1], bL[ni>>1][(ni & 1) + 2] };
                    mma16816(acc[mi][ni], aH[mi], l2);
                }
            uint32_t aL[MI][4];
            #pragma unroll
            for (int mi = 0; mi < MI; mi++)
                ldsm4(aL[mi], st + AOFF_L + swz(wm*WM + mi*16 + (lane & 15), kc));
            #pragma unroll
            for (int mi = 0; mi < MI; mi++)
                #pragma unroll
                for (int ni = 0; ni < 4; ni++) {
                    uint32_t h2[2] = { bH[ni>>1][ni & 1], bH[ni>>1][(ni & 1) + 2] };
                    mma16816(acc[mi][ni], aL[mi], h2);
                }
        }
        // no bottom barrier: next iteration's top barrier seals stage reuse
    }

    // epilogue (paired stores; gn pairs are contiguous)
    #pragma unroll
    for (int mi = 0; mi < MI; mi++) {
        #pragma unroll
        for (int ni = 0; ni < 4; ni++) {
            int rb = m0 + wm*WM + mi*16 + (lane >> 2);
            int cb = n0 + wn*32 + ni*8 + (lane & 3)*2;
            #pragma unroll
            for (int half = 0; half < 2; half++) {
                int gm = rb + half*8;
                float v0 = acc[mi][ni][half*2+0], v1 = acc[mi][ni][half*2+1];
                if (mode == 0) {
                    *(float2*)&CfB[(long)gm*ldc + cb] = make_float2(v0, v1);
                } else if (mode == 4) {
                    long idx = (long)gm*ldc + cb;
                    *(float2*)&CfB[idx] = make_float2(v0, v1);
                    __nv_bfloat16 h0,l0,h1,l1;
                    bsplit(v0,h0,l0); bsplit(v1,h1,l1);
                    *(uint32_t*)&Ch[idx] = pk2(h0,h1);
                    *(uint32_t*)&Cl[idx] = pk2(l0,l1);
                } else if (mode == 3) {   // [(b*16+h)][t][d], d pair contiguous
                    int b = gm >> 10, t = gm & 1023, h = cb >> 6, d = cb & 63;
                    long idx = (((long)(b*16 + h)) * 1024 + t) * 64 + d;
                    __nv_bfloat16 h0,l0,h1,l1;
                    bsplit(v0,h0,l0); bsplit(v1,h1,l1);
                    *(uint32_t*)&Ch[idx] = pk2(h0,h1);
                    *(uint32_t*)&Cl[idx] = pk2(l0,l1);
                } else if (mode == 2) {   // vT: [(b*16+h)][d][t], d pair stride 1024
                    int b = gm >> 10, t = gm & 1023, h = cb >> 6, d = cb & 63;
                    long idx = (((long)(b*16 + h)) * 64 + d) * 1024 + t;
                    bsplit(v0, Ch[idx], Cl[idx]);
                    bsplit(v1, Ch[idx + 1024], Cl[idx + 1024]);
                } else {                  // mode 5: gated accumulate
                    long idx = (long)gm*ldc + cb;
                    float g = sgate[cb >> 6];
                    float2 old = *(float2*)&CfB[idx];
                    *(float2*)&CfB[idx] = make_float2(old.x + g*v0, old.y + g*v1);
                }
            }
        }
    }
}

// generic wrapper (eb / branch-3 / final)
template<int TN>
__global__ void __launch_bounds__(256, 2) tgemm(
    const __nv_bfloat16* __restrict__ Ah_, const __nv_bfloat16* __restrict__ Al_,
    const __nv_bfloat16* __restrict__ Bh_, const __nv_bfloat16* __restrict__ Bl_,
    int K, long lda, long ldb, long sAz, long sBz, int kcap,
    int mode, float* __restrict__ Cf,
    __nv_bfloat16* __restrict__ Ch, __nv_bfloat16* __restrict__ Cl,
    long ldc, long sCz, const float* __restrict__ gate)
{
    extern __shared__ char smem[];
    const int z = blockIdx.z;
    const int Keff = kcap ? (blockIdx.y*128 + 128) : K;
    gemm_body<TN>(smem,
                  Ah_ + (long)z*sAz, Al_ + (long)z*sAz,
                  Bh_ + (long)z*sBz, Bl_ + (long)z*sBz,
                  Keff/32, lda, ldb, mode,
                  Cf ? (Cf + (long)z*sCz) : nullptr, Ch, Cl, ldc, gate);
}

// merged 5-projection kernel (z picks weight + output mode)
struct P5 {
    const __nv_bfloat16* bh[5]; const __nv_bfloat16* bl[5];
    float* cf[5]; __nv_bfloat16* ch[5]; __nv_bfloat16* cl[5];
    long ldc[5]; int mode[5];
};
__global__ void __launch_bounds__(256, 2) proj5(
    const __nv_bfloat16* __restrict__ xh, const __nv_bfloat16* __restrict__ xl, P5 p)
{
    extern __shared__ char smem[];
    const int z = blockIdx.z;
    gemm_body<128>(smem, xh, xl, p.bh[z], p.bl[z], 32, 1024, 1024,
                   p.mode[z], p.cf[z], p.ch[z], p.cl[z], p.ldc[z], nullptr);
}

// ---------------- fused flash branch 1 ----------------
#define FL_SMEM 180224
__global__ void __launch_bounds__(256) flash1(const float* __restrict__ gate)
{
    extern __shared__ char smem[];
    const int tid = threadIdx.x, wid = tid >> 5, lane = tid & 31;
    const int m0 = (gridDim.x - 1 - blockIdx.x) * 128;   // heavy tiles first
    const int bh = blockIdx.y;
    const uint32_t sb = smem_u32(smem);
    const uint32_t sQh = sb, sQl = sb + 18432;

    const long qoff = (long)bh * TT * DD;
    const long voff = (long)bh * DD * TT;

    for (int i = tid; i < 128*8; i += 256) {
        int r = i >> 3, c = i & 7;
        cpasync16(sQh + r*144 + c*16, g_qsh + qoff + (long)(m0+r)*64 + c*8);
        cpasync16(sQl + r*144 + c*16, g_qsl + qoff + (long)(m0+r)*64 + c*8);
    }
    CP_COMMIT();

    const int nchunks = m0/128 + 1;
    auto pf = [&](int cidx, int st) {
        uint32_t kh = sb + 36864 + st*36864, kl = kh + 18432;
        uint32_t vh = sb + 110592 + st*34816, vl = vh + 17408;
        int j0 = cidx * 128;
        for (int i = tid; i < 128*8; i += 256) {
            int r = i >> 3, c = i & 7;
            cpasync16(kh + r*144 + c*16, g_ksh + qoff + (long)(j0+r)*64 + c*8);
            cpasync16(kl + r*144 + c*16, g_ksl + qoff + (long)(j0+r)*64 + c*8);
        }
        for (int i = tid; i < 64*16; i += 256) {
            int r = i >> 4, c = i & 15;
            cpasync16(vh + r*272 + c*16, g_vth + voff + (long)r*TT + j0 + c*8);
            cpasync16(vl + r*272 + c*16, g_vtl + voff + (long)r*TT + j0 + c*8);
        }
    };
    pf(0, 0); CP_COMMIT();

    uint32_t qfh[4][4], qfl[4][4];
    float oa[8][4] = {};
    float ms0 = -1e30f, ms1 = -1e30f, l0 = 0.f, l1 = 0.f;

    for (int c = 0; c < nchunks; c++) {
        CP_WAIT0();
        __syncthreads();   // stage c (and Q) arrived; all warps done with stage c-1
        if (c + 1 < nchunks) { pf(c + 1, (c + 1) & 1); CP_COMMIT(); }

        if (c == 0) {
            #pragma unroll
            for (int ks = 0; ks < 4; ks++) {
                ldsm4(qfh[ks], sQh + (wid*16 + (lane & 15))*144 + ks*32 + (lane >> 4)*16);
                ldsm4(qfl[ks], sQl + (wid*16 + (lane & 15))*144 + ks*32 + (lane >> 4)*16);
            }
        }

        const int st = c & 1, j0 = c * 128;
        const uint32_t khb = sb + 36864 + st*36864, klb = khb + 18432;
        const uint32_t vhb = sb + 110592 + st*34816, vlb = vhb + 17408;

        float sa[16][4];
        #pragma unroll
        for (int nt = 0; nt < 16; nt++)
            sa[nt][0] = sa[nt][1] = sa[nt][2] = sa[nt][3] = 0.f;

        #pragma unroll
        for (int ks = 0; ks < 4; ks++) {
            uint32_t bf4[8][4];
            #pragma unroll
            for (int g = 0; g < 8; g++)
                ldsm4(bf4[g], khb + (g*16 + (lane & 15))*144 + ks*32 + (lane >> 4)*16);
            #pragma unroll
            for (int nt = 0; nt < 16; nt++) {
                uint32_t b2[2] = { bf4[nt>>1][nt & 1], bf4[nt>>1][(nt & 1) + 2] };
                mma16816(sa[nt], qfh[ks], b2);
            }
            #pragma unroll
            for (int nt = 0; nt < 16; nt++) {
                uint32_t b2[2] = { bf4[nt>>1][nt & 1], bf4[nt>>1][(nt & 1) + 2] };
                mma16816(sa[nt], qfl[ks], b2);
            }
            #pragma unroll
            for (int g = 0; g < 8; g++)
                ldsm4(bf4[g], klb + (g*16 + (lane & 15))*144 + ks*32 + (lane >> 4)*16);
            #pragma unroll
            for (int nt = 0; nt < 16; nt++) {
                uint32_t b2[2] = { bf4[nt>>1][nt & 1], bf4[nt>>1][(nt & 1) + 2] };
                mma16816(sa[nt], qfh[ks], b2);
            }
        }

        const int qr0 = m0 + wid*16 + (lane >> 2);
        const int qr1 = qr0 + 8;
        if (j0 == m0) {
            #pragma unroll
            for (int nt = 0; nt < 16; nt++) {
                int col = j0 + nt*8 + (lane & 3)*2;
                sa[nt][0] = (col     > qr0) ? -1e30f : sa[nt][0]*0.125f;
                sa[nt][1] = (col + 1 > qr0) ? -1e30f : sa[nt][1]*0.125f;
                sa[nt][2] = (col     > qr1) ? -1e30f : sa[nt][2]*0.125f;
                sa[nt][3] = (col + 1 > qr1) ? -1e30f : sa[nt][3]*0.125f;
            }
        } else {
            #pragma unroll
            for (int nt = 0; nt < 16; nt++) {
                sa[nt][0] *= 0.125f; sa[nt][1] *= 0.125f;
                sa[nt][2] *= 0.125f; sa[nt][3] *= 0.125f;
            }
        }

        float mx0 = -1e30f, mx1 = -1e30f;
        #pragma unroll
        for (int nt = 0; nt < 16; nt++) {
            mx0 = fmaxf(mx0, fmaxf(sa[nt][0], sa[nt][1]));
            mx1 = fmaxf(mx1, fmaxf(sa[nt][2], sa[nt][3]));
        }
        mx0 = fmaxf(mx0, __shfl_xor_sync(0xffffffffu, mx0, 1));
        mx0 = fmaxf(mx0, __shfl_xor_sync(0xffffffffu, mx0, 2));
        mx1 = fmaxf(mx1, __shfl_xor_sync(0xffffffffu, mx1, 1));
        mx1 = fmaxf(mx1, __shfl_xor_sync(0xffffffffu, mx1, 2));

        float mn0 = fmaxf(ms0, mx0), mn1 = fmaxf(ms1, mx1);
        float cor0 = fexp(ms0 - mn0), cor1 = fexp(ms1 - mn1);

        float rs0 = 0.f, rs1 = 0.f;
        #pragma unroll
        for (int nt = 0; nt < 16; nt++) {
            sa[nt][0] = fexp(sa[nt][0] - mn0);
            sa[nt][1] = fexp(sa[nt][1] - mn0);
            sa[nt][2] = fexp(sa[nt][2] - mn1);
            sa[nt][3] = fexp(sa[nt][3] - mn1);
            rs0 += sa[nt][0] + sa[nt][1];
            rs1 += sa[nt][2] + sa[nt][3];
        }
        rs0 += __shfl_xor_sync(0xffffffffu, rs0, 1);
        rs0 += __shfl_xor_sync(0xffffffffu, rs0, 2);
        rs1 += __shfl_xor_sync(0xffffffffu, rs1, 1);
        rs1 += __shfl_xor_sync(0xffffffffu, rs1, 2);
        l0 = l0*cor0 + rs0;
        l1 = l1*cor1 + rs1;
        ms0 = mn0; ms1 = mn1;
        #pragma unroll
        for (int dn = 0; dn < 8; dn++) {
            oa[dn][0] *= cor0; oa[dn][1] *= cor0;
            oa[dn][2] *= cor1; oa[dn][3] *= cor1;
        }

        // ---- O += Ph Vh + Pl Vh + Ph Vl (independent-acc sweeps) ----
        #pragma unroll
        for (int ks = 0; ks < 8; ks++) {
            uint32_t aH[4], aL[4];
            {
                float p0 = sa[2*ks][0],   p1 = sa[2*ks][1];
                float p2 = sa[2*ks][2],   p3 = sa[2*ks][3];
                float r0 = sa[2*ks+1][0], r1 = sa[2*ks+1][1];
                float r2 = sa[2*ks+1][2], r3 = sa[2*ks+1][3];
                __nv_bfloat16 h0 = __float2bfloat16(p0), h1 = __float2bfloat16(p1);
                __nv_bfloat16 h2 = __float2bfloat16(p2), h3 = __float2bfloat16(p3);
                __nv_bfloat16 g0 = __float2bfloat16(r0), g1 = __float2bfloat16(r1);
                __nv_bfloat16 g2 = __float2bfloat16(r2), g3 = __float2bfloat16(r3);
                aH[0] = pk2(h0, h1); aH[1] = pk2(h2, h3);
                aH[2] = pk2(g0, g1); aH[3] = pk2(g2, g3);
                aL[0] = pk2(__float2bfloat16(p0 - __bfloat162float(h0)),
                            __float2bfloat16(p1 - __bfloat162float(h1)));
                aL[1] = pk2(__float2bfloat16(p2 - __bfloat162float(h2)),
                            __float2bfloat16(p3 - __bfloat162float(h3)));
                aL[2] = pk2(__float2bfloat16(r0 - __bfloat162float(g0)),
                            __float2bfloat16(r1 - __bfloat162float(g1)));
                aL[3] = pk2(__float2bfloat16(r2 - __bfloat162float(g2)),
                            __float2bfloat16(r3 - __bfloat162float(g3)));
            }
            uint32_t bvh[4][4], bvl[4][4];
            #pragma unroll
            for (int g = 0; g < 4; g++) {
                ldsm4(bvh[g], vhb + (g*16 + (lane & 15))*272 + ks*32 + (lane >> 4)*16);
                ldsm4(bvl[g], vlb + (g*16 + (lane & 15))*272 + ks*32 + (lane >> 4)*16);
            }
            #pragma unroll
            for (int dn = 0; dn < 8; dn++) {
                uint32_t b2h[2] = { bvh[dn>>1][dn & 1], bvh[dn>>1][(dn & 1) + 2] };
                mma16816(oa[dn], aH, b2h);
            }
            #pragma unroll
            for (int dn = 0; dn < 8; dn++) {
                uint32_t b2h[2] = { bvh[dn>>1][dn & 1], bvh[dn>>1][(dn & 1) + 2] };
                mma16816(oa[dn], aL, b2h);
            }
            #pragma unroll
            for (int dn = 0; dn < 8; dn++) {
                uint32_t b2l[2] = { bvl[dn>>1][dn & 1], bvl[dn>>1][(dn & 1) + 2] };
                mma16816(oa[dn], aH, b2l);
            }
        }
        // no bottom barrier: next iteration's top barrier seals stage reuse
    }

    const float g0w = gate_w(gate, bh & 15, 0);
    const float s0 = g0w / l0, s1 = g0w / l1;
    const int b = bh >> 4, h = bh & 15;
    const int qr0 = m0 + wid*16 + (lane >> 2), qr1 = qr0 + 8;
    float* c0 = g_comb + ((long)b*TT + qr0)*EE + h*64;
    float* c1 = g_comb + ((long)b*TT + qr1)*EE + h*64;
    #pragma unroll
    for (int dn = 0; dn < 8; dn++) {
        int d = dn*8 + (lane & 3)*2;
        *(float2*)&c0[d] = make_float2(oa[dn][0]*s0, oa[dn][1]*s0);
        *(float2*)&c1[d] = make_float2(oa[dn][2]*s1, oa[dn][3]*s1);
    }
}

// ---------------- conversion kernels ----------------
__global__ void conv_split(const float* __restrict__ in,
                           __nv_bfloat16* __restrict__ h, __nv_bfloat16* __restrict__ l, int n)
{
    int i = (blockIdx.x * 256 + threadIdx.x) * 4;
    if (i >= n) return;
    float4 v = *(const float4*)(in + i);
    __nv_bfloat16 h0,h1,h2,h3,l0,l1,l2,l3;
    bsplit(v.x,h0,l0); bsplit(v.y,h1,l1); bsplit(v.z,h2,l2); bsplit(v.w,h3,l3);
    *(uint2*)(h + i) = make_uint2(pk2(h0,h1), pk2(h2,h3));
    *(uint2*)(l + i) = make_uint2(pk2(l0,l1), pk2(l2,l3));
}
struct CW { const float* in[6]; __nv_bfloat16* oh[6]; __nv_bfloat16* ol[6]; };
__global__ void conv_split_w(CW cw)
{
    int t = blockIdx.y;
    int i = (blockIdx.x * 256 + threadIdx.x) * 4;
    float4 v = *(const float4*)(cw.in[t] + i);
    __nv_bfloat16 h0,h1,h2,h3,l0,l1,l2,l3;
    bsplit(v.x,h0,l0); bsplit(v.y,h1,l1); bsplit(v.z,h2,l2); bsplit(v.w,h3,l3);
    *(uint2*)(cw.oh[t] + i) = make_uint2(pk2(h0,h1), pk2(h2,h3));
    *(uint2*)(cw.ol[t] + i) = make_uint2(pk2(l0,l1), pk2(l2,l3));
}
__global__ void conv_split_T(const float* __restrict__ in,
                             __nv_bfloat16* __restrict__ h, __nv_bfloat16* __restrict__ l)
{   // out[e*E+f] = in[f*E+e]
    int i = blockIdx.x * 256 + threadIdx.x;
    int e = i >> 10, f = i & 1023;
    bsplit(in[(long)f * EE + e], h[i], l[i]);
}
// per-batch transpose-split: echo [b][t][e] -> echoT [b][e][t]
__global__ void transpose_split(const float* __restrict__ in,
                                __nv_bfloat16* __restrict__ oh, __nv_bfloat16* __restrict__ ol)
{
    __shared__ float tile[32][33];
    int b = blockIdx.z;
    int t0 = blockIdx.x * 32, e0 = blockIdx.y * 32;
    int tx = threadIdx.x, ty = threadIdx.y;   // (32, 8)
    const float* ib = in + ((long)b*TT + t0)*EE + e0;
    #pragma unroll
    for (int k = 0; k < 4; k++)
        tile[ty + k*8][tx] = ib[(long)(ty + k*8)*EE + tx];
    __syncthreads();
    #pragma unroll
    for (int k = 0; k < 4; k++) {
        int e = ty + k*8;
        long idx = ((long)b*EE + e0 + e)*TT + t0 + tx;
        bsplit(tile[tx][e], oh[idx], ol[idx]);
    }
}

// ---------------- s2[b,h,t] = (1/8) dot(x[b,t,:], wr[h,:,t]) ----------------
__global__ void s2_kernel(const float* __restrict__ x, const float* __restrict__ wr)
{
    __shared__ float xs[256][33];
    int t0 = blockIdx.x * 256;
    int h = blockIdx.y, b = blockIdx.z;
    int tid = threadIdx.x, w = tid >> 5, lane = tid & 31;
    int t = t0 + tid;
    float acc = 0.f;
    for (int e0 = 0; e0 < EE; e0 += 32) {
        #pragma unroll 4
        for (int rr = 0; rr < 32; rr++)
            xs[w*32 + rr][lane] = x[(long)b*TT*EE + (long)(t0 + w*32 + rr)*EE + e0 + lane];
        __syncthreads();
        const float* wrp = wr + (long)h*EE*TT + (long)e0*TT + t;
        #pragma unroll
        for (int e = 0; e < 32; e++) acc += xs[tid][e] * wrp[(long)e*TT];
        __syncthreads();
    }
    g_s2[(b*HH + h)*TT + t] = acc * 0.125f;
}

// ---------------- sc[b,t] = dot(x[b,t], eb[b,t]) / 32 ----------------
__global__ void sc_kernel(const float* __restrict__ x)
{
    __shared__ float red[256];
    long base = (long)blockIdx.x * EE;
    int tid = threadIdx.x;
    float s = 0.f;
    for (int e = tid; e < EE; e += 256) s += x[base+e] * g_eb[base+e];
    red[tid] = s; __syncthreads();
    for (int st = 128; st; st >>= 1) { if (tid < st) red[tid] += red[tid+st]; __syncthreads(); }
    if (tid == 0) g_sc[blockIdx.x] = red[0] * (1.f/32.f);
}

// ---------------- branch-3 probs (single exp pass, smem-staged) ----------------
// grid (T, B), 512 threads
__global__ void __launch_bounds__(512) p3_kernel()
{
    __shared__ float scs[1024];
    __shared__ float w[1024];
    __shared__ float red[512];
    int i = blockIdx.x, b = blockIdx.y;
    int tid = threadIdx.x;
    scs[tid] = g_sc[b*TT + tid];
    scs[tid + 512] = g_sc[b*TT + tid + 512];
    __syncthreads();
    float sci = scs[i];
    long base = ((long)b*TT + i)*TT;

    float m = -CUDART_INF_F;
    for (int j = tid; j <= i; j += 512) m = fmaxf(m, sci * scs[j]);
    red[tid] = m; __syncthreads();
    for (int st = 256; st; st >>= 1) { if (tid < st) red[tid] = fmaxf(red[tid], red[tid+st]); __syncthreads(); }
    m = red[0]; __syncthreads();

    float sum = 0.f;
    for (int j = tid; j <= i; j += 512) {
        float v = fexp(sci * scs[j] - m);
        w[j] = v; sum += v;
    }
    red[tid] = sum; __syncthreads();
    for (int st = 256; st; st >>= 1) { if (tid < st) red[tid] += red[tid+st]; __syncthreads(); }
    float inv = 1.f / red[0];

    for (int j = tid; j <= i; j += 512)
        bsplit(w[j] * inv, g_p3h[base+j], g_p3l[base+j]);
    __nv_bfloat16 zz = __float2bfloat16(0.f);
    for (int j = i+1+tid; j < TT; j += 512) { g_p3h[base+j] = zz; g_p3l[base+j] = zz; }
}

// ---------------- branch 2 ----------------
// b2a: softmax weights + prefix inverse -> global. grid BH, 512 threads.
__global__ void __launch_bounds__(512) b2a_kernel()
{
    __shared__ float red[512];
    int bh = blockIdx.x;
    int tid = threadIdx.x;
    const float* s2p = g_s2 + bh*TT;

    float m = fmaxf(s2p[tid], s2p[tid + 512]);
    red[tid] = m; __syncthreads();
    for (int st = 256; st; st >>= 1) { if (tid < st) red[tid] = fmaxf(red[tid], red[tid+st]); __syncthreads(); }
    m = red[0]; __syncthreads();

    float w0 = fexp(s2p[2*tid] - m), w1 = fexp(s2p[2*tid+1] - m);
    g_b2w[bh*TT + 2*tid] = w0; g_b2w[bh*TT + 2*tid+1] = w1;
    red[tid] = w0 + w1; __syncthreads();
    for (int off = 1; off < 512; off <<= 1) {
        float v = (tid >= off) ? red[tid - off] : 0.f;
        __syncthreads();
        red[tid] += v;
        __syncthreads();
    }
    float basep = (tid == 0) ? 0.f : red[tid - 1];
    g_b2inv[bh*TT + 2*tid]   = 1.f / (basep + w0);
    g_b2inv[bh*TT + 2*tid+1] = 1.f / (basep + w0 + w1);
}

// b2b: gated prefix accumulate. grid (2, BH), 512 threads; lane = d column.
__global__ void __launch_bounds__(512) b2b_kernel(const float* __restrict__ gate)
{
    __shared__ float w[1024], inv[1024], seg[16][32];
    int bh = blockIdx.y, b = bh >> 4, h = bh & 15;
    int dh = blockIdx.x;
    int tid = threadIdx.x, wp = tid >> 5, ln = tid & 31;
    w[tid] = g_b2w[bh*TT + tid];     w[tid+512] = g_b2w[bh*TT + tid+512];
    inv[tid] = g_b2inv[bh*TT + tid]; inv[tid+512] = g_b2inv[bh*TT + tid+512];
    __syncthreads();

    const int d = dh*32 + ln;
    const float* rvp = g_rv + (long)b*TT*EE + h*64 + d;
    float p = 0.f;
    #pragma unroll 4
    for (int j = wp*64; j < wp*64 + 64; j++) p += w[j] * rvp[(long)j*EE];
    seg[wp][ln] = p;
    __syncthreads();
    if (tid < 32) {
        float a = 0.f;
        #pragma unroll
        for (int s = 0; s < 16; s++) { float t = seg[s][tid]; seg[s][tid] = a; a += t; }
    }
    __syncthreads();

    float g1 = gate_w(gate, h, 1);
    float a = seg[wp][ln];
    float* cp = g_comb + (long)b*TT*EE + h*64 + d;
    #pragma unroll 4
    for (int j = wp*64; j < wp*64 + 64; j++) {
        a += w[j] * rvp[(long)j*EE];
        cp[(long)j*EE] += g1 * a * inv[j];
    }
}

// ---------------- host launch ----------------
extern "C" void kernel_launch(void* const* d_in, const int* in_sizes, int n_in,
                              void* d_out, int out_size)
{
    const float* x    = (const float*)d_in[0];
    const float* wq   = (const float*)d_in[1];
    const float* wk   = (const float*)d_in[2];
    const float* wv   = (const float*)d_in[3];
    const float* wvr  = (const float*)d_in[4];
    const float* wr   = (const float*)d_in[5];
    const float* wj   = (const float*)d_in[6];
    const float* gate = (const float*)d_in[7];
    const float* wo   = (const float*)d_in[8];
    float* out = (float*)d_out;

#define GA(sym, var, type) type* var; cudaGetSymbolAddress((void**)&var, sym)
    GA(g_xh, xh, __nv_bfloat16);   GA(g_xl, xl, __nv_bfloat16);
    GA(g_wqh, wqh, __nv_bfloat16); GA(g_wql, wql, __nv_bfloat16);
    GA(g_wkh, wkh, __nv_bfloat16); GA(g_wkl, wkl, __nv_bfloat16);
    GA(g_wvh, wvh, __nv_bfloat16); GA(g_wvl, wvl, __nv_bfloat16);
    GA(g_wrh, wrh, __nv_bfloat16); GA(g_wrl, wrl, __nv_bfloat16);
    GA(g_wjh, wjh, __nv_bfloat16); GA(g_wjl, wjl, __nv_bfloat16);
    GA(g_wjTh, wjTh, __nv_bfloat16); GA(g_wjTl, wjTl, __nv_bfloat16);
    GA(g_woh, woh, __nv_bfloat16); GA(g_wol, wol, __nv_bfloat16);
    GA(g_qsh, qsh, __nv_bfloat16); GA(g_qsl, qsl, __nv_bfloat16);
    GA(g_ksh, ksh, __nv_bfloat16); GA(g_ksl, ksl, __nv_bfloat16);
    GA(g_vth, vth, __nv_bfloat16); GA(g_vtl, vtl, __nv_bfloat16);
    GA(g_rv, rvf, float);
    GA(g_echo, echof, float);
    GA(g_eh, eh, __nv_bfloat16);   GA(g_el, el, __nv_bfloat16);
    GA(g_eTh, eTh, __nv_bfloat16); GA(g_eTl, eTl, __nv_bfloat16);
    GA(g_eb, ebf, float);
    GA(g_comb, combf, float);
    GA(g_ch, ch, __nv_bfloat16);   GA(g_cl, cl, __nv_bfloat16);
    GA(g_p3h, p3h, __nv_bfloat16); GA(g_p3l, p3l, __nv_bfloat16);
#undef GA

    const int SM1P = 3 * (2*128 + 2*128) * 64;   // 98304 (3-stage swizzled)
    cudaFuncSetAttribute(tgemm<128>, cudaFuncAttributeMaxDynamicSharedMemorySize, SM1P);
    cudaFuncSetAttribute(proj5, cudaFuncAttributeMaxDynamicSharedMemorySize, SM1P);
    cudaFuncSetAttribute(flash1, cudaFuncAttributeMaxDynamicSharedMemorySize, FL_SMEM);

    // 1. split x
    conv_split<<<(BT*EE)/1024, 256>>>(x, xh, xl, BT*EE);
    // 2. split all 6 weights in one launch
    CW cw;
    cw.in[0]=wq;  cw.oh[0]=wqh; cw.ol[0]=wql;
    cw.in[1]=wk;  cw.oh[1]=wkh; cw.ol[1]=wkl;
    cw.in[2]=wv;  cw.oh[2]=wvh; cw.ol[2]=wvl;
    cw.in[3]=wvr; cw.oh[3]=wrh; cw.ol[3]=wrl;
    cw.in[4]=wj;  cw.oh[4]=wjh; cw.ol[4]=wjl;
    cw.in[5]=wo;  cw.oh[5]=woh; cw.ol[5]=wol;
    conv_split_w<<<dim3((EE*EE)/1024, 6), 256>>>(cw);
    // 3. wj transpose split
    conv_split_T<<<(EE*EE)/256, 256>>>(wj, wjTh, wjTl);

    // 4. merged 5 projections
    P5 p;
    p.bh[0]=wqh; p.bl[0]=wql; p.cf[0]=nullptr; p.ch[0]=qsh; p.cl[0]=qsl; p.ldc[0]=0;    p.mode[0]=3;
    p.bh[1]=wkh; p.bl[1]=wkl; p.cf[1]=nullptr; p.ch[1]=ksh; p.cl[1]=ksl; p.ldc[1]=0;    p.mode[1]=3;
    p.bh[2]=wvh; p.bl[2]=wvl; p.cf[2]=nullptr; p.ch[2]=vth; p.cl[2]=vtl; p.ldc[2]=0;    p.mode[2]=2;
    p.bh[3]=wrh; p.bl[3]=wrl; p.cf[3]=rvf;     p.ch[3]=nullptr; p.cl[3]=nullptr; p.ldc[3]=1024; p.mode[3]=0;
    p.bh[4]=wjh; p.bl[4]=wjl; p.cf[4]=echof;   p.ch[4]=eh;  p.cl[4]=el;  p.ldc[4]=1024; p.mode[4]=4;
    proj5<<<dim3(8, 32, 5), 256, SM1P>>>(xh, xl, p);

    // 5. echo_back = echo @ wj
    tgemm<128><<<dim3(8, 32, 1), 256, SM1P>>>(eh, el, wjTh, wjTl, 1024, 1024, 1024, 0, 0, 0,
                                              0, ebf, nullptr, nullptr, 1024, 0, nullptr);

    // 6. branch 1 fused
    flash1<<<dim3(8, 64), 256, FL_SMEM>>>(gate);

    // 7-8. s2 / sc
    s2_kernel<<<dim3(TT/256, HH, BB), 256>>>(x, wr);
    sc_kernel<<<BT, 256>>>(x);

    // 9-10. branch-3 probs + echo transpose
    p3_kernel<<<dim3(TT, BB), 512>>>();
    transpose_split<<<dim3(32, 32, BB), dim3(32, 8)>>>(echof, eTh, eTl);

    // 11-12. branch 2
    b2a_kernel<<<BH, 512>>>();
    b2b_kernel<<<dim3(2, BH), 512>>>(gate);

    // 13. branch 3 GEMM: comb += g2[h] * (P3 @ echo), causal K-capped
    tgemm<128><<<dim3(8, 8, BB), 256, SM1P>>>(
        p3h, p3l, eTh, eTl, 1024, 1024, 1024,
        (long)TT*TT, (long)TT*EE, 1,
        5, combf, nullptr, nullptr, 1024, (long)TT*EE, gate);

    // 14-15. final: out = comb @ wo^T
    conv_split<<<(BT*EE)/1024, 256>>>(combf, ch, cl, BT*EE);
    tgemm<128><<<dim3(8, 32, 1), 256, SM1P>>>(ch, cl, woh, wol, 1024, 1024, 1024, 0, 0, 0,
                                              0, out, nullptr, nullptr, 1024, 0, nullptr);
}